// round 4
// baseline (speedup 1.0000x reference)
#include <cuda_runtime.h>
#include <cuda_bf16.h>
#include <cstdint>
#include <cstddef>

// Problem constants
constexpr int B_ = 8;
constexpr int N_ = 2048;
constexpr int INC = 128;
constexpr int HIDC = 256;
constexpr int OUTC = 32;
constexpr int BN = B_ * N_;

// Scratch (device globals: no allocation allowed)
__device__ __align__(16) float g_deg_inv[BN];
__device__ __align__(16) float g_agg[(size_t)BN * HIDC];
__device__ __align__(16) float g_h[(size_t)BN * HIDC];
__device__ __align__(16) __nv_bfloat16 g_T_hi[(size_t)B_ * HIDC * N_];  // [b][d][i]
__device__ __align__(16) __nv_bfloat16 g_T_lo[(size_t)B_ * HIDC * N_];
__device__ __align__(16) __nv_bfloat16 g_Mt[(size_t)B_ * N_ * N_];      // [b][j][i] mask^T

using ull = unsigned long long;

#define SWZ(off) ((off) ^ (((off) >> 3) & 0x70))

__device__ __forceinline__ uint32_t smem_u32(const void* p) {
    uint32_t a;
    asm("{ .reg .u64 t; cvta.to.shared.u64 t, %1; cvt.u32.u64 %0, t; }"
        : "=r"(a) : "l"(p));
    return a;
}
__device__ __forceinline__ void cpa16(uint32_t dst, const void* src) {
    asm volatile("cp.async.cg.shared.global [%0], [%1], 16;" :: "r"(dst), "l"(src));
}
__device__ __forceinline__ void ldsm4(uint32_t* r, uint32_t addr) {
    asm volatile("ldmatrix.sync.aligned.m8n8.x4.shared.b16 {%0,%1,%2,%3}, [%4];"
                 : "=r"(r[0]), "=r"(r[1]), "=r"(r[2]), "=r"(r[3]) : "r"(addr));
}
__device__ __forceinline__ void mma_bf16(float* c, const uint32_t* a,
                                         uint32_t b0, uint32_t b1) {
    asm volatile(
        "mma.sync.aligned.m16n8k16.row.col.f32.bf16.bf16.f32 "
        "{%0,%1,%2,%3}, {%4,%5,%6,%7}, {%8,%9}, {%0,%1,%2,%3};"
        : "+f"(c[0]), "+f"(c[1]), "+f"(c[2]), "+f"(c[3])
        : "r"(a[0]), "r"(a[1]), "r"(a[2]), "r"(a[3]), "r"(b0), "r"(b1));
}

// packed fp32 fma helpers for SIMT dense layers
__device__ __forceinline__ ull pack2(float a, float b) {
    ull r;
    asm("mov.b64 %0, {%1, %2};" : "=l"(r)
        : "r"(__float_as_uint(a)), "r"(__float_as_uint(b)));
    return r;
}
__device__ __forceinline__ ull fma2(ull a, ull b, ull c) {
    ull d;
    asm("fma.rn.f32x2 %0, %1, %2, %3;" : "=l"(d) : "l"(a), "l"(b), "l"(c));
    return d;
}
__device__ __forceinline__ float2 unpack2(ull v) {
    unsigned lo, hi;
    asm("mov.b64 {%0, %1}, %2;" : "=r"(lo), "=r"(hi) : "l"(v));
    return make_float2(__uint_as_float(lo), __uint_as_float(hi));
}

// ---------------------------------------------------------------------------
// A int32 [b][i][j] -> Mt bf16 [b][j][i] + deg_inv. One block owns 64 j and
// loops over all i (local degree -> no global atomics, no zero kernel).
// ---------------------------------------------------------------------------
__global__ __launch_bounds__(256)
void mask_convert_kernel(const int* __restrict__ A) {
    __shared__ __nv_bfloat16 sT[64][72];
    __shared__ float sdeg[64];
    const int t = threadIdx.x;
    const int j0 = blockIdx.x * 64, b = blockIdx.y;
    if (t < 64) sdeg[t] = 0.0f;
    __syncthreads();

    const int4* Ap = reinterpret_cast<const int4*>(
        A + (size_t)b * N_ * N_ + j0);
    const int j4 = t & 15;    // 4 j's per thread
    const int rbase = t >> 4; // 16 i-rows per pass
    float s0 = 0, s1 = 0, s2 = 0, s3 = 0;

#pragma unroll 1
    for (int itile = 0; itile < N_ / 64; ++itile) {
        const int i0 = itile * 64;
#pragma unroll
        for (int p = 0; p < 4; ++p) {
            int il = rbase + p * 16;
            int4 v = Ap[(size_t)(i0 + il) * (N_ / 4) + j4];
            float m0 = v.x ? 1.0f : 0.0f, m1 = v.y ? 1.0f : 0.0f;
            float m2 = v.z ? 1.0f : 0.0f, m3 = v.w ? 1.0f : 0.0f;
            s0 += m0; s1 += m1; s2 += m2; s3 += m3;
            sT[j4 * 4 + 0][il] = __float2bfloat16(m0);
            sT[j4 * 4 + 1][il] = __float2bfloat16(m1);
            sT[j4 * 4 + 2][il] = __float2bfloat16(m2);
            sT[j4 * 4 + 3][il] = __float2bfloat16(m3);
        }
        __syncthreads();
#pragma unroll
        for (int p = 0; p < 2; ++p) {
            int idx = t + p * 256;
            int jr = idx >> 3, c = idx & 7;
            uint4 v = *reinterpret_cast<const uint4*>(&sT[jr][c * 8]);
            *reinterpret_cast<uint4*>(
                g_Mt + ((size_t)(b * N_ + j0 + jr)) * N_ + i0 + c * 8) = v;
        }
        __syncthreads();
    }
    atomicAdd(&sdeg[j4 * 4 + 0], s0);
    atomicAdd(&sdeg[j4 * 4 + 1], s1);
    atomicAdd(&sdeg[j4 * 4 + 2], s2);
    atomicAdd(&sdeg[j4 * 4 + 3], s3);
    __syncthreads();
    if (t < 64) g_deg_inv[b * N_ + j0 + t] = 1.0f / fmaxf(sdeg[t], 1.0f);
}

// ---------------------------------------------------------------------------
// Transpose + bf16 hi/lo split for x: [b][i][INC] fp32 -> g_T [b][d][i]
// ---------------------------------------------------------------------------
__global__ __launch_bounds__(256)
void convertT_x_kernel(const float* __restrict__ src) {
    constexpr int C = INC;
    __shared__ float sT[64][65];
    const int t = threadIdx.x;
    const int b = blockIdx.z, i0 = blockIdx.x * 64, d0 = blockIdx.y * 64;

#pragma unroll
    for (int p = 0; p < 4; ++p) {
        int e = t + p * 256;
        int row = e >> 4, c4 = e & 15;
        float4 v = *reinterpret_cast<const float4*>(
            src + ((size_t)(b * N_ + i0 + row)) * C + d0 + c4 * 4);
        sT[row][c4 * 4 + 0] = v.x; sT[row][c4 * 4 + 1] = v.y;
        sT[row][c4 * 4 + 2] = v.z; sT[row][c4 * 4 + 3] = v.w;
    }
    __syncthreads();

    const int d = t >> 2, ic = (t & 3) * 16;
    uint32_t hb[8], lb[8];
#pragma unroll
    for (int q = 0; q < 8; ++q) {
        float v0 = sT[ic + q * 2][d], v1 = sT[ic + q * 2 + 1][d];
        __nv_bfloat16 h0 = __float2bfloat16(v0);
        __nv_bfloat16 h1 = __float2bfloat16(v1);
        __nv_bfloat16 l0 = __float2bfloat16(v0 - __bfloat162float(h0));
        __nv_bfloat16 l1 = __float2bfloat16(v1 - __bfloat162float(h1));
        __nv_bfloat162 hp; hp.x = h0; hp.y = h1;
        __nv_bfloat162 lp; lp.x = l0; lp.y = l1;
        hb[q] = *reinterpret_cast<uint32_t*>(&hp);
        lb[q] = *reinterpret_cast<uint32_t*>(&lp);
    }
    size_t obase = ((size_t)(b * C + d0 + d)) * N_ + i0 + ic;
    reinterpret_cast<uint4*>(g_T_hi + obase)[0] = make_uint4(hb[0], hb[1], hb[2], hb[3]);
    reinterpret_cast<uint4*>(g_T_hi + obase)[1] = make_uint4(hb[4], hb[5], hb[6], hb[7]);
    reinterpret_cast<uint4*>(g_T_lo + obase)[0] = make_uint4(lb[0], lb[1], lb[2], lb[3]);
    reinterpret_cast<uint4*>(g_T_lo + obase)[1] = make_uint4(lb[4], lb[5], lb[6], lb[7]);
}

// ---------------------------------------------------------------------------
// HMMA aggregation: agg[b,j,d] = deg_inv[b,j] * sum_i Mt[b,j,i]*XT[b,d,i]
// CTA = 128 j x 128 d; 8 warps (4jw x 2dw); warp = 32j x 64d; K-step 64.
// cp.async double-buffered SW128 smem; bf16 hi/lo split of X.
// ---------------------------------------------------------------------------
template <int C>
__global__ __launch_bounds__(256, 2)
void agg_mma_kernel() {
    extern __shared__ __align__(1024) char smem[];
    constexpr int NIT = N_ / 64;
    constexpr uint32_t MOFF = 0, XOFF = 32768;

    const int tid = threadIdx.x, lane = tid & 31, wid = tid >> 5;
    const int b = blockIdx.z, j0 = blockIdx.x * 128, d0 = blockIdx.y * 128;
    const int jw = wid & 3, dw = wid >> 2;
    const uint32_t sb = smem_u32(smem);

    float acc[2][8][4];
#pragma unroll
    for (int mg = 0; mg < 2; ++mg)
#pragma unroll
        for (int ng = 0; ng < 8; ++ng)
#pragma unroll
            for (int q = 0; q < 4; ++q) acc[mg][ng][q] = 0.0f;

    const __nv_bfloat16* Mb = g_Mt + ((size_t)(b * N_ + j0)) * N_;

    auto load_stage = [&](int stage, int it) {
        const int i0 = it * 64;
        // mask tile: 128j x 64i bf16 (16 KB)
#pragma unroll
        for (int p = 0; p < 4; ++p) {
            int idx = tid + p * 256;
            int row = idx >> 3, c = idx & 7;
            const void* src = Mb + (size_t)row * N_ + i0 + c * 8;
            uint32_t dst = sb + MOFF + stage * 16384 +
                           SWZ((uint32_t)(row * 128 + c * 16));
            cpa16(dst, src);
        }
        // X tile: 2hl x 128d x 64i bf16 (32 KB)
#pragma unroll
        for (int p = 0; p < 8; ++p) {
            int idx = tid + p * 256;
            int r = idx >> 3, c = idx & 7;
            int hl = r >> 7, d = d0 + (r & 127);
            const __nv_bfloat16* g = hl ? g_T_lo : g_T_hi;
            const void* src = g + ((size_t)(b * C + d)) * N_ + i0 + c * 8;
            uint32_t dst = sb + XOFF + stage * 32768 + hl * 16384 +
                           SWZ((uint32_t)((r & 127) * 128 + c * 16));
            cpa16(dst, src);
        }
        asm volatile("cp.async.commit_group;");
    };

    load_stage(0, 0);

#pragma unroll 1
    for (int it = 0; it < NIT; ++it) {
        const int cur = it & 1;
        if (it + 1 < NIT) {
            load_stage(cur ^ 1, it + 1);
            asm volatile("cp.async.wait_group 1;");
        } else {
            asm volatile("cp.async.wait_group 0;");
        }
        __syncthreads();

        const uint32_t mbase = sb + MOFF + cur * 16384;
        const uint32_t xbase = sb + XOFF + cur * 32768;
#pragma unroll
        for (int kk = 0; kk < 4; ++kk) {
            uint32_t a[2][4];
#pragma unroll
            for (int mg = 0; mg < 2; ++mg) {
                uint32_t addr = mbase + SWZ((uint32_t)(
                    (jw * 32 + mg * 16 + (lane & 15)) * 128 +
                    kk * 32 + (lane >> 4) * 16));
                ldsm4(a[mg], addr);
            }
#pragma unroll
            for (int hl = 0; hl < 2; ++hl) {
                uint32_t bf[4][4];
#pragma unroll
                for (int ng = 0; ng < 4; ++ng) {
                    int rowB = dw * 64 + ng * 16 + (lane & 7) + ((lane >> 4) << 3);
                    uint32_t addr = xbase + hl * 16384 + SWZ((uint32_t)(
                        rowB * 128 + kk * 32 + ((lane >> 3) & 1) * 16));
                    ldsm4(bf[ng], addr);
                }
#pragma unroll
                for (int mg = 0; mg < 2; ++mg)
#pragma unroll
                    for (int ng = 0; ng < 4; ++ng)
#pragma unroll
                        for (int sub = 0; sub < 2; ++sub)
                            mma_bf16(acc[mg][ng * 2 + sub], a[mg],
                                     bf[ng][sub * 2], bf[ng][sub * 2 + 1]);
            }
        }
        __syncthreads();
    }

    // epilogue: scale by deg_inv, store fp32
    const int rbase = j0 + jw * 32 + (lane >> 2);
    float dv[2][2];
#pragma unroll
    for (int mg = 0; mg < 2; ++mg)
#pragma unroll
        for (int h = 0; h < 2; ++h)
            dv[mg][h] = g_deg_inv[b * N_ + rbase + mg * 16 + h * 8];

#pragma unroll
    for (int mg = 0; mg < 2; ++mg) {
#pragma unroll
        for (int ng = 0; ng < 8; ++ng) {
            int d = d0 + dw * 64 + ng * 8 + (lane & 3) * 2;
            int jl = j0 + jw * 32 + mg * 16 + (lane >> 2);
            float2 v0 = make_float2(acc[mg][ng][0] * dv[mg][0],
                                    acc[mg][ng][1] * dv[mg][0]);
            float2 v1 = make_float2(acc[mg][ng][2] * dv[mg][1],
                                    acc[mg][ng][3] * dv[mg][1]);
            *reinterpret_cast<float2*>(g_agg + ((size_t)(b * N_ + jl)) * C + d) = v0;
            *reinterpret_cast<float2*>(g_agg + ((size_t)(b * N_ + jl + 8)) * C + d) = v1;
        }
    }
}

// ---------------------------------------------------------------------------
// Dense layer 1: h = relu(agg1 @ W1_l + x @ W1_r + b1)  (SIMT fp32x2)
// Fused epilogue: writes g_h AND the transposed bf16 hi/lo split of h
// (g_T_hi/lo, stride HIDC) consumed by agg2 — kills the convertT_h pass.
// ---------------------------------------------------------------------------
__global__ __launch_bounds__(256)
void dense1_kernel(const float* __restrict__ x,
                   const float* __restrict__ W1l, const float* __restrict__ W1r,
                   const float* __restrict__ b1) {
    constexpr int TM = 64, TN = 128, KT = 16;
    __shared__ __align__(16) float sA[TM][KT + 1];
    __shared__ __align__(16) float sW[KT][TN];
    __shared__ __align__(16) float sT[TM][TN + 1];

    const int tid = threadIdx.x;
    const int tx = tid & 15, ty = tid >> 4;
    const int r0 = blockIdx.y * TM;
    const int c0 = blockIdx.x * TN;

    ull acc[4][4];
#pragma unroll
    for (int rr = 0; rr < 4; ++rr)
#pragma unroll
        for (int p = 0; p < 4; ++p) acc[rr][p] = 0ull;

#pragma unroll 1
    for (int kt = 0; kt < 16; ++kt) {
        const float* srcA = (kt < 8) ? g_agg : x;
        const float* srcW = (kt < 8) ? W1l : W1r;
        const int kb = (kt & 7) * KT;
        {
            int row = tid >> 2, kq = (tid & 3) * 4;
            float4 v = *reinterpret_cast<const float4*>(
                srcA + (size_t)(r0 + row) * INC + kb + kq);
            sA[row][kq] = v.x; sA[row][kq + 1] = v.y;
            sA[row][kq + 2] = v.z; sA[row][kq + 3] = v.w;
        }
#pragma unroll
        for (int r = 0; r < 2; ++r) {
            int e = tid + r * 256;
            int k = e >> 5, c4 = e & 31;
            reinterpret_cast<float4*>(sW[k])[c4] =
                *reinterpret_cast<const float4*>(
                    srcW + (size_t)(kb + k) * HIDC + c0 + c4 * 4);
        }
        __syncthreads();

#pragma unroll
        for (int k = 0; k < KT; ++k) {
            ull a2[4];
#pragma unroll
            for (int rr = 0; rr < 4; ++rr) {
                float a = sA[ty * 4 + rr][k];
                a2[rr] = pack2(a, a);
            }
            ull wv[4];
#pragma unroll
            for (int q = 0; q < 2; ++q) {
                float4 w = *reinterpret_cast<const float4*>(&sW[k][tx * 4 + q * 64]);
                wv[q * 2]     = pack2(w.x, w.y);
                wv[q * 2 + 1] = pack2(w.z, w.w);
            }
#pragma unroll
            for (int rr = 0; rr < 4; ++rr)
#pragma unroll
                for (int p = 0; p < 4; ++p)
                    acc[rr][p] = fma2(a2[rr], wv[p], acc[rr][p]);
        }
        __syncthreads();
    }

#pragma unroll
    for (int rr = 0; rr < 4; ++rr) {
        int row = ty * 4 + rr;
        float* hrow = g_h + (size_t)(r0 + row) * HIDC + c0;
#pragma unroll
        for (int q = 0; q < 2; ++q) {
            float4 bq = *reinterpret_cast<const float4*>(b1 + c0 + tx * 4 + q * 64);
            float2 lo = unpack2(acc[rr][q * 2]);
            float2 hi = unpack2(acc[rr][q * 2 + 1]);
            float4 o = make_float4(fmaxf(lo.x + bq.x, 0.0f), fmaxf(lo.y + bq.y, 0.0f),
                                   fmaxf(hi.x + bq.z, 0.0f), fmaxf(hi.y + bq.w, 0.0f));
            *reinterpret_cast<float4*>(hrow + tx * 4 + q * 64) = o;
            sT[row][tx * 4 + q * 64 + 0] = o.x;
            sT[row][tx * 4 + q * 64 + 1] = o.y;
            sT[row][tx * 4 + q * 64 + 2] = o.z;
            sT[row][tx * 4 + q * 64 + 3] = o.w;
        }
    }
    __syncthreads();

    // transpose + hi/lo split: h[64i][128d] -> g_T_hi/lo[b][d][i0..i0+64]
    const int bidx = r0 >> 11;            // batch
    const int i0 = r0 & (N_ - 1);         // i offset within batch
    const int iq = (tid & 7) * 8;
#pragma unroll
    for (int p = 0; p < 4; ++p) {
        int dl = (tid >> 3) + p * 32;
        uint32_t hb[4], lb[4];
#pragma unroll
        for (int q = 0; q < 4; ++q) {
            float v0 = sT[iq + q * 2][dl], v1 = sT[iq + q * 2 + 1][dl];
            __nv_bfloat16 h0 = __float2bfloat16(v0);
            __nv_bfloat16 h1 = __float2bfloat16(v1);
            __nv_bfloat16 l0 = __float2bfloat16(v0 - __bfloat162float(h0));
            __nv_bfloat16 l1 = __float2bfloat16(v1 - __bfloat162float(h1));
            __nv_bfloat162 hp; hp.x = h0; hp.y = h1;
            __nv_bfloat162 lp; lp.x = l0; lp.y = l1;
            hb[q] = *reinterpret_cast<uint32_t*>(&hp);
            lb[q] = *reinterpret_cast<uint32_t*>(&lp);
        }
        size_t obase = ((size_t)(bidx * HIDC + c0 + dl)) * N_ + i0 + iq;
        *reinterpret_cast<uint4*>(g_T_hi + obase) = make_uint4(hb[0], hb[1], hb[2], hb[3]);
        *reinterpret_cast<uint4*>(g_T_lo + obase) = make_uint4(lb[0], lb[1], lb[2], lb[3]);
    }
}

// ---------------------------------------------------------------------------
// Dense layer 2 + bias + log_softmax
// ---------------------------------------------------------------------------
__global__ __launch_bounds__(256)
void dense2_kernel(const float* __restrict__ W2l, const float* __restrict__ W2r,
                   const float* __restrict__ b2, float* __restrict__ out,
                   int write_raw) {
    constexpr int TM = 128, KT = 16;
    __shared__ __align__(16) float sA[TM][KT + 1];
    __shared__ __align__(16) float sW[KT][OUTC];
    __shared__ float sOut[TM][OUTC + 1];

    const int tid = threadIdx.x;
    const int tx = tid & 7, ty = tid >> 3;
    const int r0 = blockIdx.x * TM;

    ull acc[4][2];
#pragma unroll
    for (int rr = 0; rr < 4; ++rr) { acc[rr][0] = 0ull; acc[rr][1] = 0ull; }

#pragma unroll 1
    for (int kt = 0; kt < 32; ++kt) {
        const float* srcA = (kt < 16) ? g_agg : g_h;
        const float* srcW = (kt < 16) ? W2l : W2r;
        const int kb = (kt & 15) * KT;
#pragma unroll
        for (int r = 0; r < 2; ++r) {
            int e = tid + r * 256;
            int row = e >> 2, kq = (e & 3) * 4;
            float4 v = *reinterpret_cast<const float4*>(
                srcA + (size_t)(r0 + row) * HIDC + kb + kq);
            sA[row][kq] = v.x; sA[row][kq + 1] = v.y;
            sA[row][kq + 2] = v.z; sA[row][kq + 3] = v.w;
        }
        if (tid < 128) {
            int k = tid >> 3, c4 = tid & 7;
            reinterpret_cast<float4*>(sW[k])[c4] =
                *reinterpret_cast<const float4*>(srcW + (size_t)(kb + k) * OUTC + c4 * 4);
        }
        __syncthreads();

#pragma unroll
        for (int k = 0; k < KT; ++k) {
            float4 wq = *reinterpret_cast<const float4*>(&sW[k][tx * 4]);
            ull wv0 = pack2(wq.x, wq.y);
            ull wv1 = pack2(wq.z, wq.w);
#pragma unroll
            for (int rr = 0; rr < 4; ++rr) {
                float a = sA[ty * 4 + rr][k];
                ull a2 = pack2(a, a);
                acc[rr][0] = fma2(a2, wv0, acc[rr][0]);
                acc[rr][1] = fma2(a2, wv1, acc[rr][1]);
            }
        }
        __syncthreads();
    }

    float4 bq = *reinterpret_cast<const float4*>(b2 + tx * 4);
#pragma unroll
    for (int rr = 0; rr < 4; ++rr) {
        float2 lo = unpack2(acc[rr][0]);
        float2 hi = unpack2(acc[rr][1]);
        int row = ty * 4 + rr;
        sOut[row][tx * 4 + 0] = lo.x + bq.x;
        sOut[row][tx * 4 + 1] = lo.y + bq.y;
        sOut[row][tx * 4 + 2] = hi.x + bq.z;
        sOut[row][tx * 4 + 3] = hi.y + bq.w;
    }
    __syncthreads();

    const int lane = tid & 31, wid = tid >> 5;
#pragma unroll 1
    for (int rit = 0; rit < TM / 8; ++rit) {
        int row = rit * 8 + wid;
        float v = sOut[row][lane];
        float m = v;
#pragma unroll
        for (int o = 16; o > 0; o >>= 1)
            m = fmaxf(m, __shfl_xor_sync(0xffffffffu, m, o));
        float s = expf(v - m);
#pragma unroll
        for (int o = 16; o > 0; o >>= 1)
            s += __shfl_xor_sync(0xffffffffu, s, o);
        float lsm = v - m - logf(s);
        size_t gi = (size_t)(r0 + row) * OUTC + lane;
        out[gi] = lsm;
        if (write_raw) out[(size_t)BN * OUTC + gi] = v;
    }
}

// ---------------------------------------------------------------------------
extern "C" void kernel_launch(void* const* d_in, const int* in_sizes, int n_in,
                              void* d_out, int out_size) {
    const float* x   = (const float*)d_in[0];
    const int*   A   = (const int*)d_in[1];
    const float* W1l = (const float*)d_in[2];
    const float* W1r = (const float*)d_in[3];
    const float* b1  = (const float*)d_in[4];
    const float* W2l = (const float*)d_in[5];
    const float* W2r = (const float*)d_in[6];
    const float* b2  = (const float*)d_in[7];
    float* out = (float*)d_out;
    (void)in_sizes; (void)n_in;

    const int write_raw = (out_size >= 2 * BN * OUTC) ? 1 : 0;

    constexpr int AGG_SMEM = 32768 + 2 * 32768;  // 98304 B
    cudaFuncSetAttribute(agg_mma_kernel<INC>,
                         cudaFuncAttributeMaxDynamicSharedMemorySize, AGG_SMEM);
    cudaFuncSetAttribute(agg_mma_kernel<HIDC>,
                         cudaFuncAttributeMaxDynamicSharedMemorySize, AGG_SMEM);

    convertT_x_kernel<<<dim3(N_ / 64, INC / 64, B_), 256>>>(x);
    mask_convert_kernel<<<dim3(N_ / 64, B_), 256>>>(A);
    agg_mma_kernel<INC><<<dim3(N_ / 128, 1, B_), 256, AGG_SMEM>>>();
    dense1_kernel<<<dim3(HIDC / 128, BN / 64), 256>>>(x, W1l, W1r, b1);
    agg_mma_kernel<HIDC><<<dim3(N_ / 128, HIDC / 128, B_), 256, AGG_SMEM>>>();
    dense2_kernel<<<BN / 128, 256>>>(W2l, W2r, b2, out, write_raw);
}

// round 5
// speedup vs baseline: 1.1621x; 1.1621x over previous
#include <cuda_runtime.h>
#include <cuda_bf16.h>
#include <cstdint>
#include <cstddef>

// Problem constants
constexpr int B_ = 8;
constexpr int N_ = 2048;
constexpr int INC = 128;
constexpr int HIDC = 256;
constexpr int OUTC = 32;
constexpr int BN = B_ * N_;

// Scratch (device globals: no allocation allowed)
__device__ __align__(16) float g_deg_inv[BN];
__device__ __align__(16) __nv_bfloat16 g_agg_hi[(size_t)BN * HIDC];  // row-major
__device__ __align__(16) __nv_bfloat16 g_agg_lo[(size_t)BN * HIDC];
__device__ __align__(16) __nv_bfloat16 g_h_hi[(size_t)BN * HIDC];    // row-major
__device__ __align__(16) __nv_bfloat16 g_h_lo[(size_t)BN * HIDC];
__device__ __align__(16) __nv_bfloat16 g_x_hi[(size_t)BN * INC];     // row-major
__device__ __align__(16) __nv_bfloat16 g_x_lo[(size_t)BN * INC];
__device__ __align__(16) __nv_bfloat16 g_T_hi[(size_t)B_ * HIDC * N_];  // [b][d][i]
__device__ __align__(16) __nv_bfloat16 g_T_lo[(size_t)B_ * HIDC * N_];
__device__ __align__(16) __nv_bfloat16 g_Mt[(size_t)B_ * N_ * N_];      // [b][j][i]
__device__ __align__(16) __nv_bfloat16 g_W1t_hi[2 * HIDC * INC];   // [mtx][n][k]
__device__ __align__(16) __nv_bfloat16 g_W1t_lo[2 * HIDC * INC];
__device__ __align__(16) __nv_bfloat16 g_W2t_hi[2 * OUTC * HIDC];
__device__ __align__(16) __nv_bfloat16 g_W2t_lo[2 * OUTC * HIDC];

#define SWZ(off) ((off) ^ (((off) >> 3) & 0x70))

__device__ __forceinline__ uint32_t smem_u32(const void* p) {
    uint32_t a;
    asm("{ .reg .u64 t; cvta.to.shared.u64 t, %1; cvt.u32.u64 %0, t; }"
        : "=r"(a) : "l"(p));
    return a;
}
__device__ __forceinline__ void cpa16(uint32_t dst, const void* src) {
    asm volatile("cp.async.cg.shared.global [%0], [%1], 16;" :: "r"(dst), "l"(src));
}
__device__ __forceinline__ void ldsm4(uint32_t* r, uint32_t addr) {
    asm volatile("ldmatrix.sync.aligned.m8n8.x4.shared.b16 {%0,%1,%2,%3}, [%4];"
                 : "=r"(r[0]), "=r"(r[1]), "=r"(r[2]), "=r"(r[3]) : "r"(addr));
}
__device__ __forceinline__ void mma_bf16(float* c, const uint32_t* a,
                                         uint32_t b0, uint32_t b1) {
    asm volatile(
        "mma.sync.aligned.m16n8k16.row.col.f32.bf16.bf16.f32 "
        "{%0,%1,%2,%3}, {%4,%5,%6,%7}, {%8,%9}, {%0,%1,%2,%3};"
        : "+f"(c[0]), "+f"(c[1]), "+f"(c[2]), "+f"(c[3])
        : "r"(a[0]), "r"(a[1]), "r"(a[2]), "r"(a[3]), "r"(b0), "r"(b1));
}
// Pack two floats to hi bf162 + lo bf162 (residual split)
__device__ __forceinline__ void split2(float v0, float v1, uint32_t& hw, uint32_t& lw) {
    __nv_bfloat16 h0 = __float2bfloat16(v0);
    __nv_bfloat16 h1 = __float2bfloat16(v1);
    __nv_bfloat16 l0 = __float2bfloat16(v0 - __bfloat162float(h0));
    __nv_bfloat16 l1 = __float2bfloat16(v1 - __bfloat162float(h1));
    __nv_bfloat162 hp; hp.x = h0; hp.y = h1;
    __nv_bfloat162 lp; lp.x = l0; lp.y = l1;
    hw = *reinterpret_cast<uint32_t*>(&hp);
    lw = *reinterpret_cast<uint32_t*>(&lp);
}

// ---------------------------------------------------------------------------
// Weight prep: transpose + hi/lo split. W1l/W1r [128k][256n] -> [mtx][n][128k];
// W2l/W2r [256k][32n] -> [mtx][n][256k]. 81920 elements total.
// ---------------------------------------------------------------------------
__global__ __launch_bounds__(256)
void wprep_kernel(const float* __restrict__ W1l, const float* __restrict__ W1r,
                  const float* __restrict__ W2l, const float* __restrict__ W2r) {
    int idx = blockIdx.x * 256 + threadIdx.x;
    float v;
    __nv_bfloat16 *hi, *lo;
    int off;
    if (idx < 2 * HIDC * INC) {
        int mtx = idx >> 15, rem = idx & 32767;
        int n = rem >> 7, k = rem & 127;
        v = (mtx ? W1r : W1l)[k * HIDC + n];
        hi = g_W1t_hi; lo = g_W1t_lo; off = idx;
    } else {
        int j = idx - 2 * HIDC * INC;
        if (j >= 2 * OUTC * HIDC) return;
        int mtx = j >> 13, rem = j & 8191;
        int n = rem >> 8, k = rem & 255;
        v = (mtx ? W2r : W2l)[k * OUTC + n];
        hi = g_W2t_hi; lo = g_W2t_lo; off = j;
    }
    __nv_bfloat16 h = __float2bfloat16(v);
    hi[off] = h;
    lo[off] = __float2bfloat16(v - __bfloat162float(h));
}

// ---------------------------------------------------------------------------
// A int32 [b][i][j] -> Mt bf16 [b][j][i] + deg_inv.
// ---------------------------------------------------------------------------
__global__ __launch_bounds__(256)
void mask_convert_kernel(const int* __restrict__ A) {
    __shared__ __nv_bfloat16 sT[64][72];
    __shared__ float sdeg[64];
    const int t = threadIdx.x;
    const int j0 = blockIdx.x * 64, b = blockIdx.y;
    if (t < 64) sdeg[t] = 0.0f;
    __syncthreads();

    const int4* Ap = reinterpret_cast<const int4*>(A + (size_t)b * N_ * N_ + j0);
    const int j4 = t & 15;
    const int rbase = t >> 4;
    float s0 = 0, s1 = 0, s2 = 0, s3 = 0;

#pragma unroll 1
    for (int itile = 0; itile < N_ / 64; ++itile) {
        const int i0 = itile * 64;
#pragma unroll
        for (int p = 0; p < 4; ++p) {
            int il = rbase + p * 16;
            int4 v = Ap[(size_t)(i0 + il) * (N_ / 4) + j4];
            float m0 = v.x ? 1.0f : 0.0f, m1 = v.y ? 1.0f : 0.0f;
            float m2 = v.z ? 1.0f : 0.0f, m3 = v.w ? 1.0f : 0.0f;
            s0 += m0; s1 += m1; s2 += m2; s3 += m3;
            sT[j4 * 4 + 0][il] = __float2bfloat16(m0);
            sT[j4 * 4 + 1][il] = __float2bfloat16(m1);
            sT[j4 * 4 + 2][il] = __float2bfloat16(m2);
            sT[j4 * 4 + 3][il] = __float2bfloat16(m3);
        }
        __syncthreads();
#pragma unroll
        for (int p = 0; p < 2; ++p) {
            int idx = t + p * 256;
            int jr = idx >> 3, c = idx & 7;
            uint4 v = *reinterpret_cast<const uint4*>(&sT[jr][c * 8]);
            *reinterpret_cast<uint4*>(
                g_Mt + ((size_t)(b * N_ + j0 + jr)) * N_ + i0 + c * 8) = v;
        }
        __syncthreads();
    }
    atomicAdd(&sdeg[j4 * 4 + 0], s0);
    atomicAdd(&sdeg[j4 * 4 + 1], s1);
    atomicAdd(&sdeg[j4 * 4 + 2], s2);
    atomicAdd(&sdeg[j4 * 4 + 3], s3);
    __syncthreads();
    if (t < 64) g_deg_inv[b * N_ + j0 + t] = 1.0f / fmaxf(sdeg[t], 1.0f);
}

// ---------------------------------------------------------------------------
// x prep: row-major hi/lo split (for dense1) + transposed hi/lo (for agg1).
// ---------------------------------------------------------------------------
__global__ __launch_bounds__(256)
void convertT_x_kernel(const float* __restrict__ src) {
    constexpr int C = INC;
    __shared__ float sT[64][65];
    const int t = threadIdx.x;
    const int b = blockIdx.z, i0 = blockIdx.x * 64, d0 = blockIdx.y * 64;

#pragma unroll
    for (int p = 0; p < 4; ++p) {
        int e = t + p * 256;
        int row = e >> 4, c4 = e & 15;
        size_t goff = ((size_t)(b * N_ + i0 + row)) * C + d0 + c4 * 4;
        float4 v = *reinterpret_cast<const float4*>(src + goff);
        sT[row][c4 * 4 + 0] = v.x; sT[row][c4 * 4 + 1] = v.y;
        sT[row][c4 * 4 + 2] = v.z; sT[row][c4 * 4 + 3] = v.w;
        // row-major split
        uint32_t h0, l0, h1, l1;
        split2(v.x, v.y, h0, l0);
        split2(v.z, v.w, h1, l1);
        *reinterpret_cast<uint2*>(g_x_hi + goff) = make_uint2(h0, h1);
        *reinterpret_cast<uint2*>(g_x_lo + goff) = make_uint2(l0, l1);
    }
    __syncthreads();

    const int d = t >> 2, ic = (t & 3) * 16;
    uint32_t hb[8], lb[8];
#pragma unroll
    for (int q = 0; q < 8; ++q)
        split2(sT[ic + q * 2][d], sT[ic + q * 2 + 1][d], hb[q], lb[q]);
    size_t obase = ((size_t)(b * C + d0 + d)) * N_ + i0 + ic;
    reinterpret_cast<uint4*>(g_T_hi + obase)[0] = make_uint4(hb[0], hb[1], hb[2], hb[3]);
    reinterpret_cast<uint4*>(g_T_hi + obase)[1] = make_uint4(hb[4], hb[5], hb[6], hb[7]);
    reinterpret_cast<uint4*>(g_T_lo + obase)[0] = make_uint4(lb[0], lb[1], lb[2], lb[3]);
    reinterpret_cast<uint4*>(g_T_lo + obase)[1] = make_uint4(lb[4], lb[5], lb[6], lb[7]);
}

// ---------------------------------------------------------------------------
// HMMA aggregation: agg[b,j,d] = deg_inv[b,j] * sum_i Mt[b,j,i]*XT[b,d,i]
// CTA = 128 j x 128 d; 8 warps (4jw x 2dw); epilogue writes bf16 hi/lo.
// ---------------------------------------------------------------------------
template <int C>
__global__ __launch_bounds__(256, 2)
void agg_mma_kernel() {
    extern __shared__ __align__(1024) char smem[];
    constexpr int NIT = N_ / 64;
    constexpr uint32_t MOFF = 0, XOFF = 32768;

    const int tid = threadIdx.x, lane = tid & 31, wid = tid >> 5;
    const int b = blockIdx.z, j0 = blockIdx.x * 128, d0 = blockIdx.y * 128;
    const int jw = wid & 3, dw = wid >> 2;
    const uint32_t sb = smem_u32(smem);

    float acc[2][8][4];
#pragma unroll
    for (int mg = 0; mg < 2; ++mg)
#pragma unroll
        for (int ng = 0; ng < 8; ++ng)
#pragma unroll
            for (int q = 0; q < 4; ++q) acc[mg][ng][q] = 0.0f;

    const __nv_bfloat16* Mb = g_Mt + ((size_t)(b * N_ + j0)) * N_;

    auto load_stage = [&](int stage, int it) {
        const int i0 = it * 64;
#pragma unroll
        for (int p = 0; p < 4; ++p) {
            int idx = tid + p * 256;
            int row = idx >> 3, c = idx & 7;
            cpa16(sb + MOFF + stage * 16384 + SWZ((uint32_t)(row * 128 + c * 16)),
                  Mb + (size_t)row * N_ + i0 + c * 8);
        }
#pragma unroll
        for (int p = 0; p < 8; ++p) {
            int idx = tid + p * 256;
            int r = idx >> 3, c = idx & 7;
            int hl = r >> 7, d = d0 + (r & 127);
            const __nv_bfloat16* g = hl ? g_T_lo : g_T_hi;
            cpa16(sb + XOFF + stage * 32768 + hl * 16384 +
                      SWZ((uint32_t)((r & 127) * 128 + c * 16)),
                  g + ((size_t)(b * C + d)) * N_ + i0 + c * 8);
        }
        asm volatile("cp.async.commit_group;");
    };

    load_stage(0, 0);

#pragma unroll 1
    for (int it = 0; it < NIT; ++it) {
        const int cur = it & 1;
        if (it + 1 < NIT) {
            load_stage(cur ^ 1, it + 1);
            asm volatile("cp.async.wait_group 1;");
        } else {
            asm volatile("cp.async.wait_group 0;");
        }
        __syncthreads();

        const uint32_t mbase = sb + MOFF + cur * 16384;
        const uint32_t xbase = sb + XOFF + cur * 32768;
#pragma unroll
        for (int kk = 0; kk < 4; ++kk) {
            uint32_t a[2][4];
#pragma unroll
            for (int mg = 0; mg < 2; ++mg) {
                uint32_t addr = mbase + SWZ((uint32_t)(
                    (jw * 32 + mg * 16 + (lane & 15)) * 128 +
                    kk * 32 + (lane >> 4) * 16));
                ldsm4(a[mg], addr);
            }
#pragma unroll
            for (int hl = 0; hl < 2; ++hl) {
                uint32_t bf[4][4];
#pragma unroll
                for (int ng = 0; ng < 4; ++ng) {
                    int rowB = dw * 64 + ng * 16 + (lane & 7) + ((lane >> 4) << 3);
                    uint32_t addr = xbase + hl * 16384 + SWZ((uint32_t)(
                        rowB * 128 + kk * 32 + ((lane >> 3) & 1) * 16));
                    ldsm4(bf[ng], addr);
                }
#pragma unroll
                for (int mg = 0; mg < 2; ++mg)
#pragma unroll
                    for (int ng = 0; ng < 4; ++ng)
#pragma unroll
                        for (int sub = 0; sub < 2; ++sub)
                            mma_bf16(acc[mg][ng * 2 + sub], a[mg],
                                     bf[ng][sub * 2], bf[ng][sub * 2 + 1]);
            }
        }
        __syncthreads();
    }

    // epilogue: scale by deg_inv, hi/lo split, bf16 stores
    const int rbase = j0 + jw * 32 + (lane >> 2);
    float dv[2][2];
#pragma unroll
    for (int mg = 0; mg < 2; ++mg)
#pragma unroll
        for (int h = 0; h < 2; ++h)
            dv[mg][h] = g_deg_inv[b * N_ + rbase + mg * 16 + h * 8];

#pragma unroll
    for (int mg = 0; mg < 2; ++mg) {
#pragma unroll
        for (int ng = 0; ng < 8; ++ng) {
            int d = d0 + dw * 64 + ng * 8 + (lane & 3) * 2;
            size_t r0o = ((size_t)(b * N_ + j0 + jw * 32 + mg * 16 + (lane >> 2))) * C + d;
            uint32_t hw, lw;
            split2(acc[mg][ng][0] * dv[mg][0], acc[mg][ng][1] * dv[mg][0], hw, lw);
            *reinterpret_cast<uint32_t*>(g_agg_hi + r0o) = hw;
            *reinterpret_cast<uint32_t*>(g_agg_lo + r0o) = lw;
            split2(acc[mg][ng][2] * dv[mg][1], acc[mg][ng][3] * dv[mg][1], hw, lw);
            *reinterpret_cast<uint32_t*>(g_agg_hi + r0o + (size_t)8 * C) = hw;
            *reinterpret_cast<uint32_t*>(g_agg_lo + r0o + (size_t)8 * C) = lw;
        }
    }
}

// ---------------------------------------------------------------------------
// Dense1 HMMA: h = relu(agg1 @ W1_l + x @ W1_r + b1); 3-term bf16 split.
// CTA 128 rows x 128 cols; 12 stages. Epilogue: h row-major hi/lo + h^T hi/lo.
// ---------------------------------------------------------------------------
__global__ __launch_bounds__(256, 2)
void dense1_mma_kernel(const float* __restrict__ b1) {
    extern __shared__ __align__(1024) char smem[];
    const int tid = threadIdx.x, lane = tid & 31, wid = tid >> 5;
    const int mw = wid & 3, nw = wid >> 2;
    const int r0 = blockIdx.x * 128, c0 = blockIdx.y * 128;
    const int b = r0 >> 11, i0 = r0 & (N_ - 1);
    const uint32_t sb = smem_u32(smem);

    float acc[2][8][4];
#pragma unroll
    for (int mg = 0; mg < 2; ++mg)
#pragma unroll
        for (int ng = 0; ng < 8; ++ng)
#pragma unroll
            for (int q = 0; q < 4; ++q) acc[mg][ng][q] = 0.0f;

    const __nv_bfloat16* Asrc[6] = {g_agg_hi, g_agg_lo, g_agg_hi,
                                    g_x_hi,   g_x_lo,   g_x_hi};
    const __nv_bfloat16* Bsrc[6] = {g_W1t_hi, g_W1t_hi, g_W1t_lo,
                                    g_W1t_hi + HIDC * INC, g_W1t_hi + HIDC * INC,
                                    g_W1t_lo + HIDC * INC};

    auto load_stage = [&](int st, int sidx) {
        const int p = sidx >> 1, kb = (sidx & 1) * 64;
        const __nv_bfloat16* As = Asrc[p];
        const __nv_bfloat16* Bs = Bsrc[p];
#pragma unroll
        for (int q = 0; q < 4; ++q) {
            int idx = tid + q * 256;
            int row = idx >> 3, c = idx & 7;
            cpa16(sb + st * 32768 + SWZ((uint32_t)(row * 128 + c * 16)),
                  As + (size_t)(r0 + row) * INC + kb + c * 8);
        }
#pragma unroll
        for (int q = 0; q < 4; ++q) {
            int idx = tid + q * 256;
            int row = idx >> 3, c = idx & 7;
            cpa16(sb + st * 32768 + 16384 + SWZ((uint32_t)(row * 128 + c * 16)),
                  Bs + (size_t)(c0 + row) * INC + kb + c * 8);
        }
        asm volatile("cp.async.commit_group;");
    };

    load_stage(0, 0);

#pragma unroll 1
    for (int s = 0; s < 12; ++s) {
        const int cur = s & 1;
        if (s + 1 < 12) {
            load_stage(cur ^ 1, s + 1);
            asm volatile("cp.async.wait_group 1;");
        } else {
            asm volatile("cp.async.wait_group 0;");
        }
        __syncthreads();

        const uint32_t abase = sb + cur * 32768;
        const uint32_t bbase = abase + 16384;
#pragma unroll
        for (int kk = 0; kk < 4; ++kk) {
            uint32_t a[2][4];
#pragma unroll
            for (int mg = 0; mg < 2; ++mg) {
                uint32_t addr = abase + SWZ((uint32_t)(
                    (mw * 32 + mg * 16 + (lane & 15)) * 128 +
                    kk * 32 + (lane >> 4) * 16));
                ldsm4(a[mg], addr);
            }
            uint32_t bf[4][4];
#pragma unroll
            for (int ng = 0; ng < 4; ++ng) {
                int rowB = nw * 64 + ng * 16 + (lane & 7) + ((lane >> 4) << 3);
                uint32_t addr = bbase + SWZ((uint32_t)(
                    rowB * 128 + kk * 32 + ((lane >> 3) & 1) * 16));
                ldsm4(bf[ng], addr);
            }
#pragma unroll
            for (int mg = 0; mg < 2; ++mg)
#pragma unroll
                for (int ng = 0; ng < 4; ++ng)
#pragma unroll
                    for (int sub = 0; sub < 2; ++sub)
                        mma_bf16(acc[mg][ng * 2 + sub], a[mg],
                                 bf[ng][sub * 2], bf[ng][sub * 2 + 1]);
        }
        __syncthreads();
    }

    // bias + relu in place, then row-major hi/lo stores
#pragma unroll
    for (int mg = 0; mg < 2; ++mg) {
#pragma unroll
        for (int ng = 0; ng < 8; ++ng) {
            int dloc = nw * 64 + ng * 8 + (lane & 3) * 2;
            float2 bv = *reinterpret_cast<const float2*>(b1 + c0 + dloc);
            acc[mg][ng][0] = fmaxf(acc[mg][ng][0] + bv.x, 0.0f);
            acc[mg][ng][1] = fmaxf(acc[mg][ng][1] + bv.y, 0.0f);
            acc[mg][ng][2] = fmaxf(acc[mg][ng][2] + bv.x, 0.0f);
            acc[mg][ng][3] = fmaxf(acc[mg][ng][3] + bv.y, 0.0f);
            size_t ro = ((size_t)(r0 + mw * 32 + mg * 16 + (lane >> 2))) * HIDC +
                        c0 + dloc;
            uint32_t hw, lw;
            split2(acc[mg][ng][0], acc[mg][ng][1], hw, lw);
            *reinterpret_cast<uint32_t*>(g_h_hi + ro) = hw;
            *reinterpret_cast<uint32_t*>(g_h_lo + ro) = lw;
            split2(acc[mg][ng][2], acc[mg][ng][3], hw, lw);
            *reinterpret_cast<uint32_t*>(g_h_hi + ro + (size_t)8 * HIDC) = hw;
            *reinterpret_cast<uint32_t*>(g_h_lo + ro + (size_t)8 * HIDC) = lw;
        }
    }

    // transposed hi/lo stores via smem (two 64-col halves)
    float* sT = reinterpret_cast<float*>(smem);
#pragma unroll 1
    for (int half = 0; half < 2; ++half) {
        __syncthreads();
        if (nw == half) {
#pragma unroll
            for (int mg = 0; mg < 2; ++mg)
#pragma unroll
                for (int ng = 0; ng < 8; ++ng)
#pragma unroll
                    for (int q = 0; q < 4; ++q) {
                        int irow = mw * 32 + mg * 16 + (lane >> 2) + (q >> 1) * 8;
                        int dl = ng * 8 + (lane & 3) * 2 + (q & 1);
                        sT[irow * 65 + dl] = acc[mg][ng][q];
                    }
        }
        __syncthreads();
        const int dl = tid >> 2, ic = (tid & 3) * 32;
        uint32_t hb[16], lb[16];
#pragma unroll
        for (int q = 0; q < 16; ++q)
            split2(sT[(ic + q * 2) * 65 + dl], sT[(ic + q * 2 + 1) * 65 + dl],
                   hb[q], lb[q]);
        size_t ob = ((size_t)(b * HIDC + c0 + half * 64 + dl)) * N_ + i0 + ic;
#pragma unroll
        for (int q = 0; q < 4; ++q) {
            reinterpret_cast<uint4*>(g_T_hi + ob)[q] =
                make_uint4(hb[q * 4], hb[q * 4 + 1], hb[q * 4 + 2], hb[q * 4 + 3]);
            reinterpret_cast<uint4*>(g_T_lo + ob)[q] =
                make_uint4(lb[q * 4], lb[q * 4 + 1], lb[q * 4 + 2], lb[q * 4 + 3]);
        }
    }
}

// ---------------------------------------------------------------------------
// Dense2 HMMA + bias + log_softmax. CTA 128 rows x 32 cols; 24 stages.
// ---------------------------------------------------------------------------
__global__ __launch_bounds__(256)
void dense2_mma_kernel(const float* __restrict__ b2, float* __restrict__ out,
                       int write_raw) {
    extern __shared__ __align__(1024) char smem[];
    const int tid = threadIdx.x, lane = tid & 31, wid = tid >> 5;
    const int r0 = blockIdx.x * 128;
    const uint32_t sb = smem_u32(smem);
    constexpr int STG = 20480;  // A 16 KB + B 4 KB

    float acc[4][4];
#pragma unroll
    for (int t = 0; t < 4; ++t)
#pragma unroll
        for (int q = 0; q < 4; ++q) acc[t][q] = 0.0f;

    const __nv_bfloat16* Asrc[6] = {g_agg_hi, g_agg_lo, g_agg_hi,
                                    g_h_hi,   g_h_lo,   g_h_hi};
    const __nv_bfloat16* Bsrc[6] = {g_W2t_hi, g_W2t_hi, g_W2t_lo,
                                    g_W2t_hi + OUTC * HIDC, g_W2t_hi + OUTC * HIDC,
                                    g_W2t_lo + OUTC * HIDC};

    auto load_stage = [&](int st, int sidx) {
        const int p = sidx >> 2, kb = (sidx & 3) * 64;
        const __nv_bfloat16* As = Asrc[p];
        const __nv_bfloat16* Bs = Bsrc[p];
#pragma unroll
        for (int q = 0; q < 4; ++q) {
            int idx = tid + q * 256;
            int row = idx >> 3, c = idx & 7;
            cpa16(sb + st * STG + SWZ((uint32_t)(row * 128 + c * 16)),
                  As + (size_t)(r0 + row) * HIDC + kb + c * 8);
        }
        {
            int row = tid >> 3, c = tid & 7;
            cpa16(sb + st * STG + 16384 + SWZ((uint32_t)(row * 128 + c * 16)),
                  Bs + (size_t)row * HIDC + kb + c * 8);
        }
        asm volatile("cp.async.commit_group;");
    };

    load_stage(0, 0);

#pragma unroll 1
    for (int s = 0; s < 24; ++s) {
        const int cur = s & 1;
        if (s + 1 < 24) {
            load_stage(cur ^ 1, s + 1);
            asm volatile("cp.async.wait_group 1;");
        } else {
            asm volatile("cp.async.wait_group 0;");
        }
        __syncthreads();

        const uint32_t abase = sb + cur * STG;
        const uint32_t bbase = abase + 16384;
#pragma unroll
        for (int kk = 0; kk < 4; ++kk) {
            uint32_t a[4];
            {
                uint32_t addr = abase + SWZ((uint32_t)(
                    (wid * 16 + (lane & 15)) * 128 + kk * 32 + (lane >> 4) * 16));
                ldsm4(a, addr);
            }
            uint32_t bf[2][4];
#pragma unroll
            for (int ng = 0; ng < 2; ++ng) {
                int rowB = ng * 16 + (lane & 7) + ((lane >> 4) << 3);
                uint32_t addr = bbase + SWZ((uint32_t)(
                    rowB * 128 + kk * 32 + ((lane >> 3) & 1) * 16));
                ldsm4(bf[ng], addr);
            }
#pragma unroll
            for (int ng = 0; ng < 2; ++ng)
#pragma unroll
                for (int sub = 0; sub < 2; ++sub)
                    mma_bf16(acc[ng * 2 + sub], a, bf[ng][sub * 2], bf[ng][sub * 2 + 1]);
        }
        __syncthreads();
    }

    // stage to smem with bias, then warp-per-row log_softmax
    float* sOut = reinterpret_cast<float*>(smem);  // [128][33]
    __syncthreads();
#pragma unroll
    for (int t = 0; t < 4; ++t) {
        int d = t * 8 + (lane & 3) * 2;
        float2 bv = *reinterpret_cast<const float2*>(b2 + d);
        int row = wid * 16 + (lane >> 2);
        sOut[row * 33 + d] = acc[t][0] + bv.x;
        sOut[row * 33 + d + 1] = acc[t][1] + bv.y;
        sOut[(row + 8) * 33 + d] = acc[t][2] + bv.x;
        sOut[(row + 8) * 33 + d + 1] = acc[t][3] + bv.y;
    }
    __syncthreads();

#pragma unroll 1
    for (int rit = 0; rit < 16; ++rit) {
        int row = rit * 8 + wid;
        float v = sOut[row * 33 + lane];
        float m = v;
#pragma unroll
        for (int o = 16; o > 0; o >>= 1)
            m = fmaxf(m, __shfl_xor_sync(0xffffffffu, m, o));
        float s = expf(v - m);
#pragma unroll
        for (int o = 16; o > 0; o >>= 1)
            s += __shfl_xor_sync(0xffffffffu, s, o);
        float lsm = v - m - logf(s);
        size_t gi = (size_t)(r0 + row) * OUTC + lane;
        out[gi] = lsm;
        if (write_raw) out[(size_t)BN * OUTC + gi] = v;
    }
}

// ---------------------------------------------------------------------------
extern "C" void kernel_launch(void* const* d_in, const int* in_sizes, int n_in,
                              void* d_out, int out_size) {
    const float* x   = (const float*)d_in[0];
    const int*   A   = (const int*)d_in[1];
    const float* W1l = (const float*)d_in[2];
    const float* W1r = (const float*)d_in[3];
    const float* b1  = (const float*)d_in[4];
    const float* W2l = (const float*)d_in[5];
    const float* W2r = (const float*)d_in[6];
    const float* b2  = (const float*)d_in[7];
    float* out = (float*)d_out;
    (void)in_sizes; (void)n_in;

    const int write_raw = (out_size >= 2 * BN * OUTC) ? 1 : 0;

    constexpr int AGG_SMEM = 32768 + 2 * 32768;  // 98304
    constexpr int D1_SMEM = 2 * 32768;           // 65536
    constexpr int D2_SMEM = 2 * 20480;           // 40960
    cudaFuncSetAttribute(agg_mma_kernel<INC>,
                         cudaFuncAttributeMaxDynamicSharedMemorySize, AGG_SMEM);
    cudaFuncSetAttribute(agg_mma_kernel<HIDC>,
                         cudaFuncAttributeMaxDynamicSharedMemorySize, AGG_SMEM);
    cudaFuncSetAttribute(dense1_mma_kernel,
                         cudaFuncAttributeMaxDynamicSharedMemorySize, D1_SMEM);
    cudaFuncSetAttribute(dense2_mma_kernel,
                         cudaFuncAttributeMaxDynamicSharedMemorySize, D2_SMEM);

    wprep_kernel<<<320, 256>>>(W1l, W1r, W2l, W2r);
    convertT_x_kernel<<<dim3(N_ / 64, INC / 64, B_), 256>>>(x);
    mask_convert_kernel<<<dim3(N_ / 64, B_), 256>>>(A);
    agg_mma_kernel<INC><<<dim3(N_ / 128, 1, B_), 256, AGG_SMEM>>>();
    dense1_mma_kernel<<<dim3(BN / 128, HIDC / 128), 256, D1_SMEM>>>(b1);
    agg_mma_kernel<HIDC><<<dim3(N_ / 128, HIDC / 128, B_), 256, AGG_SMEM>>>();
    dense2_mma_kernel<<<BN / 128, 256, D2_SMEM>>>(b2, out, write_raw);
}

// round 6
// speedup vs baseline: 1.3853x; 1.1920x over previous
#include <cuda_runtime.h>
#include <cuda_bf16.h>
#include <cstdint>
#include <cstddef>

// Problem constants
constexpr int B_ = 8;
constexpr int N_ = 2048;
constexpr int INC = 128;
constexpr int HIDC = 256;
constexpr int OUTC = 32;
constexpr int BN = B_ * N_;

// Scratch (device globals: no allocation allowed)
__device__ __align__(16) float g_deg_inv[BN];
__device__ __align__(16) __nv_bfloat16 g_agg_hi[(size_t)BN * HIDC];  // row-major
__device__ __align__(16) __nv_bfloat16 g_agg_lo[(size_t)BN * HIDC];
__device__ __align__(16) __nv_bfloat16 g_h_hi[(size_t)BN * HIDC];    // row-major
__device__ __align__(16) __nv_bfloat16 g_h_lo[(size_t)BN * HIDC];
__device__ __align__(16) __nv_bfloat16 g_x_hi[(size_t)BN * INC];     // row-major
__device__ __align__(16) __nv_bfloat16 g_x_lo[(size_t)BN * INC];
__device__ __align__(16) __nv_bfloat16 g_T_hi[(size_t)B_ * HIDC * N_];  // [b][d][i]
__device__ __align__(16) __nv_bfloat16 g_T_lo[(size_t)B_ * HIDC * N_];
// Mask tiles, PRE-SWIZZLED: [b][jt(32)][it(32)][8192 bytes] (64j x 64i bf16)
__device__ __align__(16) __nv_bfloat16 g_Mt[(size_t)B_ * N_ * N_];
__device__ __align__(16) __nv_bfloat16 g_W1t_hi[2 * HIDC * INC];   // [mtx][n][k]
__device__ __align__(16) __nv_bfloat16 g_W1t_lo[2 * HIDC * INC];
__device__ __align__(16) __nv_bfloat16 g_W2t_hi[2 * OUTC * HIDC];
__device__ __align__(16) __nv_bfloat16 g_W2t_lo[2 * OUTC * HIDC];

#define SWZ(off) ((off) ^ (((off) >> 3) & 0x70))

__device__ __forceinline__ uint32_t smem_u32(const void* p) {
    uint32_t a;
    asm("{ .reg .u64 t; cvta.to.shared.u64 t, %1; cvt.u32.u64 %0, t; }"
        : "=r"(a) : "l"(p));
    return a;
}
__device__ __forceinline__ void cpa16(uint32_t dst, const void* src) {
    asm volatile("cp.async.cg.shared.global [%0], [%1], 16;" :: "r"(dst), "l"(src));
}
__device__ __forceinline__ void ldsm4(uint32_t* r, uint32_t addr) {
    asm volatile("ldmatrix.sync.aligned.m8n8.x4.shared.b16 {%0,%1,%2,%3}, [%4];"
                 : "=r"(r[0]), "=r"(r[1]), "=r"(r[2]), "=r"(r[3]) : "r"(addr));
}
__device__ __forceinline__ void mma_bf16(float* c, const uint32_t* a,
                                         uint32_t b0, uint32_t b1) {
    asm volatile(
        "mma.sync.aligned.m16n8k16.row.col.f32.bf16.bf16.f32 "
        "{%0,%1,%2,%3}, {%4,%5,%6,%7}, {%8,%9}, {%0,%1,%2,%3};"
        : "+f"(c[0]), "+f"(c[1]), "+f"(c[2]), "+f"(c[3])
        : "r"(a[0]), "r"(a[1]), "r"(a[2]), "r"(a[3]), "r"(b0), "r"(b1));
}
__device__ __forceinline__ void split2(float v0, float v1, uint32_t& hw, uint32_t& lw) {
    __nv_bfloat16 h0 = __float2bfloat16(v0);
    __nv_bfloat16 h1 = __float2bfloat16(v1);
    __nv_bfloat16 l0 = __float2bfloat16(v0 - __bfloat162float(h0));
    __nv_bfloat16 l1 = __float2bfloat16(v1 - __bfloat162float(h1));
    __nv_bfloat162 hp; hp.x = h0; hp.y = h1;
    __nv_bfloat162 lp; lp.x = l0; lp.y = l1;
    hw = *reinterpret_cast<uint32_t*>(&hp);
    lw = *reinterpret_cast<uint32_t*>(&lp);
}

// ---------------------------------------------------------------------------
// Weight prep: transpose + hi/lo split.
// ---------------------------------------------------------------------------
__global__ __launch_bounds__(256)
void wprep_kernel(const float* __restrict__ W1l, const float* __restrict__ W1r,
                  const float* __restrict__ W2l, const float* __restrict__ W2r) {
    int idx = blockIdx.x * 256 + threadIdx.x;
    float v;
    __nv_bfloat16 *hi, *lo;
    int off;
    if (idx < 2 * HIDC * INC) {
        int mtx = idx >> 15, rem = idx & 32767;
        int n = rem >> 7, k = rem & 127;
        v = (mtx ? W1r : W1l)[k * HIDC + n];
        hi = g_W1t_hi; lo = g_W1t_lo; off = idx;
    } else {
        int j = idx - 2 * HIDC * INC;
        if (j >= 2 * OUTC * HIDC) return;
        int mtx = j >> 13, rem = j & 8191;
        int n = rem >> 8, k = rem & 255;
        v = (mtx ? W2r : W2l)[k * OUTC + n];
        hi = g_W2t_hi; lo = g_W2t_lo; off = j;
    }
    __nv_bfloat16 h = __float2bfloat16(v);
    hi[off] = h;
    lo[off] = __float2bfloat16(v - __bfloat162float(h));
}

// ---------------------------------------------------------------------------
// x prep: row-major hi/lo split (for dense1) + transposed hi/lo (for agg1).
// ---------------------------------------------------------------------------
__global__ __launch_bounds__(256)
void convertT_x_kernel(const float* __restrict__ src) {
    constexpr int C = INC;
    __shared__ float sT[64][65];
    const int t = threadIdx.x;
    const int b = blockIdx.z, i0 = blockIdx.x * 64, d0 = blockIdx.y * 64;

#pragma unroll
    for (int p = 0; p < 4; ++p) {
        int e = t + p * 256;
        int row = e >> 4, c4 = e & 15;
        size_t goff = ((size_t)(b * N_ + i0 + row)) * C + d0 + c4 * 4;
        float4 v = *reinterpret_cast<const float4*>(src + goff);
        sT[row][c4 * 4 + 0] = v.x; sT[row][c4 * 4 + 1] = v.y;
        sT[row][c4 * 4 + 2] = v.z; sT[row][c4 * 4 + 3] = v.w;
        uint32_t h0, l0, h1, l1;
        split2(v.x, v.y, h0, l0);
        split2(v.z, v.w, h1, l1);
        *reinterpret_cast<uint2*>(g_x_hi + goff) = make_uint2(h0, h1);
        *reinterpret_cast<uint2*>(g_x_lo + goff) = make_uint2(l0, l1);
    }
    __syncthreads();

    const int d = t >> 2, ic = (t & 3) * 16;
    uint32_t hb[8], lb[8];
#pragma unroll
    for (int q = 0; q < 8; ++q)
        split2(sT[ic + q * 2][d], sT[ic + q * 2 + 1][d], hb[q], lb[q]);
    size_t obase = ((size_t)(b * C + d0 + d)) * N_ + i0 + ic;
    reinterpret_cast<uint4*>(g_T_hi + obase)[0] = make_uint4(hb[0], hb[1], hb[2], hb[3]);
    reinterpret_cast<uint4*>(g_T_hi + obase)[1] = make_uint4(hb[4], hb[5], hb[6], hb[7]);
    reinterpret_cast<uint4*>(g_T_lo + obase)[0] = make_uint4(lb[0], lb[1], lb[2], lb[3]);
    reinterpret_cast<uint4*>(g_T_lo + obase)[1] = make_uint4(lb[4], lb[5], lb[6], lb[7]);
}

// ---------------------------------------------------------------------------
// agg1 (fused): reads A, converts mask in-pipeline (degree fused), HMMAs with
// x^T hi/lo, writes agg1 bf16 hi/lo + pre-swizzled mask tiles + deg_inv.
// CTA = 64 j x 128 d; 8 warps (2jw x 4dw); warp = 32j x 32d; K-step 64 i.
// ---------------------------------------------------------------------------
__global__ __launch_bounds__(256, 2)
void agg1_kernel(const int* __restrict__ A) {
    extern __shared__ __align__(1024) char smem[];
    constexpr int C = INC;
    constexpr int NIT = N_ / 64;
    constexpr int STG = 40960;  // mask 8 KB + X 32 KB
    const int tid = threadIdx.x, lane = tid & 31, wid = tid >> 5;
    const int b = blockIdx.z, jt = blockIdx.x, j0 = jt * 64;
    const int jw = wid & 1, dw = wid >> 1;
    const uint32_t sb = smem_u32(smem);
    float* sdeg = reinterpret_cast<float*>(smem + 2 * STG);

    if (tid < 64) sdeg[tid] = 0.0f;

    float acc[2][4][4];
#pragma unroll
    for (int mg = 0; mg < 2; ++mg)
#pragma unroll
        for (int ng = 0; ng < 4; ++ng)
#pragma unroll
            for (int q = 0; q < 4; ++q) acc[mg][ng][q] = 0.0f;

    const int jj = tid & 63, iq = tid >> 6;
    const int* Ap = A + (size_t)b * N_ * N_ + j0 + jj;
    float degloc = 0.0f;

    auto fill = [&](int stage, int it) {
        const int i0 = it * 64;
        // mask: LDG over j (coalesced), convert, transposed STS (bf162 pairs)
        {
            char* mb = smem + stage * STG;
#pragma unroll
            for (int r = 0; r < 8; ++r) {
                int il = iq * 16 + r * 2;
                int a0 = Ap[(size_t)(i0 + il) * N_];
                int a1 = Ap[(size_t)(i0 + il + 1) * N_];
                float m0 = a0 ? 1.0f : 0.0f;
                float m1 = a1 ? 1.0f : 0.0f;
                degloc += m0 + m1;
                __nv_bfloat162 mv = __floats2bfloat162_rn(m0, m1);
                *reinterpret_cast<__nv_bfloat162*>(
                    mb + SWZ((uint32_t)(jj * 128 + il * 2))) = mv;
            }
        }
        // X tile via cp.async: 2hl x 128d x 64i
#pragma unroll
        for (int p = 0; p < 8; ++p) {
            int idx = tid + p * 256;
            int r = idx >> 3, c = idx & 7;
            int hl = r >> 7, d = r & 127;
            const __nv_bfloat16* g = hl ? g_T_lo : g_T_hi;
            cpa16(sb + stage * STG + 8192 + hl * 16384 +
                      SWZ((uint32_t)(d * 128 + c * 16)),
                  g + ((size_t)(b * C + d)) * N_ + i0 + c * 8);
        }
        asm volatile("cp.async.commit_group;");
    };

    fill(0, 0);

#pragma unroll 1
    for (int it = 0; it < NIT; ++it) {
        const int cur = it & 1;
        if (it + 1 < NIT) {
            fill(cur ^ 1, it + 1);
            asm volatile("cp.async.wait_group 1;");
        } else {
            asm volatile("cp.async.wait_group 0;");
        }
        __syncthreads();

        const uint32_t mbase = sb + cur * STG;
        const uint32_t xbase = mbase + 8192;
#pragma unroll
        for (int kk = 0; kk < 4; ++kk) {
            uint32_t a[2][4];
#pragma unroll
            for (int mg = 0; mg < 2; ++mg) {
                uint32_t addr = mbase + SWZ((uint32_t)(
                    (jw * 32 + mg * 16 + (lane & 15)) * 128 +
                    kk * 32 + (lane >> 4) * 16));
                ldsm4(a[mg], addr);
            }
#pragma unroll
            for (int hl = 0; hl < 2; ++hl) {
                uint32_t bf[2][4];
#pragma unroll
                for (int ng = 0; ng < 2; ++ng) {
                    int rowB = dw * 32 + ng * 16 + (lane & 7) + ((lane >> 4) << 3);
                    uint32_t addr = xbase + hl * 16384 + SWZ((uint32_t)(
                        rowB * 128 + kk * 32 + ((lane >> 3) & 1) * 16));
                    ldsm4(bf[ng], addr);
                }
#pragma unroll
                for (int mg = 0; mg < 2; ++mg)
#pragma unroll
                    for (int ng = 0; ng < 2; ++ng)
#pragma unroll
                        for (int sub = 0; sub < 2; ++sub)
                            mma_bf16(acc[mg][ng * 2 + sub], a[mg],
                                     bf[ng][sub * 2], bf[ng][sub * 2 + 1]);
            }
        }
        // write the pre-swizzled mask tile to gmem (raw byte copy)
        {
            const char* msrc = smem + cur * STG + tid * 32;
            uint4 v0 = *reinterpret_cast<const uint4*>(msrc);
            uint4 v1 = *reinterpret_cast<const uint4*>(msrc + 16);
            char* mdst = reinterpret_cast<char*>(g_Mt) +
                         (((size_t)(b * 32 + jt)) * 32 + it) * 8192 + tid * 32;
            *reinterpret_cast<uint4*>(mdst) = v0;
            *reinterpret_cast<uint4*>(mdst + 16) = v1;
        }
        __syncthreads();
    }

    atomicAdd(&sdeg[jj], degloc);
    __syncthreads();
    if (tid < 64) {
        float dinv = 1.0f / fmaxf(sdeg[tid], 1.0f);
        g_deg_inv[b * N_ + j0 + tid] = dinv;
        sdeg[tid] = dinv;
    }
    __syncthreads();

    // epilogue: scale, hi/lo split, bf16 stores
#pragma unroll
    for (int mg = 0; mg < 2; ++mg) {
        int jl0 = jw * 32 + mg * 16 + (lane >> 2);
        float dv0 = sdeg[jl0], dv1 = sdeg[jl0 + 8];
#pragma unroll
        for (int ng = 0; ng < 4; ++ng) {
            int d = dw * 32 + ng * 8 + (lane & 3) * 2;
            size_t ro = ((size_t)(b * N_ + j0 + jl0)) * C + d;
            uint32_t hw, lw;
            split2(acc[mg][ng][0] * dv0, acc[mg][ng][1] * dv0, hw, lw);
            *reinterpret_cast<uint32_t*>(g_agg_hi + ro) = hw;
            *reinterpret_cast<uint32_t*>(g_agg_lo + ro) = lw;
            split2(acc[mg][ng][2] * dv1, acc[mg][ng][3] * dv1, hw, lw);
            *reinterpret_cast<uint32_t*>(g_agg_hi + ro + (size_t)8 * C) = hw;
            *reinterpret_cast<uint32_t*>(g_agg_lo + ro + (size_t)8 * C) = lw;
        }
    }
}

// ---------------------------------------------------------------------------
// agg2: reads pre-swizzled mask tiles (cp.async, no swizzle math) + h^T hi/lo.
// CTA = 64 j x 128 d; grid (32, 2, 8).
// ---------------------------------------------------------------------------
__global__ __launch_bounds__(256, 2)
void agg2_kernel() {
    extern __shared__ __align__(1024) char smem[];
    constexpr int C = HIDC;
    constexpr int NIT = N_ / 64;
    constexpr int STG = 40960;
    const int tid = threadIdx.x, lane = tid & 31, wid = tid >> 5;
    const int b = blockIdx.z, jt = blockIdx.x, j0 = jt * 64, d0 = blockIdx.y * 128;
    const int jw = wid & 1, dw = wid >> 1;
    const uint32_t sb = smem_u32(smem);

    float acc[2][4][4];
#pragma unroll
    for (int mg = 0; mg < 2; ++mg)
#pragma unroll
        for (int ng = 0; ng < 4; ++ng)
#pragma unroll
            for (int q = 0; q < 4; ++q) acc[mg][ng][q] = 0.0f;

    const char* Mtiles = reinterpret_cast<const char*>(g_Mt) +
                         ((size_t)(b * 32 + jt)) * 32 * 8192;

    auto fill = [&](int stage, int it) {
        const int i0 = it * 64;
        // mask tile: raw 8 KB copy (already swizzled)
#pragma unroll
        for (int p = 0; p < 2; ++p) {
            int idx = tid + p * 256;
            cpa16(sb + stage * STG + idx * 16, Mtiles + (size_t)it * 8192 + idx * 16);
        }
#pragma unroll
        for (int p = 0; p < 8; ++p) {
            int idx = tid + p * 256;
            int r = idx >> 3, c = idx & 7;
            int hl = r >> 7, d = d0 + (r & 127);
            const __nv_bfloat16* g = hl ? g_T_lo : g_T_hi;
            cpa16(sb + stage * STG + 8192 + hl * 16384 +
                      SWZ((uint32_t)((r & 127) * 128 + c * 16)),
                  g + ((size_t)(b * C + d)) * N_ + i0 + c * 8);
        }
        asm volatile("cp.async.commit_group;");
    };

    fill(0, 0);

#pragma unroll 1
    for (int it = 0; it < NIT; ++it) {
        const int cur = it & 1;
        if (it + 1 < NIT) {
            fill(cur ^ 1, it + 1);
            asm volatile("cp.async.wait_group 1;");
        } else {
            asm volatile("cp.async.wait_group 0;");
        }
        __syncthreads();

        const uint32_t mbase = sb + cur * STG;
        const uint32_t xbase = mbase + 8192;
#pragma unroll
        for (int kk = 0; kk < 4; ++kk) {
            uint32_t a[2][4];
#pragma unroll
            for (int mg = 0; mg < 2; ++mg) {
                uint32_t addr = mbase + SWZ((uint32_t)(
                    (jw * 32 + mg * 16 + (lane & 15)) * 128 +
                    kk * 32 + (lane >> 4) * 16));
                ldsm4(a[mg], addr);
            }
#pragma unroll
            for (int hl = 0; hl < 2; ++hl) {
                uint32_t bf[2][4];
#pragma unroll
                for (int ng = 0; ng < 2; ++ng) {
                    int rowB = dw * 32 + ng * 16 + (lane & 7) + ((lane >> 4) << 3);
                    uint32_t addr = xbase + hl * 16384 + SWZ((uint32_t)(
                        rowB * 128 + kk * 32 + ((lane >> 3) & 1) * 16));
                    ldsm4(bf[ng], addr);
                }
#pragma unroll
                for (int mg = 0; mg < 2; ++mg)
#pragma unroll
                    for (int ng = 0; ng < 2; ++ng)
#pragma unroll
                        for (int sub = 0; sub < 2; ++sub)
                            mma_bf16(acc[mg][ng * 2 + sub], a[mg],
                                     bf[ng][sub * 2], bf[ng][sub * 2 + 1]);
            }
        }
        __syncthreads();
    }

#pragma unroll
    for (int mg = 0; mg < 2; ++mg) {
        int jl0 = jw * 32 + mg * 16 + (lane >> 2);
        float dv0 = g_deg_inv[b * N_ + j0 + jl0];
        float dv1 = g_deg_inv[b * N_ + j0 + jl0 + 8];
#pragma unroll
        for (int ng = 0; ng < 4; ++ng) {
            int d = d0 + dw * 32 + ng * 8 + (lane & 3) * 2;
            size_t ro = ((size_t)(b * N_ + j0 + jl0)) * C + d;
            uint32_t hw, lw;
            split2(acc[mg][ng][0] * dv0, acc[mg][ng][1] * dv0, hw, lw);
            *reinterpret_cast<uint32_t*>(g_agg_hi + ro) = hw;
            *reinterpret_cast<uint32_t*>(g_agg_lo + ro) = lw;
            split2(acc[mg][ng][2] * dv1, acc[mg][ng][3] * dv1, hw, lw);
            *reinterpret_cast<uint32_t*>(g_agg_hi + ro + (size_t)8 * C) = hw;
            *reinterpret_cast<uint32_t*>(g_agg_lo + ro + (size_t)8 * C) = lw;
        }
    }
}

// ---------------------------------------------------------------------------
// Dense1 HMMA: h = relu(agg1 @ W1_l + x @ W1_r + b1); 3-term bf16 split.
// ---------------------------------------------------------------------------
__global__ __launch_bounds__(256, 2)
void dense1_mma_kernel(const float* __restrict__ b1) {
    extern __shared__ __align__(1024) char smem[];
    const int tid = threadIdx.x, lane = tid & 31, wid = tid >> 5;
    const int mw = wid & 3, nw = wid >> 2;
    const int r0 = blockIdx.x * 128, c0 = blockIdx.y * 128;
    const int b = r0 >> 11, i0 = r0 & (N_ - 1);
    const uint32_t sb = smem_u32(smem);

    float acc[2][8][4];
#pragma unroll
    for (int mg = 0; mg < 2; ++mg)
#pragma unroll
        for (int ng = 0; ng < 8; ++ng)
#pragma unroll
            for (int q = 0; q < 4; ++q) acc[mg][ng][q] = 0.0f;

    const __nv_bfloat16* Asrc[6] = {g_agg_hi, g_agg_lo, g_agg_hi,
                                    g_x_hi,   g_x_lo,   g_x_hi};
    const __nv_bfloat16* Bsrc[6] = {g_W1t_hi, g_W1t_hi, g_W1t_lo,
                                    g_W1t_hi + HIDC * INC, g_W1t_hi + HIDC * INC,
                                    g_W1t_lo + HIDC * INC};

    auto load_stage = [&](int st, int sidx) {
        const int p = sidx >> 1, kb = (sidx & 1) * 64;
        const __nv_bfloat16* As = Asrc[p];
        const __nv_bfloat16* Bs = Bsrc[p];
#pragma unroll
        for (int q = 0; q < 4; ++q) {
            int idx = tid + q * 256;
            int row = idx >> 3, c = idx & 7;
            cpa16(sb + st * 32768 + SWZ((uint32_t)(row * 128 + c * 16)),
                  As + (size_t)(r0 + row) * INC + kb + c * 8);
        }
#pragma unroll
        for (int q = 0; q < 4; ++q) {
            int idx = tid + q * 256;
            int row = idx >> 3, c = idx & 7;
            cpa16(sb + st * 32768 + 16384 + SWZ((uint32_t)(row * 128 + c * 16)),
                  Bs + (size_t)(c0 + row) * INC + kb + c * 8);
        }
        asm volatile("cp.async.commit_group;");
    };

    load_stage(0, 0);

#pragma unroll 1
    for (int s = 0; s < 12; ++s) {
        const int cur = s & 1;
        if (s + 1 < 12) {
            load_stage(cur ^ 1, s + 1);
            asm volatile("cp.async.wait_group 1;");
        } else {
            asm volatile("cp.async.wait_group 0;");
        }
        __syncthreads();

        const uint32_t abase = sb + cur * 32768;
        const uint32_t bbase = abase + 16384;
#pragma unroll
        for (int kk = 0; kk < 4; ++kk) {
            uint32_t a[2][4];
#pragma unroll
            for (int mg = 0; mg < 2; ++mg) {
                uint32_t addr = abase + SWZ((uint32_t)(
                    (mw * 32 + mg * 16 + (lane & 15)) * 128 +
                    kk * 32 + (lane >> 4) * 16));
                ldsm4(a[mg], addr);
            }
            uint32_t bf[4][4];
#pragma unroll
            for (int ng = 0; ng < 4; ++ng) {
                int rowB = nw * 64 + ng * 16 + (lane & 7) + ((lane >> 4) << 3);
                uint32_t addr = bbase + SWZ((uint32_t)(
                    rowB * 128 + kk * 32 + ((lane >> 3) & 1) * 16));
                ldsm4(bf[ng], addr);
            }
#pragma unroll
            for (int mg = 0; mg < 2; ++mg)
#pragma unroll
                for (int ng = 0; ng < 4; ++ng)
#pragma unroll
                    for (int sub = 0; sub < 2; ++sub)
                        mma_bf16(acc[mg][ng * 2 + sub], a[mg],
                                 bf[ng][sub * 2], bf[ng][sub * 2 + 1]);
        }
        __syncthreads();
    }

#pragma unroll
    for (int mg = 0; mg < 2; ++mg) {
#pragma unroll
        for (int ng = 0; ng < 8; ++ng) {
            int dloc = nw * 64 + ng * 8 + (lane & 3) * 2;
            float2 bv = *reinterpret_cast<const float2*>(b1 + c0 + dloc);
            acc[mg][ng][0] = fmaxf(acc[mg][ng][0] + bv.x, 0.0f);
            acc[mg][ng][1] = fmaxf(acc[mg][ng][1] + bv.y, 0.0f);
            acc[mg][ng][2] = fmaxf(acc[mg][ng][2] + bv.x, 0.0f);
            acc[mg][ng][3] = fmaxf(acc[mg][ng][3] + bv.y, 0.0f);
            size_t ro = ((size_t)(r0 + mw * 32 + mg * 16 + (lane >> 2))) * HIDC +
                        c0 + dloc;
            uint32_t hw, lw;
            split2(acc[mg][ng][0], acc[mg][ng][1], hw, lw);
            *reinterpret_cast<uint32_t*>(g_h_hi + ro) = hw;
            *reinterpret_cast<uint32_t*>(g_h_lo + ro) = lw;
            split2(acc[mg][ng][2], acc[mg][ng][3], hw, lw);
            *reinterpret_cast<uint32_t*>(g_h_hi + ro + (size_t)8 * HIDC) = hw;
            *reinterpret_cast<uint32_t*>(g_h_lo + ro + (size_t)8 * HIDC) = lw;
        }
    }

    // transposed hi/lo stores via smem (two 64-col halves)
    float* sT = reinterpret_cast<float*>(smem);
#pragma unroll 1
    for (int half = 0; half < 2; ++half) {
        __syncthreads();
        if (nw == half) {
#pragma unroll
            for (int mg = 0; mg < 2; ++mg)
#pragma unroll
                for (int ng = 0; ng < 8; ++ng)
#pragma unroll
                    for (int q = 0; q < 4; ++q) {
                        int irow = mw * 32 + mg * 16 + (lane >> 2) + (q >> 1) * 8;
                        int dl = ng * 8 + (lane & 3) * 2 + (q & 1);
                        sT[irow * 65 + dl] = acc[mg][ng][q];
                    }
        }
        __syncthreads();
        const int dl = tid >> 2, ic = (tid & 3) * 32;
        uint32_t hb[16], lb[16];
#pragma unroll
        for (int q = 0; q < 16; ++q)
            split2(sT[(ic + q * 2) * 65 + dl], sT[(ic + q * 2 + 1) * 65 + dl],
                   hb[q], lb[q]);
        size_t ob = ((size_t)(b * HIDC + c0 + half * 64 + dl)) * N_ + i0 + ic;
#pragma unroll
        for (int q = 0; q < 4; ++q) {
            reinterpret_cast<uint4*>(g_T_hi + ob)[q] =
                make_uint4(hb[q * 4], hb[q * 4 + 1], hb[q * 4 + 2], hb[q * 4 + 3]);
            reinterpret_cast<uint4*>(g_T_lo + ob)[q] =
                make_uint4(lb[q * 4], lb[q * 4 + 1], lb[q * 4 + 2], lb[q * 4 + 3]);
        }
    }
}

// ---------------------------------------------------------------------------
// Dense2 HMMA + bias + log_softmax.
// ---------------------------------------------------------------------------
__global__ __launch_bounds__(256)
void dense2_mma_kernel(const float* __restrict__ b2, float* __restrict__ out,
                       int write_raw) {
    extern __shared__ __align__(1024) char smem[];
    const int tid = threadIdx.x, lane = tid & 31, wid = tid >> 5;
    const int r0 = blockIdx.x * 128;
    const uint32_t sb = smem_u32(smem);
    constexpr int STG = 20480;

    float acc[4][4];
#pragma unroll
    for (int t = 0; t < 4; ++t)
#pragma unroll
        for (int q = 0; q < 4; ++q) acc[t][q] = 0.0f;

    const __nv_bfloat16* Asrc[6] = {g_agg_hi, g_agg_lo, g_agg_hi,
                                    g_h_hi,   g_h_lo,   g_h_hi};
    const __nv_bfloat16* Bsrc[6] = {g_W2t_hi, g_W2t_hi, g_W2t_lo,
                                    g_W2t_hi + OUTC * HIDC, g_W2t_hi + OUTC * HIDC,
                                    g_W2t_lo + OUTC * HIDC};

    auto load_stage = [&](int st, int sidx) {
        const int p = sidx >> 2, kb = (sidx & 3) * 64;
        const __nv_bfloat16* As = Asrc[p];
        const __nv_bfloat16* Bs = Bsrc[p];
#pragma unroll
        for (int q = 0; q < 4; ++q) {
            int idx = tid + q * 256;
            int row = idx >> 3, c = idx & 7;
            cpa16(sb + st * STG + SWZ((uint32_t)(row * 128 + c * 16)),
                  As + (size_t)(r0 + row) * HIDC + kb + c * 8);
        }
        {
            int row = tid >> 3, c = tid & 7;
            cpa16(sb + st * STG + 16384 + SWZ((uint32_t)(row * 128 + c * 16)),
                  Bs + (size_t)row * HIDC + kb + c * 8);
        }
        asm volatile("cp.async.commit_group;");
    };

    load_stage(0, 0);

#pragma unroll 1
    for (int s = 0; s < 24; ++s) {
        const int cur = s & 1;
        if (s + 1 < 24) {
            load_stage(cur ^ 1, s + 1);
            asm volatile("cp.async.wait_group 1;");
        } else {
            asm volatile("cp.async.wait_group 0;");
        }
        __syncthreads();

        const uint32_t abase = sb + cur * STG;
        const uint32_t bbase = abase + 16384;
#pragma unroll
        for (int kk = 0; kk < 4; ++kk) {
            uint32_t a[4];
            {
                uint32_t addr = abase + SWZ((uint32_t)(
                    (wid * 16 + (lane & 15)) * 128 + kk * 32 + (lane >> 4) * 16));
                ldsm4(a, addr);
            }
            uint32_t bf[2][4];
#pragma unroll
            for (int ng = 0; ng < 2; ++ng) {
                int rowB = ng * 16 + (lane & 7) + ((lane >> 4) << 3);
                uint32_t addr = bbase + SWZ((uint32_t)(
                    rowB * 128 + kk * 32 + ((lane >> 3) & 1) * 16));
                ldsm4(bf[ng], addr);
            }
#pragma unroll
            for (int ng = 0; ng < 2; ++ng)
#pragma unroll
                for (int sub = 0; sub < 2; ++sub)
                    mma_bf16(acc[ng * 2 + sub], a, bf[ng][sub * 2], bf[ng][sub * 2 + 1]);
        }
        __syncthreads();
    }

    float* sOut = reinterpret_cast<float*>(smem);
    __syncthreads();
#pragma unroll
    for (int t = 0; t < 4; ++t) {
        int d = t * 8 + (lane & 3) * 2;
        float2 bv = *reinterpret_cast<const float2*>(b2 + d);
        int row = wid * 16 + (lane >> 2);
        sOut[row * 33 + d] = acc[t][0] + bv.x;
        sOut[row * 33 + d + 1] = acc[t][1] + bv.y;
        sOut[(row + 8) * 33 + d] = acc[t][2] + bv.x;
        sOut[(row + 8) * 33 + d + 1] = acc[t][3] + bv.y;
    }
    __syncthreads();

#pragma unroll 1
    for (int rit = 0; rit < 16; ++rit) {
        int row = rit * 8 + wid;
        float v = sOut[row * 33 + lane];
        float m = v;
#pragma unroll
        for (int o = 16; o > 0; o >>= 1)
            m = fmaxf(m, __shfl_xor_sync(0xffffffffu, m, o));
        float s = expf(v - m);
#pragma unroll
        for (int o = 16; o > 0; o >>= 1)
            s += __shfl_xor_sync(0xffffffffu, s, o);
        float lsm = v - m - logf(s);
        size_t gi = (size_t)(r0 + row) * OUTC + lane;
        out[gi] = lsm;
        if (write_raw) out[(size_t)BN * OUTC + gi] = v;
    }
}

// ---------------------------------------------------------------------------
extern "C" void kernel_launch(void* const* d_in, const int* in_sizes, int n_in,
                              void* d_out, int out_size) {
    const float* x   = (const float*)d_in[0];
    const int*   A   = (const int*)d_in[1];
    const float* W1l = (const float*)d_in[2];
    const float* W1r = (const float*)d_in[3];
    const float* b1  = (const float*)d_in[4];
    const float* W2l = (const float*)d_in[5];
    const float* W2r = (const float*)d_in[6];
    const float* b2  = (const float*)d_in[7];
    float* out = (float*)d_out;
    (void)in_sizes; (void)n_in;

    const int write_raw = (out_size >= 2 * BN * OUTC) ? 1 : 0;

    constexpr int AGG1_SMEM = 2 * 40960 + 256;  // 82176
    constexpr int AGG2_SMEM = 2 * 40960;        // 81920
    constexpr int D1_SMEM = 2 * 32768;          // 65536
    constexpr int D2_SMEM = 2 * 20480;          // 40960
    cudaFuncSetAttribute(agg1_kernel,
                         cudaFuncAttributeMaxDynamicSharedMemorySize, AGG1_SMEM);
    cudaFuncSetAttribute(agg2_kernel,
                         cudaFuncAttributeMaxDynamicSharedMemorySize, AGG2_SMEM);
    cudaFuncSetAttribute(dense1_mma_kernel,
                         cudaFuncAttributeMaxDynamicSharedMemorySize, D1_SMEM);
    cudaFuncSetAttribute(dense2_mma_kernel,
                         cudaFuncAttributeMaxDynamicSharedMemorySize, D2_SMEM);

    wprep_kernel<<<320, 256>>>(W1l, W1r, W2l, W2r);
    convertT_x_kernel<<<dim3(N_ / 64, INC / 64, B_), 256>>>(x);
    agg1_kernel<<<dim3(N_ / 64, 1, B_), 256, AGG1_SMEM>>>(A);
    dense1_mma_kernel<<<dim3(BN / 128, HIDC / 128), 256, D1_SMEM>>>(b1);
    agg2_kernel<<<dim3(N_ / 64, HIDC / 128, B_), 256, AGG2_SMEM>>>();
    dense2_mma_kernel<<<BN / 128, 256, D2_SMEM>>>(b2, out, write_raw);
}

// round 8
// speedup vs baseline: 1.4191x; 1.0244x over previous
#include <cuda_runtime.h>
#include <cuda_bf16.h>
#include <cstdint>
#include <cstddef>

// Problem constants
constexpr int B_ = 8;
constexpr int N_ = 2048;
constexpr int INC = 128;
constexpr int HIDC = 256;
constexpr int OUTC = 32;
constexpr int BN = B_ * N_;

// Scratch (device globals: no allocation allowed)
__device__ __align__(16) float g_deg_inv[BN];
__device__ __align__(16) __nv_bfloat16 g_agg_hi[(size_t)BN * HIDC];  // row-major
__device__ __align__(16) __nv_bfloat16 g_agg_lo[(size_t)BN * HIDC];
__device__ __align__(16) __nv_bfloat16 g_h_hi[(size_t)BN * HIDC];    // row-major
__device__ __align__(16) __nv_bfloat16 g_h_lo[(size_t)BN * HIDC];
__device__ __align__(16) __nv_bfloat16 g_x_hi[(size_t)BN * INC];     // row-major
__device__ __align__(16) __nv_bfloat16 g_x_lo[(size_t)BN * INC];
__device__ __align__(16) __nv_bfloat16 g_T_hi[(size_t)B_ * HIDC * N_];  // [b][d][i]
__device__ __align__(16) __nv_bfloat16 g_T_lo[(size_t)B_ * HIDC * N_];
// Mask tiles, PRE-SWIZZLED: [b][jt(32)][it(32)][8192 bytes] (64j x 64i bf16)
__device__ __align__(16) __nv_bfloat16 g_Mt[(size_t)B_ * N_ * N_];
__device__ __align__(16) __nv_bfloat16 g_W1t_hi[2 * HIDC * INC];   // [mtx][n][k]
__device__ __align__(16) __nv_bfloat16 g_W1t_lo[2 * HIDC * INC];
__device__ __align__(16) __nv_bfloat16 g_W2t_hi[2 * OUTC * HIDC];
__device__ __align__(16) __nv_bfloat16 g_W2t_lo[2 * OUTC * HIDC];

#define SWZ(off) ((off) ^ (((off) >> 3) & 0x70))

__device__ __forceinline__ uint32_t smem_u32(const void* p) {
    uint32_t a;
    asm("{ .reg .u64 t; cvta.to.shared.u64 t, %1; cvt.u32.u64 %0, t; }"
        : "=r"(a) : "l"(p));
    return a;
}
__device__ __forceinline__ void cpa16(uint32_t dst, const void* src) {
    asm volatile("cp.async.cg.shared.global [%0], [%1], 16;" :: "r"(dst), "l"(src));
}
__device__ __forceinline__ void ldsm4(uint32_t* r, uint32_t addr) {
    asm volatile("ldmatrix.sync.aligned.m8n8.x4.shared.b16 {%0,%1,%2,%3}, [%4];"
                 : "=r"(r[0]), "=r"(r[1]), "=r"(r[2]), "=r"(r[3]) : "r"(addr));
}
__device__ __forceinline__ void mma_bf16(float* c, const uint32_t* a,
                                         uint32_t b0, uint32_t b1) {
    asm volatile(
        "mma.sync.aligned.m16n8k16.row.col.f32.bf16.bf16.f32 "
        "{%0,%1,%2,%3}, {%4,%5,%6,%7}, {%8,%9}, {%0,%1,%2,%3};"
        : "+f"(c[0]), "+f"(c[1]), "+f"(c[2]), "+f"(c[3])
        : "r"(a[0]), "r"(a[1]), "r"(a[2]), "r"(a[3]), "r"(b0), "r"(b1));
}
__device__ __forceinline__ void split2(float v0, float v1, uint32_t& hw, uint32_t& lw) {
    __nv_bfloat16 h0 = __float2bfloat16(v0);
    __nv_bfloat16 h1 = __float2bfloat16(v1);
    __nv_bfloat16 l0 = __float2bfloat16(v0 - __bfloat162float(h0));
    __nv_bfloat16 l1 = __float2bfloat16(v1 - __bfloat162float(h1));
    __nv_bfloat162 hp; hp.x = h0; hp.y = h1;
    __nv_bfloat162 lp; lp.x = l0; lp.y = l1;
    hw = *reinterpret_cast<uint32_t*>(&hp);
    lw = *reinterpret_cast<uint32_t*>(&lp);
}

// ---------------------------------------------------------------------------
// Weight prep: transpose + hi/lo split.
// ---------------------------------------------------------------------------
__global__ __launch_bounds__(256)
void wprep_kernel(const float* __restrict__ W1l, const float* __restrict__ W1r,
                  const float* __restrict__ W2l, const float* __restrict__ W2r) {
    int idx = blockIdx.x * 256 + threadIdx.x;
    float v;
    __nv_bfloat16 *hi, *lo;
    int off;
    if (idx < 2 * HIDC * INC) {
        int mtx = idx >> 15, rem = idx & 32767;
        int n = rem >> 7, k = rem & 127;
        v = (mtx ? W1r : W1l)[k * HIDC + n];
        hi = g_W1t_hi; lo = g_W1t_lo; off = idx;
    } else {
        int j = idx - 2 * HIDC * INC;
        if (j >= 2 * OUTC * HIDC) return;
        int mtx = j >> 13, rem = j & 8191;
        int n = rem >> 8, k = rem & 255;
        v = (mtx ? W2r : W2l)[k * OUTC + n];
        hi = g_W2t_hi; lo = g_W2t_lo; off = j;
    }
    __nv_bfloat16 h = __float2bfloat16(v);
    hi[off] = h;
    lo[off] = __float2bfloat16(v - __bfloat162float(h));
}

// ---------------------------------------------------------------------------
// x prep: row-major hi/lo split (for dense1) + transposed hi/lo (for agg1).
// ---------------------------------------------------------------------------
__global__ __launch_bounds__(256)
void convertT_x_kernel(const float* __restrict__ src) {
    constexpr int C = INC;
    __shared__ float sT[64][65];
    const int t = threadIdx.x;
    const int b = blockIdx.z, i0 = blockIdx.x * 64, d0 = blockIdx.y * 64;

#pragma unroll
    for (int p = 0; p < 4; ++p) {
        int e = t + p * 256;
        int row = e >> 4, c4 = e & 15;
        size_t goff = ((size_t)(b * N_ + i0 + row)) * C + d0 + c4 * 4;
        float4 v = *reinterpret_cast<const float4*>(src + goff);
        sT[row][c4 * 4 + 0] = v.x; sT[row][c4 * 4 + 1] = v.y;
        sT[row][c4 * 4 + 2] = v.z; sT[row][c4 * 4 + 3] = v.w;
        uint32_t h0, l0, h1, l1;
        split2(v.x, v.y, h0, l0);
        split2(v.z, v.w, h1, l1);
        *reinterpret_cast<uint2*>(g_x_hi + goff) = make_uint2(h0, h1);
        *reinterpret_cast<uint2*>(g_x_lo + goff) = make_uint2(l0, l1);
    }
    __syncthreads();

    const int d = t >> 2, ic = (t & 3) * 16;
    uint32_t hb[8], lb[8];
#pragma unroll
    for (int q = 0; q < 8; ++q)
        split2(sT[ic + q * 2][d], sT[ic + q * 2 + 1][d], hb[q], lb[q]);
    size_t obase = ((size_t)(b * C + d0 + d)) * N_ + i0 + ic;
    reinterpret_cast<uint4*>(g_T_hi + obase)[0] = make_uint4(hb[0], hb[1], hb[2], hb[3]);
    reinterpret_cast<uint4*>(g_T_hi + obase)[1] = make_uint4(hb[4], hb[5], hb[6], hb[7]);
    reinterpret_cast<uint4*>(g_T_lo + obase)[0] = make_uint4(lb[0], lb[1], lb[2], lb[3]);
    reinterpret_cast<uint4*>(g_T_lo + obase)[1] = make_uint4(lb[4], lb[5], lb[6], lb[7]);
}

// ---------------------------------------------------------------------------
// agg1 (fused): reads A, converts mask in-pipeline (degree fused), HMMAs with
// x^T hi/lo, writes agg1 bf16 hi/lo + pre-swizzled mask tiles + deg_inv.
// ---------------------------------------------------------------------------
__global__ __launch_bounds__(256, 2)
void agg1_kernel(const int* __restrict__ A) {
    extern __shared__ __align__(1024) char smem[];
    constexpr int C = INC;
    constexpr int NIT = N_ / 64;
    constexpr int STG = 40960;
    const int tid = threadIdx.x, lane = tid & 31, wid = tid >> 5;
    const int b = blockIdx.z, jt = blockIdx.x, j0 = jt * 64;
    const int jw = wid & 1, dw = wid >> 1;
    const uint32_t sb = smem_u32(smem);
    float* sdeg = reinterpret_cast<float*>(smem + 2 * STG);

    if (tid < 64) sdeg[tid] = 0.0f;

    float acc[2][4][4];
#pragma unroll
    for (int mg = 0; mg < 2; ++mg)
#pragma unroll
        for (int ng = 0; ng < 4; ++ng)
#pragma unroll
            for (int q = 0; q < 4; ++q) acc[mg][ng][q] = 0.0f;

    const int jj = tid & 63, iq = tid >> 6;
    const int* Ap = A + (size_t)b * N_ * N_ + j0 + jj;
    float degloc = 0.0f;

    auto fill = [&](int stage, int it) {
        const int i0 = it * 64;
        {
            char* mb = smem + stage * STG;
#pragma unroll
            for (int r = 0; r < 8; ++r) {
                int il = iq * 16 + r * 2;
                int a0 = Ap[(size_t)(i0 + il) * N_];
                int a1 = Ap[(size_t)(i0 + il + 1) * N_];
                float m0 = a0 ? 1.0f : 0.0f;
                float m1 = a1 ? 1.0f : 0.0f;
                degloc += m0 + m1;
                __nv_bfloat162 mv = __floats2bfloat162_rn(m0, m1);
                *reinterpret_cast<__nv_bfloat162*>(
                    mb + SWZ((uint32_t)(jj * 128 + il * 2))) = mv;
            }
        }
#pragma unroll
        for (int p = 0; p < 8; ++p) {
            int idx = tid + p * 256;
            int r = idx >> 3, c = idx & 7;
            int hl = r >> 7, d = r & 127;
            const __nv_bfloat16* g = hl ? g_T_lo : g_T_hi;
            cpa16(sb + stage * STG + 8192 + hl * 16384 +
                      SWZ((uint32_t)(d * 128 + c * 16)),
                  g + ((size_t)(b * C + d)) * N_ + i0 + c * 8);
        }
        asm volatile("cp.async.commit_group;");
    };

    fill(0, 0);

#pragma unroll 1
    for (int it = 0; it < NIT; ++it) {
        const int cur = it & 1;
        if (it + 1 < NIT) {
            fill(cur ^ 1, it + 1);
            asm volatile("cp.async.wait_group 1;");
        } else {
            asm volatile("cp.async.wait_group 0;");
        }
        __syncthreads();

        const uint32_t mbase = sb + cur * STG;
        const uint32_t xbase = mbase + 8192;
#pragma unroll
        for (int kk = 0; kk < 4; ++kk) {
            uint32_t a[2][4];
#pragma unroll
            for (int mg = 0; mg < 2; ++mg) {
                uint32_t addr = mbase + SWZ((uint32_t)(
                    (jw * 32 + mg * 16 + (lane & 15)) * 128 +
                    kk * 32 + (lane >> 4) * 16));
                ldsm4(a[mg], addr);
            }
#pragma unroll
            for (int hl = 0; hl < 2; ++hl) {
                uint32_t bf[2][4];
#pragma unroll
                for (int ng = 0; ng < 2; ++ng) {
                    int rowB = dw * 32 + ng * 16 + (lane & 7) + ((lane >> 4) << 3);
                    uint32_t addr = xbase + hl * 16384 + SWZ((uint32_t)(
                        rowB * 128 + kk * 32 + ((lane >> 3) & 1) * 16));
                    ldsm4(bf[ng], addr);
                }
#pragma unroll
                for (int mg = 0; mg < 2; ++mg)
#pragma unroll
                    for (int ng = 0; ng < 2; ++ng)
#pragma unroll
                        for (int sub = 0; sub < 2; ++sub)
                            mma_bf16(acc[mg][ng * 2 + sub], a[mg],
                                     bf[ng][sub * 2], bf[ng][sub * 2 + 1]);
            }
        }
        {
            const char* msrc = smem + cur * STG + tid * 32;
            uint4 v0 = *reinterpret_cast<const uint4*>(msrc);
            uint4 v1 = *reinterpret_cast<const uint4*>(msrc + 16);
            char* mdst = reinterpret_cast<char*>(g_Mt) +
                         (((size_t)(b * 32 + jt)) * 32 + it) * 8192 + tid * 32;
            *reinterpret_cast<uint4*>(mdst) = v0;
            *reinterpret_cast<uint4*>(mdst + 16) = v1;
        }
        __syncthreads();
    }

    atomicAdd(&sdeg[jj], degloc);
    __syncthreads();
    if (tid < 64) {
        float dinv = 1.0f / fmaxf(sdeg[tid], 1.0f);
        g_deg_inv[b * N_ + j0 + tid] = dinv;
        sdeg[tid] = dinv;
    }
    __syncthreads();

#pragma unroll
    for (int mg = 0; mg < 2; ++mg) {
        int jl0 = jw * 32 + mg * 16 + (lane >> 2);
        float dv0 = sdeg[jl0], dv1 = sdeg[jl0 + 8];
#pragma unroll
        for (int ng = 0; ng < 4; ++ng) {
            int d = dw * 32 + ng * 8 + (lane & 3) * 2;
            size_t ro = ((size_t)(b * N_ + j0 + jl0)) * C + d;
            uint32_t hw, lw;
            split2(acc[mg][ng][0] * dv0, acc[mg][ng][1] * dv0, hw, lw);
            *reinterpret_cast<uint32_t*>(g_agg_hi + ro) = hw;
            *reinterpret_cast<uint32_t*>(g_agg_lo + ro) = lw;
            split2(acc[mg][ng][2] * dv1, acc[mg][ng][3] * dv1, hw, lw);
            *reinterpret_cast<uint32_t*>(g_agg_hi + ro + (size_t)8 * C) = hw;
            *reinterpret_cast<uint32_t*>(g_agg_lo + ro + (size_t)8 * C) = lw;
        }
    }
}

// ---------------------------------------------------------------------------
// agg2: reads pre-swizzled mask tiles + h^T hi/lo.
// ---------------------------------------------------------------------------
__global__ __launch_bounds__(256, 2)
void agg2_kernel() {
    extern __shared__ __align__(1024) char smem[];
    constexpr int C = HIDC;
    constexpr int NIT = N_ / 64;
    constexpr int STG = 40960;
    const int tid = threadIdx.x, lane = tid & 31, wid = tid >> 5;
    const int b = blockIdx.z, jt = blockIdx.x, j0 = jt * 64, d0 = blockIdx.y * 128;
    const int jw = wid & 1, dw = wid >> 1;
    const uint32_t sb = smem_u32(smem);

    float acc[2][4][4];
#pragma unroll
    for (int mg = 0; mg < 2; ++mg)
#pragma unroll
        for (int ng = 0; ng < 4; ++ng)
#pragma unroll
            for (int q = 0; q < 4; ++q) acc[mg][ng][q] = 0.0f;

    const char* Mtiles = reinterpret_cast<const char*>(g_Mt) +
                         ((size_t)(b * 32 + jt)) * 32 * 8192;

    auto fill = [&](int stage, int it) {
        const int i0 = it * 64;
#pragma unroll
        for (int p = 0; p < 2; ++p) {
            int idx = tid + p * 256;
            cpa16(sb + stage * STG + idx * 16, Mtiles + (size_t)it * 8192 + idx * 16);
        }
#pragma unroll
        for (int p = 0; p < 8; ++p) {
            int idx = tid + p * 256;
            int r = idx >> 3, c = idx & 7;
            int hl = r >> 7, d = d0 + (r & 127);
            const __nv_bfloat16* g = hl ? g_T_lo : g_T_hi;
            cpa16(sb + stage * STG + 8192 + hl * 16384 +
                      SWZ((uint32_t)((r & 127) * 128 + c * 16)),
                  g + ((size_t)(b * C + d)) * N_ + i0 + c * 8);
        }
        asm volatile("cp.async.commit_group;");
    };

    fill(0, 0);

#pragma unroll 1
    for (int it = 0; it < NIT; ++it) {
        const int cur = it & 1;
        if (it + 1 < NIT) {
            fill(cur ^ 1, it + 1);
            asm volatile("cp.async.wait_group 1;");
        } else {
            asm volatile("cp.async.wait_group 0;");
        }
        __syncthreads();

        const uint32_t mbase = sb + cur * STG;
        const uint32_t xbase = mbase + 8192;
#pragma unroll
        for (int kk = 0; kk < 4; ++kk) {
            uint32_t a[2][4];
#pragma unroll
            for (int mg = 0; mg < 2; ++mg) {
                uint32_t addr = mbase + SWZ((uint32_t)(
                    (jw * 32 + mg * 16 + (lane & 15)) * 128 +
                    kk * 32 + (lane >> 4) * 16));
                ldsm4(a[mg], addr);
            }
#pragma unroll
            for (int hl = 0; hl < 2; ++hl) {
                uint32_t bf[2][4];
#pragma unroll
                for (int ng = 0; ng < 2; ++ng) {
                    int rowB = dw * 32 + ng * 16 + (lane & 7) + ((lane >> 4) << 3);
                    uint32_t addr = xbase + hl * 16384 + SWZ((uint32_t)(
                        rowB * 128 + kk * 32 + ((lane >> 3) & 1) * 16));
                    ldsm4(bf[ng], addr);
                }
#pragma unroll
                for (int mg = 0; mg < 2; ++mg)
#pragma unroll
                    for (int ng = 0; ng < 2; ++ng)
#pragma unroll
                        for (int sub = 0; sub < 2; ++sub)
                            mma_bf16(acc[mg][ng * 2 + sub], a[mg],
                                     bf[ng][sub * 2], bf[ng][sub * 2 + 1]);
            }
        }
        __syncthreads();
    }

#pragma unroll
    for (int mg = 0; mg < 2; ++mg) {
        int jl0 = jw * 32 + mg * 16 + (lane >> 2);
        float dv0 = g_deg_inv[b * N_ + j0 + jl0];
        float dv1 = g_deg_inv[b * N_ + j0 + jl0 + 8];
#pragma unroll
        for (int ng = 0; ng < 4; ++ng) {
            int d = d0 + dw * 32 + ng * 8 + (lane & 3) * 2;
            size_t ro = ((size_t)(b * N_ + j0 + jl0)) * C + d;
            uint32_t hw, lw;
            split2(acc[mg][ng][0] * dv0, acc[mg][ng][1] * dv0, hw, lw);
            *reinterpret_cast<uint32_t*>(g_agg_hi + ro) = hw;
            *reinterpret_cast<uint32_t*>(g_agg_lo + ro) = lw;
            split2(acc[mg][ng][2] * dv1, acc[mg][ng][3] * dv1, hw, lw);
            *reinterpret_cast<uint32_t*>(g_agg_hi + ro + (size_t)8 * C) = hw;
            *reinterpret_cast<uint32_t*>(g_agg_lo + ro + (size_t)8 * C) = lw;
        }
    }
}

// ---------------------------------------------------------------------------
// Dense1 v2 (fixed): per-64K-chunk load {A_hi, A_lo, W_hi, W_lo}; 3 MMA
// combos per fragment set; kk covers all 4 k16 steps. CTA 64 x 128; 4 stages.
// ---------------------------------------------------------------------------
__global__ __launch_bounds__(256, 2)
void dense1_mma_kernel(const float* __restrict__ b1) {
    extern __shared__ __align__(1024) char smem[];
    constexpr int STG = 49152;  // Ah 8K | Al 8K | Bh 16K | Bl 16K
    const int tid = threadIdx.x, lane = tid & 31, wid = tid >> 5;
    const int mw = wid & 1, nw = wid >> 1;
    const int r0 = blockIdx.x * 64, c0 = blockIdx.y * 128;
    const int b = r0 >> 11, i0 = r0 & (N_ - 1);
    const uint32_t sb = smem_u32(smem);

    float acc[2][4][4];
#pragma unroll
    for (int mg = 0; mg < 2; ++mg)
#pragma unroll
        for (int nq = 0; nq < 4; ++nq)
#pragma unroll
            for (int q = 0; q < 4; ++q) acc[mg][nq][q] = 0.0f;

    auto load_stage = [&](int st, int sidx) {
        const int part = sidx >> 1, kb = (sidx & 1) * 64;
        const __nv_bfloat16* Ah = part ? g_x_hi : g_agg_hi;
        const __nv_bfloat16* Al = part ? g_x_lo : g_agg_lo;
        const __nv_bfloat16* Bh = g_W1t_hi + part * HIDC * INC;
        const __nv_bfloat16* Bl = g_W1t_lo + part * HIDC * INC;
#pragma unroll
        for (int p = 0; p < 4; ++p) {
            int idx = tid + p * 256;
            int r = idx >> 3, c = idx & 7;
            int hl = r >> 6, row = r & 63;
            cpa16(sb + st * STG + hl * 8192 + SWZ((uint32_t)(row * 128 + c * 16)),
                  (hl ? Al : Ah) + (size_t)(r0 + row) * INC + kb + c * 8);
        }
#pragma unroll
        for (int p = 0; p < 8; ++p) {
            int idx = tid + p * 256;
            int r = idx >> 3, c = idx & 7;
            int hl = r >> 7, row = r & 127;
            cpa16(sb + st * STG + 16384 + hl * 16384 +
                      SWZ((uint32_t)(row * 128 + c * 16)),
                  (hl ? Bl : Bh) + (size_t)(c0 + row) * INC + kb + c * 8);
        }
        asm volatile("cp.async.commit_group;");
    };

    load_stage(0, 0);

#pragma unroll 1
    for (int s = 0; s < 4; ++s) {
        const int cur = s & 1;
        if (s + 1 < 4) {
            load_stage(cur ^ 1, s + 1);
            asm volatile("cp.async.wait_group 1;");
        } else {
            asm volatile("cp.async.wait_group 0;");
        }
        __syncthreads();

        const uint32_t ahb = sb + cur * STG;
        const uint32_t alb = ahb + 8192;
        const uint32_t bhb = ahb + 16384;
        const uint32_t blb = ahb + 32768;
#pragma unroll
        for (int kk = 0; kk < 4; ++kk) {
            uint32_t ah[2][4], al[2][4];
#pragma unroll
            for (int mg = 0; mg < 2; ++mg) {
                uint32_t off = SWZ((uint32_t)(
                    (mw * 32 + mg * 16 + (lane & 15)) * 128 +
                    kk * 32 + (lane >> 4) * 16));
                ldsm4(ah[mg], ahb + off);
                ldsm4(al[mg], alb + off);
            }
            uint32_t bh[2][4], bl[2][4];
#pragma unroll
            for (int ng = 0; ng < 2; ++ng) {
                int rowB = nw * 32 + ng * 16 + (lane & 7) + ((lane >> 4) << 3);
                uint32_t off = SWZ((uint32_t)(
                    rowB * 128 + kk * 32 + ((lane >> 3) & 1) * 16));
                ldsm4(bh[ng], bhb + off);
                ldsm4(bl[ng], blb + off);
            }
#pragma unroll
            for (int mg = 0; mg < 2; ++mg)
#pragma unroll
                for (int ng = 0; ng < 2; ++ng)
#pragma unroll
                    for (int sub = 0; sub < 2; ++sub) {
                        float* c = acc[mg][ng * 2 + sub];
                        mma_bf16(c, ah[mg], bh[ng][sub * 2], bh[ng][sub * 2 + 1]);
                        mma_bf16(c, al[mg], bh[ng][sub * 2], bh[ng][sub * 2 + 1]);
                        mma_bf16(c, ah[mg], bl[ng][sub * 2], bl[ng][sub * 2 + 1]);
                    }
        }
        __syncthreads();
    }

    // bias + relu, row-major hi/lo stores
#pragma unroll
    for (int mg = 0; mg < 2; ++mg) {
#pragma unroll
        for (int nq = 0; nq < 4; ++nq) {
            int dloc = nw * 32 + nq * 8 + (lane & 3) * 2;
            float2 bv = *reinterpret_cast<const float2*>(b1 + c0 + dloc);
            acc[mg][nq][0] = fmaxf(acc[mg][nq][0] + bv.x, 0.0f);
            acc[mg][nq][1] = fmaxf(acc[mg][nq][1] + bv.y, 0.0f);
            acc[mg][nq][2] = fmaxf(acc[mg][nq][2] + bv.x, 0.0f);
            acc[mg][nq][3] = fmaxf(acc[mg][nq][3] + bv.y, 0.0f);
            size_t ro = ((size_t)(r0 + mw * 32 + mg * 16 + (lane >> 2))) * HIDC +
                        c0 + dloc;
            uint32_t hw, lw;
            split2(acc[mg][nq][0], acc[mg][nq][1], hw, lw);
            *reinterpret_cast<uint32_t*>(g_h_hi + ro) = hw;
            *reinterpret_cast<uint32_t*>(g_h_lo + ro) = lw;
            split2(acc[mg][nq][2], acc[mg][nq][3], hw, lw);
            *reinterpret_cast<uint32_t*>(g_h_hi + ro + (size_t)8 * HIDC) = hw;
            *reinterpret_cast<uint32_t*>(g_h_lo + ro + (size_t)8 * HIDC) = lw;
        }
    }

    // single-pass transpose + hi/lo split (all warps)
    float* sT = reinterpret_cast<float*>(smem);  // [64][129]
#pragma unroll
    for (int mg = 0; mg < 2; ++mg)
#pragma unroll
        for (int nq = 0; nq < 4; ++nq)
#pragma unroll
            for (int q = 0; q < 4; ++q) {
                int irow = mw * 32 + mg * 16 + (lane >> 2) + (q >> 1) * 8;
                int dl = nw * 32 + nq * 8 + (lane & 3) * 2 + (q & 1);
                sT[irow * 129 + dl] = acc[mg][nq][q];
            }
    __syncthreads();

    const int dl = tid & 127, iq = (tid >> 7) * 32;
    uint32_t hb[16], lb[16];
#pragma unroll
    for (int q = 0; q < 16; ++q)
        split2(sT[(iq + q * 2) * 129 + dl], sT[(iq + q * 2 + 1) * 129 + dl],
               hb[q], lb[q]);
    size_t ob = ((size_t)(b * HIDC + c0 + dl)) * N_ + i0 + iq;
#pragma unroll
    for (int q = 0; q < 4; ++q) {
        reinterpret_cast<uint4*>(g_T_hi + ob)[q] =
            make_uint4(hb[q * 4], hb[q * 4 + 1], hb[q * 4 + 2], hb[q * 4 + 3]);
        reinterpret_cast<uint4*>(g_T_lo + ob)[q] =
            make_uint4(lb[q * 4], lb[q * 4 + 1], lb[q * 4 + 2], lb[q * 4 + 3]);
    }
}

// ---------------------------------------------------------------------------
// Dense2 v2 (fixed): per-chunk {A_hi, A_lo, W_hi, W_lo} with 3 combos;
// kk covers 4 k16 steps; 8 stages. Epilogue: bias + log_softmax.
// ---------------------------------------------------------------------------
__global__ __launch_bounds__(256, 2)
void dense2_mma_kernel(const float* __restrict__ b2, float* __restrict__ out,
                       int write_raw) {
    extern __shared__ __align__(1024) char smem[];
    constexpr int STG = 40960;  // Ah 16K | Al 16K | Bh 4K | Bl 4K
    const int tid = threadIdx.x, lane = tid & 31, wid = tid >> 5;
    const int r0 = blockIdx.x * 128;
    const uint32_t sb = smem_u32(smem);

    float acc[4][4];
#pragma unroll
    for (int t = 0; t < 4; ++t)
#pragma unroll
        for (int q = 0; q < 4; ++q) acc[t][q] = 0.0f;

    auto load_stage = [&](int st, int sidx) {
        const int part = sidx >> 2, kb = (sidx & 3) * 64;
        const __nv_bfloat16* Ah = part ? g_h_hi : g_agg_hi;
        const __nv_bfloat16* Al = part ? g_h_lo : g_agg_lo;
        const __nv_bfloat16* Bh = g_W2t_hi + part * OUTC * HIDC;
        const __nv_bfloat16* Bl = g_W2t_lo + part * OUTC * HIDC;
#pragma unroll
        for (int p = 0; p < 8; ++p) {
            int idx = tid + p * 256;
            int r = idx >> 3, c = idx & 7;
            int hl = r >> 7, row = r & 127;
            cpa16(sb + st * STG + hl * 16384 + SWZ((uint32_t)(row * 128 + c * 16)),
                  (hl ? Al : Ah) + (size_t)(r0 + row) * HIDC + kb + c * 8);
        }
#pragma unroll
        for (int p = 0; p < 2; ++p) {
            int idx = tid + p * 256;
            int r = idx >> 3, c = idx & 7;
            int hl = r >> 5, row = r & 31;
            cpa16(sb + st * STG + 32768 + hl * 4096 +
                      SWZ((uint32_t)(row * 128 + c * 16)),
                  (hl ? Bl : Bh) + (size_t)row * HIDC + kb + c * 8);
        }
        asm volatile("cp.async.commit_group;");
    };

    load_stage(0, 0);

#pragma unroll 1
    for (int s = 0; s < 8; ++s) {
        const int cur = s & 1;
        if (s + 1 < 8) {
            load_stage(cur ^ 1, s + 1);
            asm volatile("cp.async.wait_group 1;");
        } else {
            asm volatile("cp.async.wait_group 0;");
        }
        __syncthreads();

        const uint32_t ahb = sb + cur * STG;
        const uint32_t alb = ahb + 16384;
        const uint32_t bhb = ahb + 32768;
        const uint32_t blb = ahb + 36864;
#pragma unroll
        for (int kk = 0; kk < 4; ++kk) {
            uint32_t ah[4], al[4];
            {
                uint32_t off = SWZ((uint32_t)(
                    (wid * 16 + (lane & 15)) * 128 + kk * 32 + (lane >> 4) * 16));
                ldsm4(ah, ahb + off);
                ldsm4(al, alb + off);
            }
            uint32_t bh[2][4], bl[2][4];
#pragma unroll
            for (int ng = 0; ng < 2; ++ng) {
                int rowB = ng * 16 + (lane & 7) + ((lane >> 4) << 3);
                uint32_t off = SWZ((uint32_t)(
                    rowB * 128 + kk * 32 + ((lane >> 3) & 1) * 16));
                ldsm4(bh[ng], bhb + off);
                ldsm4(bl[ng], blb + off);
            }
#pragma unroll
            for (int ng = 0; ng < 2; ++ng)
#pragma unroll
                for (int sub = 0; sub < 2; ++sub) {
                    float* c = acc[ng * 2 + sub];
                    mma_bf16(c, ah, bh[ng][sub * 2], bh[ng][sub * 2 + 1]);
                    mma_bf16(c, al, bh[ng][sub * 2], bh[ng][sub * 2 + 1]);
                    mma_bf16(c, ah, bl[ng][sub * 2], bl[ng][sub * 2 + 1]);
                }
        }
        __syncthreads();
    }

    float* sOut = reinterpret_cast<float*>(smem);
    __syncthreads();
#pragma unroll
    for (int t = 0; t < 4; ++t) {
        int d = t * 8 + (lane & 3) * 2;
        float2 bv = *reinterpret_cast<const float2*>(b2 + d);
        int row = wid * 16 + (lane >> 2);
        sOut[row * 33 + d] = acc[t][0] + bv.x;
        sOut[row * 33 + d + 1] = acc[t][1] + bv.y;
        sOut[(row + 8) * 33 + d] = acc[t][2] + bv.x;
        sOut[(row + 8) * 33 + d + 1] = acc[t][3] + bv.y;
    }
    __syncthreads();

#pragma unroll 1
    for (int rit = 0; rit < 16; ++rit) {
        int row = rit * 8 + wid;
        float v = sOut[row * 33 + lane];
        float m = v;
#pragma unroll
        for (int o = 16; o > 0; o >>= 1)
            m = fmaxf(m, __shfl_xor_sync(0xffffffffu, m, o));
        float s = expf(v - m);
#pragma unroll
        for (int o = 16; o > 0; o >>= 1)
            s += __shfl_xor_sync(0xffffffffu, s, o);
        float lsm = v - m - logf(s);
        size_t gi = (size_t)(r0 + row) * OUTC + lane;
        out[gi] = lsm;
        if (write_raw) out[(size_t)BN * OUTC + gi] = v;
    }
}

// ---------------------------------------------------------------------------
extern "C" void kernel_launch(void* const* d_in, const int* in_sizes, int n_in,
                              void* d_out, int out_size) {
    const float* x   = (const float*)d_in[0];
    const int*   A   = (const int*)d_in[1];
    const float* W1l = (const float*)d_in[2];
    const float* W1r = (const float*)d_in[3];
    const float* b1  = (const float*)d_in[4];
    const float* W2l = (const float*)d_in[5];
    const float* W2r = (const float*)d_in[6];
    const float* b2  = (const float*)d_in[7];
    float* out = (float*)d_out;
    (void)in_sizes; (void)n_in;

    const int write_raw = (out_size >= 2 * BN * OUTC) ? 1 : 0;

    constexpr int AGG1_SMEM = 2 * 40960 + 256;  // 82176
    constexpr int AGG2_SMEM = 2 * 40960;        // 81920
    constexpr int D1_SMEM = 2 * 49152;          // 98304
    constexpr int D2_SMEM = 2 * 40960;          // 81920
    cudaFuncSetAttribute(agg1_kernel,
                         cudaFuncAttributeMaxDynamicSharedMemorySize, AGG1_SMEM);
    cudaFuncSetAttribute(agg2_kernel,
                         cudaFuncAttributeMaxDynamicSharedMemorySize, AGG2_SMEM);
    cudaFuncSetAttribute(dense1_mma_kernel,
                         cudaFuncAttributeMaxDynamicSharedMemorySize, D1_SMEM);
    cudaFuncSetAttribute(dense2_mma_kernel,
                         cudaFuncAttributeMaxDynamicSharedMemorySize, D2_SMEM);

    wprep_kernel<<<320, 256>>>(W1l, W1r, W2l, W2r);
    convertT_x_kernel<<<dim3(N_ / 64, INC / 64, B_), 256>>>(x);
    agg1_kernel<<<dim3(N_ / 64, 1, B_), 256, AGG1_SMEM>>>(A);
    dense1_mma_kernel<<<dim3(BN / 64, HIDC / 128), 256, D1_SMEM>>>(b1);
    agg2_kernel<<<dim3(N_ / 64, HIDC / 128, B_), 256, AGG2_SMEM>>>();
    dense2_mma_kernel<<<BN / 128, 256, D2_SMEM>>>(b2, out, write_raw);
}

// round 9
// speedup vs baseline: 1.8029x; 1.2704x over previous
#include <cuda_runtime.h>
#include <cuda_bf16.h>
#include <cuda_fp16.h>
#include <cstdint>
#include <cstddef>

// Problem constants
constexpr int B_ = 8;
constexpr int N_ = 2048;
constexpr int INC = 128;
constexpr int HIDC = 256;
constexpr int OUTC = 32;
constexpr int BN = B_ * N_;

// Scratch (device globals: no allocation allowed)
__device__ __align__(16) float g_deg_inv[BN];
__device__ __align__(16) __nv_bfloat16 g_agg_hi[(size_t)BN * HIDC];  // row-major
__device__ __align__(16) __nv_bfloat16 g_agg_lo[(size_t)BN * HIDC];
__device__ __align__(16) __nv_bfloat16 g_h_hi[(size_t)BN * HIDC];    // row-major
__device__ __align__(16) __nv_bfloat16 g_h_lo[(size_t)BN * HIDC];
__device__ __align__(16) __nv_bfloat16 g_x_hi[(size_t)BN * INC];     // row-major
__device__ __align__(16) __nv_bfloat16 g_x_lo[(size_t)BN * INC];
// layer1: x^T bf16 hi/lo; layer2: g_T_hi reused as h^T fp16 single
__device__ __align__(16) __nv_bfloat16 g_T_hi[(size_t)B_ * HIDC * N_];  // [b][d][i]
__device__ __align__(16) __nv_bfloat16 g_T_lo[(size_t)B_ * HIDC * N_];
// Mask tiles, PRE-SWIZZLED fp16: [b][jt(32)][it(32)][8192 bytes] (64j x 64i)
__device__ __align__(16) __nv_bfloat16 g_Mt[(size_t)B_ * N_ * N_];
__device__ __align__(16) __nv_bfloat16 g_W1t_hi[2 * HIDC * INC];   // [mtx][n][k]
__device__ __align__(16) __nv_bfloat16 g_W1t_lo[2 * HIDC * INC];
__device__ __align__(16) __nv_bfloat16 g_W2t_hi[2 * OUTC * HIDC];
__device__ __align__(16) __nv_bfloat16 g_W2t_lo[2 * OUTC * HIDC];

#define SWZ(off) ((off) ^ (((off) >> 3) & 0x70))

__device__ __forceinline__ uint32_t smem_u32(const void* p) {
    uint32_t a;
    asm("{ .reg .u64 t; cvta.to.shared.u64 t, %1; cvt.u32.u64 %0, t; }"
        : "=r"(a) : "l"(p));
    return a;
}
__device__ __forceinline__ void cpa16(uint32_t dst, const void* src) {
    asm volatile("cp.async.cg.shared.global [%0], [%1], 16;" :: "r"(dst), "l"(src));
}
__device__ __forceinline__ void ldsm4(uint32_t* r, uint32_t addr) {
    asm volatile("ldmatrix.sync.aligned.m8n8.x4.shared.b16 {%0,%1,%2,%3}, [%4];"
                 : "=r"(r[0]), "=r"(r[1]), "=r"(r[2]), "=r"(r[3]) : "r"(addr));
}
__device__ __forceinline__ void mma_bf16(float* c, const uint32_t* a,
                                         uint32_t b0, uint32_t b1) {
    asm volatile(
        "mma.sync.aligned.m16n8k16.row.col.f32.bf16.bf16.f32 "
        "{%0,%1,%2,%3}, {%4,%5,%6,%7}, {%8,%9}, {%0,%1,%2,%3};"
        : "+f"(c[0]), "+f"(c[1]), "+f"(c[2]), "+f"(c[3])
        : "r"(a[0]), "r"(a[1]), "r"(a[2]), "r"(a[3]), "r"(b0), "r"(b1));
}
__device__ __forceinline__ void mma_f16(float* c, const uint32_t* a,
                                        uint32_t b0, uint32_t b1) {
    asm volatile(
        "mma.sync.aligned.m16n8k16.row.col.f32.f16.f16.f32 "
        "{%0,%1,%2,%3}, {%4,%5,%6,%7}, {%8,%9}, {%0,%1,%2,%3};"
        : "+f"(c[0]), "+f"(c[1]), "+f"(c[2]), "+f"(c[3])
        : "r"(a[0]), "r"(a[1]), "r"(a[2]), "r"(a[3]), "r"(b0), "r"(b1));
}
__device__ __forceinline__ void split2(float v0, float v1, uint32_t& hw, uint32_t& lw) {
    __nv_bfloat16 h0 = __float2bfloat16(v0);
    __nv_bfloat16 h1 = __float2bfloat16(v1);
    __nv_bfloat16 l0 = __float2bfloat16(v0 - __bfloat162float(h0));
    __nv_bfloat16 l1 = __float2bfloat16(v1 - __bfloat162float(h1));
    __nv_bfloat162 hp; hp.x = h0; hp.y = h1;
    __nv_bfloat162 lp; lp.x = l0; lp.y = l1;
    hw = *reinterpret_cast<uint32_t*>(&hp);
    lw = *reinterpret_cast<uint32_t*>(&lp);
}
// bf16 {0,1} pair -> fp16 {0,1} pair (0x3F80 -> 0x3C00), exact
__device__ __forceinline__ uint32_t bf2fp_mask(uint32_t w) {
    return ((w >> 7) & 0x00010001u) * 0x3C00u;
}

// ---------------------------------------------------------------------------
// Merged prep: blockIdx.z < 8: x transpose + hi/lo splits; z == 8: weight prep.
// ---------------------------------------------------------------------------
__global__ __launch_bounds__(256)
void prep_kernel(const float* __restrict__ src,
                 const float* __restrict__ W1l, const float* __restrict__ W1r,
                 const float* __restrict__ W2l, const float* __restrict__ W2r) {
    constexpr int C = INC;
    if (blockIdx.z == 8) {
        // weight prep: 64 blocks x 256 threads, 5 elements each
        int base = (blockIdx.x * 2 + blockIdx.y) * 256 + threadIdx.x;
#pragma unroll 1
        for (int idx = base; idx < 2 * HIDC * INC + 2 * OUTC * HIDC; idx += 16384) {
            float v;
            __nv_bfloat16 *hi, *lo;
            int off;
            if (idx < 2 * HIDC * INC) {
                int mtx = idx >> 15, rem = idx & 32767;
                int n = rem >> 7, k = rem & 127;
                v = (mtx ? W1r : W1l)[k * HIDC + n];
                hi = g_W1t_hi; lo = g_W1t_lo; off = idx;
            } else {
                int j = idx - 2 * HIDC * INC;
                int mtx = j >> 13, rem = j & 8191;
                int n = rem >> 8, k = rem & 255;
                v = (mtx ? W2r : W2l)[k * OUTC + n];
                hi = g_W2t_hi; lo = g_W2t_lo; off = j;
            }
            __nv_bfloat16 h = __float2bfloat16(v);
            hi[off] = h;
            lo[off] = __float2bfloat16(v - __bfloat162float(h));
        }
        return;
    }

    __shared__ float sT[64][65];
    const int t = threadIdx.x;
    const int b = blockIdx.z, i0 = blockIdx.x * 64, d0 = blockIdx.y * 64;

#pragma unroll
    for (int p = 0; p < 4; ++p) {
        int e = t + p * 256;
        int row = e >> 4, c4 = e & 15;
        size_t goff = ((size_t)(b * N_ + i0 + row)) * C + d0 + c4 * 4;
        float4 v = *reinterpret_cast<const float4*>(src + goff);
        sT[row][c4 * 4 + 0] = v.x; sT[row][c4 * 4 + 1] = v.y;
        sT[row][c4 * 4 + 2] = v.z; sT[row][c4 * 4 + 3] = v.w;
        uint32_t h0, l0, h1, l1;
        split2(v.x, v.y, h0, l0);
        split2(v.z, v.w, h1, l1);
        *reinterpret_cast<uint2*>(g_x_hi + goff) = make_uint2(h0, h1);
        *reinterpret_cast<uint2*>(g_x_lo + goff) = make_uint2(l0, l1);
    }
    __syncthreads();

    const int d = t >> 2, ic = (t & 3) * 16;
    uint32_t hb[8], lb[8];
#pragma unroll
    for (int q = 0; q < 8; ++q)
        split2(sT[ic + q * 2][d], sT[ic + q * 2 + 1][d], hb[q], lb[q]);
    size_t obase = ((size_t)(b * C + d0 + d)) * N_ + i0 + ic;
    reinterpret_cast<uint4*>(g_T_hi + obase)[0] = make_uint4(hb[0], hb[1], hb[2], hb[3]);
    reinterpret_cast<uint4*>(g_T_hi + obase)[1] = make_uint4(hb[4], hb[5], hb[6], hb[7]);
    reinterpret_cast<uint4*>(g_T_lo + obase)[0] = make_uint4(lb[0], lb[1], lb[2], lb[3]);
    reinterpret_cast<uint4*>(g_T_lo + obase)[1] = make_uint4(lb[4], lb[5], lb[6], lb[7]);
}

// ---------------------------------------------------------------------------
// agg1 (fused): reads A, converts mask in-pipeline (degree fused), HMMAs with
// x^T hi/lo (bf16), writes agg1 bf16 hi/lo + fp16 pre-swizzled mask tiles.
// ---------------------------------------------------------------------------
__global__ __launch_bounds__(256, 2)
void agg1_kernel(const int* __restrict__ A) {
    extern __shared__ __align__(1024) char smem[];
    constexpr int C = INC;
    constexpr int NIT = N_ / 64;
    constexpr int STG = 40960;
    const int tid = threadIdx.x, lane = tid & 31, wid = tid >> 5;
    const int b = blockIdx.z, jt = blockIdx.x, j0 = jt * 64;
    const int jw = wid & 1, dw = wid >> 1;
    const uint32_t sb = smem_u32(smem);
    float* sdeg = reinterpret_cast<float*>(smem + 2 * STG);

    if (tid < 64) sdeg[tid] = 0.0f;

    float acc[2][4][4];
#pragma unroll
    for (int mg = 0; mg < 2; ++mg)
#pragma unroll
        for (int ng = 0; ng < 4; ++ng)
#pragma unroll
            for (int q = 0; q < 4; ++q) acc[mg][ng][q] = 0.0f;

    const int jj = tid & 63, iq = tid >> 6;
    const int* Ap = A + (size_t)b * N_ * N_ + j0 + jj;
    float degloc = 0.0f;

    auto fill = [&](int stage, int it) {
        const int i0 = it * 64;
        {
            char* mb = smem + stage * STG;
#pragma unroll
            for (int r = 0; r < 8; ++r) {
                int il = iq * 16 + r * 2;
                int a0 = Ap[(size_t)(i0 + il) * N_];
                int a1 = Ap[(size_t)(i0 + il + 1) * N_];
                float m0 = a0 ? 1.0f : 0.0f;
                float m1 = a1 ? 1.0f : 0.0f;
                degloc += m0 + m1;
                __nv_bfloat162 mv = __floats2bfloat162_rn(m0, m1);
                *reinterpret_cast<__nv_bfloat162*>(
                    mb + SWZ((uint32_t)(jj * 128 + il * 2))) = mv;
            }
        }
#pragma unroll
        for (int p = 0; p < 8; ++p) {
            int idx = tid + p * 256;
            int r = idx >> 3, c = idx & 7;
            int hl = r >> 7, d = r & 127;
            const __nv_bfloat16* g = hl ? g_T_lo : g_T_hi;
            cpa16(sb + stage * STG + 8192 + hl * 16384 +
                      SWZ((uint32_t)(d * 128 + c * 16)),
                  g + ((size_t)(b * C + d)) * N_ + i0 + c * 8);
        }
        asm volatile("cp.async.commit_group;");
    };

    fill(0, 0);

#pragma unroll 1
    for (int it = 0; it < NIT; ++it) {
        const int cur = it & 1;
        if (it + 1 < NIT) {
            fill(cur ^ 1, it + 1);
            asm volatile("cp.async.wait_group 1;");
        } else {
            asm volatile("cp.async.wait_group 0;");
        }
        __syncthreads();

        const uint32_t mbase = sb + cur * STG;
        const uint32_t xbase = mbase + 8192;
#pragma unroll
        for (int kk = 0; kk < 4; ++kk) {
            uint32_t a[2][4];
#pragma unroll
            for (int mg = 0; mg < 2; ++mg) {
                uint32_t addr = mbase + SWZ((uint32_t)(
                    (jw * 32 + mg * 16 + (lane & 15)) * 128 +
                    kk * 32 + (lane >> 4) * 16));
                ldsm4(a[mg], addr);
            }
#pragma unroll
            for (int hl = 0; hl < 2; ++hl) {
                uint32_t bf[2][4];
#pragma unroll
                for (int ng = 0; ng < 2; ++ng) {
                    int rowB = dw * 32 + ng * 16 + (lane & 7) + ((lane >> 4) << 3);
                    uint32_t addr = xbase + hl * 16384 + SWZ((uint32_t)(
                        rowB * 128 + kk * 32 + ((lane >> 3) & 1) * 16));
                    ldsm4(bf[ng], addr);
                }
#pragma unroll
                for (int mg = 0; mg < 2; ++mg)
#pragma unroll
                    for (int ng = 0; ng < 2; ++ng)
#pragma unroll
                        for (int sub = 0; sub < 2; ++sub)
                            mma_bf16(acc[mg][ng * 2 + sub], a[mg],
                                     bf[ng][sub * 2], bf[ng][sub * 2 + 1]);
            }
        }
        // write mask tile to gmem, converted bf16->fp16 (exact for 0/1)
        {
            const char* msrc = smem + cur * STG + tid * 32;
            uint4 v0 = *reinterpret_cast<const uint4*>(msrc);
            uint4 v1 = *reinterpret_cast<const uint4*>(msrc + 16);
            v0 = make_uint4(bf2fp_mask(v0.x), bf2fp_mask(v0.y),
                            bf2fp_mask(v0.z), bf2fp_mask(v0.w));
            v1 = make_uint4(bf2fp_mask(v1.x), bf2fp_mask(v1.y),
                            bf2fp_mask(v1.z), bf2fp_mask(v1.w));
            char* mdst = reinterpret_cast<char*>(g_Mt) +
                         (((size_t)(b * 32 + jt)) * 32 + it) * 8192 + tid * 32;
            *reinterpret_cast<uint4*>(mdst) = v0;
            *reinterpret_cast<uint4*>(mdst + 16) = v1;
        }
        __syncthreads();
    }

    atomicAdd(&sdeg[jj], degloc);
    __syncthreads();
    if (tid < 64) {
        float dinv = 1.0f / fmaxf(sdeg[tid], 1.0f);
        g_deg_inv[b * N_ + j0 + tid] = dinv;
        sdeg[tid] = dinv;
    }
    __syncthreads();

#pragma unroll
    for (int mg = 0; mg < 2; ++mg) {
        int jl0 = jw * 32 + mg * 16 + (lane >> 2);
        float dv0 = sdeg[jl0], dv1 = sdeg[jl0 + 8];
#pragma unroll
        for (int ng = 0; ng < 4; ++ng) {
            int d = dw * 32 + ng * 8 + (lane & 3) * 2;
            size_t ro = ((size_t)(b * N_ + j0 + jl0)) * C + d;
            uint32_t hw, lw;
            split2(acc[mg][ng][0] * dv0, acc[mg][ng][1] * dv0, hw, lw);
            *reinterpret_cast<uint32_t*>(g_agg_hi + ro) = hw;
            *reinterpret_cast<uint32_t*>(g_agg_lo + ro) = lw;
            split2(acc[mg][ng][2] * dv1, acc[mg][ng][3] * dv1, hw, lw);
            *reinterpret_cast<uint32_t*>(g_agg_hi + ro + (size_t)8 * C) = hw;
            *reinterpret_cast<uint32_t*>(g_agg_lo + ro + (size_t)8 * C) = lw;
        }
    }
}

// ---------------------------------------------------------------------------
// agg2 (fp16 single-term): 128j x 128d tiles; mask fp16 tiles + h^T fp16.
// grid (16, 2, 8); 8 warps (4jw x 2dw); warp = 32j x 64d.
// ---------------------------------------------------------------------------
__global__ __launch_bounds__(256, 2)
void agg2_kernel() {
    extern __shared__ __align__(1024) char smem[];
    constexpr int C = HIDC;
    constexpr int NIT = N_ / 64;
    constexpr int STG = 32768;  // mask 16 KB (2 tiles) + X 16 KB
    const int tid = threadIdx.x, lane = tid & 31, wid = tid >> 5;
    const int b = blockIdx.z, jt0 = blockIdx.x * 2, j0 = blockIdx.x * 128;
    const int d0 = blockIdx.y * 128;
    const int jw = wid & 3, dw = wid >> 2;
    const uint32_t sb = smem_u32(smem);
    const __half* hT = reinterpret_cast<const __half*>(g_T_hi);

    float acc[2][8][4];
#pragma unroll
    for (int mg = 0; mg < 2; ++mg)
#pragma unroll
        for (int ng = 0; ng < 8; ++ng)
#pragma unroll
            for (int q = 0; q < 4; ++q) acc[mg][ng][q] = 0.0f;

    const char* Mbase = reinterpret_cast<const char*>(g_Mt) +
                        ((size_t)(b * 32 + jt0)) * 32 * 8192;

    auto fill = [&](int stage, int it) {
        const int i0 = it * 64;
        // two pre-swizzled fp16 mask tiles (raw copy)
#pragma unroll
        for (int p = 0; p < 4; ++p) {
            int idx = tid + p * 256;
            int t = idx >> 9, off = (idx & 511) * 16;
            cpa16(sb + stage * STG + t * 8192 + off,
                  Mbase + (size_t)t * 32 * 8192 + (size_t)it * 8192 + off);
        }
        // h^T fp16: 128d x 64i (128 B rows)
#pragma unroll
        for (int p = 0; p < 4; ++p) {
            int idx = tid + p * 256;
            int row = idx >> 3, c = idx & 7;
            cpa16(sb + stage * STG + 16384 + SWZ((uint32_t)(row * 128 + c * 16)),
                  hT + ((size_t)(b * C + d0 + row)) * N_ + i0 + c * 8);
        }
        asm volatile("cp.async.commit_group;");
    };

    fill(0, 0);

#pragma unroll 1
    for (int it = 0; it < NIT; ++it) {
        const int cur = it & 1;
        if (it + 1 < NIT) {
            fill(cur ^ 1, it + 1);
            asm volatile("cp.async.wait_group 1;");
        } else {
            asm volatile("cp.async.wait_group 0;");
        }
        __syncthreads();

        const uint32_t mbase = sb + cur * STG;
        const uint32_t xbase = mbase + 16384;
#pragma unroll
        for (int kk = 0; kk < 4; ++kk) {
            uint32_t a[2][4];
#pragma unroll
            for (int mg = 0; mg < 2; ++mg) {
                int row = jw * 32 + mg * 16 + (lane & 15);
                uint32_t addr = mbase + (row >> 6) * 8192 + SWZ((uint32_t)(
                    (row & 63) * 128 + kk * 32 + (lane >> 4) * 16));
                ldsm4(a[mg], addr);
            }
            uint32_t bf[4][4];
#pragma unroll
            for (int ng = 0; ng < 4; ++ng) {
                int rowB = dw * 64 + ng * 16 + (lane & 7) + ((lane >> 4) << 3);
                uint32_t addr = xbase + SWZ((uint32_t)(
                    rowB * 128 + kk * 32 + ((lane >> 3) & 1) * 16));
                ldsm4(bf[ng], addr);
            }
#pragma unroll
            for (int mg = 0; mg < 2; ++mg)
#pragma unroll
                for (int ng = 0; ng < 4; ++ng)
#pragma unroll
                    for (int sub = 0; sub < 2; ++sub)
                        mma_f16(acc[mg][ng * 2 + sub], a[mg],
                                bf[ng][sub * 2], bf[ng][sub * 2 + 1]);
        }
        __syncthreads();
    }

#pragma unroll
    for (int mg = 0; mg < 2; ++mg) {
        int jl0 = jw * 32 + mg * 16 + (lane >> 2);
        float dv0 = g_deg_inv[b * N_ + j0 + jl0];
        float dv1 = g_deg_inv[b * N_ + j0 + jl0 + 8];
#pragma unroll
        for (int ng = 0; ng < 8; ++ng) {
            int d = d0 + dw * 64 + ng * 8 + (lane & 3) * 2;
            size_t ro = ((size_t)(b * N_ + j0 + jl0)) * C + d;
            uint32_t hw, lw;
            split2(acc[mg][ng][0] * dv0, acc[mg][ng][1] * dv0, hw, lw);
            *reinterpret_cast<uint32_t*>(g_agg_hi + ro) = hw;
            *reinterpret_cast<uint32_t*>(g_agg_lo + ro) = lw;
            split2(acc[mg][ng][2] * dv1, acc[mg][ng][3] * dv1, hw, lw);
            *reinterpret_cast<uint32_t*>(g_agg_hi + ro + (size_t)8 * C) = hw;
            *reinterpret_cast<uint32_t*>(g_agg_lo + ro + (size_t)8 * C) = lw;
        }
    }
}

// ---------------------------------------------------------------------------
// Dense1: per-64K-chunk load {A_hi, A_lo, W_hi, W_lo}; 3 MMA combos.
// CTA 64 x 128; 4 stages. Epilogue: h row-major bf16 hi/lo + h^T fp16 single.
// ---------------------------------------------------------------------------
__global__ __launch_bounds__(256, 2)
void dense1_mma_kernel(const float* __restrict__ b1) {
    extern __shared__ __align__(1024) char smem[];
    constexpr int STG = 49152;  // Ah 8K | Al 8K | Bh 16K | Bl 16K
    const int tid = threadIdx.x, lane = tid & 31, wid = tid >> 5;
    const int mw = wid & 1, nw = wid >> 1;
    const int r0 = blockIdx.x * 64, c0 = blockIdx.y * 128;
    const int b = r0 >> 11, i0 = r0 & (N_ - 1);
    const uint32_t sb = smem_u32(smem);

    float acc[2][4][4];
#pragma unroll
    for (int mg = 0; mg < 2; ++mg)
#pragma unroll
        for (int nq = 0; nq < 4; ++nq)
#pragma unroll
            for (int q = 0; q < 4; ++q) acc[mg][nq][q] = 0.0f;

    auto load_stage = [&](int st, int sidx) {
        const int part = sidx >> 1, kb = (sidx & 1) * 64;
        const __nv_bfloat16* Ah = part ? g_x_hi : g_agg_hi;
        const __nv_bfloat16* Al = part ? g_x_lo : g_agg_lo;
        const __nv_bfloat16* Bh = g_W1t_hi + part * HIDC * INC;
        const __nv_bfloat16* Bl = g_W1t_lo + part * HIDC * INC;
#pragma unroll
        for (int p = 0; p < 4; ++p) {
            int idx = tid + p * 256;
            int r = idx >> 3, c = idx & 7;
            int hl = r >> 6, row = r & 63;
            cpa16(sb + st * STG + hl * 8192 + SWZ((uint32_t)(row * 128 + c * 16)),
                  (hl ? Al : Ah) + (size_t)(r0 + row) * INC + kb + c * 8);
        }
#pragma unroll
        for (int p = 0; p < 8; ++p) {
            int idx = tid + p * 256;
            int r = idx >> 3, c = idx & 7;
            int hl = r >> 7, row = r & 127;
            cpa16(sb + st * STG + 16384 + hl * 16384 +
                      SWZ((uint32_t)(row * 128 + c * 16)),
                  (hl ? Bl : Bh) + (size_t)(c0 + row) * INC + kb + c * 8);
        }
        asm volatile("cp.async.commit_group;");
    };

    load_stage(0, 0);

#pragma unroll 1
    for (int s = 0; s < 4; ++s) {
        const int cur = s & 1;
        if (s + 1 < 4) {
            load_stage(cur ^ 1, s + 1);
            asm volatile("cp.async.wait_group 1;");
        } else {
            asm volatile("cp.async.wait_group 0;");
        }
        __syncthreads();

        const uint32_t ahb = sb + cur * STG;
        const uint32_t alb = ahb + 8192;
        const uint32_t bhb = ahb + 16384;
        const uint32_t blb = ahb + 32768;
#pragma unroll
        for (int kk = 0; kk < 4; ++kk) {
            uint32_t ah[2][4], al[2][4];
#pragma unroll
            for (int mg = 0; mg < 2; ++mg) {
                uint32_t off = SWZ((uint32_t)(
                    (mw * 32 + mg * 16 + (lane & 15)) * 128 +
                    kk * 32 + (lane >> 4) * 16));
                ldsm4(ah[mg], ahb + off);
                ldsm4(al[mg], alb + off);
            }
            uint32_t bh[2][4], bl[2][4];
#pragma unroll
            for (int ng = 0; ng < 2; ++ng) {
                int rowB = nw * 32 + ng * 16 + (lane & 7) + ((lane >> 4) << 3);
                uint32_t off = SWZ((uint32_t)(
                    rowB * 128 + kk * 32 + ((lane >> 3) & 1) * 16));
                ldsm4(bh[ng], bhb + off);
                ldsm4(bl[ng], blb + off);
            }
#pragma unroll
            for (int mg = 0; mg < 2; ++mg)
#pragma unroll
                for (int ng = 0; ng < 2; ++ng)
#pragma unroll
                    for (int sub = 0; sub < 2; ++sub) {
                        float* c = acc[mg][ng * 2 + sub];
                        mma_bf16(c, ah[mg], bh[ng][sub * 2], bh[ng][sub * 2 + 1]);
                        mma_bf16(c, al[mg], bh[ng][sub * 2], bh[ng][sub * 2 + 1]);
                        mma_bf16(c, ah[mg], bl[ng][sub * 2], bl[ng][sub * 2 + 1]);
                    }
        }
        __syncthreads();
    }

    // bias + relu, row-major bf16 hi/lo stores
#pragma unroll
    for (int mg = 0; mg < 2; ++mg) {
#pragma unroll
        for (int nq = 0; nq < 4; ++nq) {
            int dloc = nw * 32 + nq * 8 + (lane & 3) * 2;
            float2 bv = *reinterpret_cast<const float2*>(b1 + c0 + dloc);
            acc[mg][nq][0] = fmaxf(acc[mg][nq][0] + bv.x, 0.0f);
            acc[mg][nq][1] = fmaxf(acc[mg][nq][1] + bv.y, 0.0f);
            acc[mg][nq][2] = fmaxf(acc[mg][nq][2] + bv.x, 0.0f);
            acc[mg][nq][3] = fmaxf(acc[mg][nq][3] + bv.y, 0.0f);
            size_t ro = ((size_t)(r0 + mw * 32 + mg * 16 + (lane >> 2))) * HIDC +
                        c0 + dloc;
            uint32_t hw, lw;
            split2(acc[mg][nq][0], acc[mg][nq][1], hw, lw);
            *reinterpret_cast<uint32_t*>(g_h_hi + ro) = hw;
            *reinterpret_cast<uint32_t*>(g_h_lo + ro) = lw;
            split2(acc[mg][nq][2], acc[mg][nq][3], hw, lw);
            *reinterpret_cast<uint32_t*>(g_h_hi + ro + (size_t)8 * HIDC) = hw;
            *reinterpret_cast<uint32_t*>(g_h_lo + ro + (size_t)8 * HIDC) = lw;
        }
    }

    // single-pass transpose, fp16 single h^T
    float* sT = reinterpret_cast<float*>(smem);  // [64][129]
#pragma unroll
    for (int mg = 0; mg < 2; ++mg)
#pragma unroll
        for (int nq = 0; nq < 4; ++nq)
#pragma unroll
            for (int q = 0; q < 4; ++q) {
                int irow = mw * 32 + mg * 16 + (lane >> 2) + (q >> 1) * 8;
                int dl = nw * 32 + nq * 8 + (lane & 3) * 2 + (q & 1);
                sT[irow * 129 + dl] = acc[mg][nq][q];
            }
    __syncthreads();

    const int dl = tid & 127, iq = (tid >> 7) * 32;
    uint32_t hb[16];
#pragma unroll
    for (int q = 0; q < 16; ++q) {
        __half2 hp = __floats2half2_rn(sT[(iq + q * 2) * 129 + dl],
                                       sT[(iq + q * 2 + 1) * 129 + dl]);
        hb[q] = *reinterpret_cast<uint32_t*>(&hp);
    }
    __half* hT = reinterpret_cast<__half*>(g_T_hi);
    size_t ob = ((size_t)(b * HIDC + c0 + dl)) * N_ + i0 + iq;
#pragma unroll
    for (int q = 0; q < 4; ++q)
        reinterpret_cast<uint4*>(hT + ob)[q] =
            make_uint4(hb[q * 4], hb[q * 4 + 1], hb[q * 4 + 2], hb[q * 4 + 3]);
}

// ---------------------------------------------------------------------------
// Dense2: per-chunk {A_hi, A_lo, W_hi, W_lo} with 3 combos; 8 stages.
// ---------------------------------------------------------------------------
__global__ __launch_bounds__(256, 2)
void dense2_mma_kernel(const float* __restrict__ b2, float* __restrict__ out,
                       int write_raw) {
    extern __shared__ __align__(1024) char smem[];
    constexpr int STG = 40960;  // Ah 16K | Al 16K | Bh 4K | Bl 4K
    const int tid = threadIdx.x, lane = tid & 31, wid = tid >> 5;
    const int r0 = blockIdx.x * 128;
    const uint32_t sb = smem_u32(smem);

    float acc[4][4];
#pragma unroll
    for (int t = 0; t < 4; ++t)
#pragma unroll
        for (int q = 0; q < 4; ++q) acc[t][q] = 0.0f;

    auto load_stage = [&](int st, int sidx) {
        const int part = sidx >> 2, kb = (sidx & 3) * 64;
        const __nv_bfloat16* Ah = part ? g_h_hi : g_agg_hi;
        const __nv_bfloat16* Al = part ? g_h_lo : g_agg_lo;
        const __nv_bfloat16* Bh = g_W2t_hi + part * OUTC * HIDC;
        const __nv_bfloat16* Bl = g_W2t_lo + part * OUTC * HIDC;
#pragma unroll
        for (int p = 0; p < 8; ++p) {
            int idx = tid + p * 256;
            int r = idx >> 3, c = idx & 7;
            int hl = r >> 7, row = r & 127;
            cpa16(sb + st * STG + hl * 16384 + SWZ((uint32_t)(row * 128 + c * 16)),
                  (hl ? Al : Ah) + (size_t)(r0 + row) * HIDC + kb + c * 8);
        }
#pragma unroll
        for (int p = 0; p < 2; ++p) {
            int idx = tid + p * 256;
            int r = idx >> 3, c = idx & 7;
            int hl = r >> 5, row = r & 31;
            cpa16(sb + st * STG + 32768 + hl * 4096 +
                      SWZ((uint32_t)(row * 128 + c * 16)),
                  (hl ? Bl : Bh) + (size_t)row * HIDC + kb + c * 8);
        }
        asm volatile("cp.async.commit_group;");
    };

    load_stage(0, 0);

#pragma unroll 1
    for (int s = 0; s < 8; ++s) {
        const int cur = s & 1;
        if (s + 1 < 8) {
            load_stage(cur ^ 1, s + 1);
            asm volatile("cp.async.wait_group 1;");
        } else {
            asm volatile("cp.async.wait_group 0;");
        }
        __syncthreads();

        const uint32_t ahb = sb + cur * STG;
        const uint32_t alb = ahb + 16384;
        const uint32_t bhb = ahb + 32768;
        const uint32_t blb = ahb + 36864;
#pragma unroll
        for (int kk = 0; kk < 4; ++kk) {
            uint32_t ah[4], al[4];
            {
                uint32_t off = SWZ((uint32_t)(
                    (wid * 16 + (lane & 15)) * 128 + kk * 32 + (lane >> 4) * 16));
                ldsm4(ah, ahb + off);
                ldsm4(al, alb + off);
            }
            uint32_t bh[2][4], bl[2][4];
#pragma unroll
            for (int ng = 0; ng < 2; ++ng) {
                int rowB = ng * 16 + (lane & 7) + ((lane >> 4) << 3);
                uint32_t off = SWZ((uint32_t)(
                    rowB * 128 + kk * 32 + ((lane >> 3) & 1) * 16));
                ldsm4(bh[ng], bhb + off);
                ldsm4(bl[ng], blb + off);
            }
#pragma unroll
            for (int ng = 0; ng < 2; ++ng)
#pragma unroll
                for (int sub = 0; sub < 2; ++sub) {
                    float* c = acc[ng * 2 + sub];
                    mma_bf16(c, ah, bh[ng][sub * 2], bh[ng][sub * 2 + 1]);
                    mma_bf16(c, al, bh[ng][sub * 2], bh[ng][sub * 2 + 1]);
                    mma_bf16(c, ah, bl[ng][sub * 2], bl[ng][sub * 2 + 1]);
                }
        }
        __syncthreads();
    }

    float* sOut = reinterpret_cast<float*>(smem);
    __syncthreads();
#pragma unroll
    for (int t = 0; t < 4; ++t) {
        int d = t * 8 + (lane & 3) * 2;
        float2 bv = *reinterpret_cast<const float2*>(b2 + d);
        int row = wid * 16 + (lane >> 2);
        sOut[row * 33 + d] = acc[t][0] + bv.x;
        sOut[row * 33 + d + 1] = acc[t][1] + bv.y;
        sOut[(row + 8) * 33 + d] = acc[t][2] + bv.x;
        sOut[(row + 8) * 33 + d + 1] = acc[t][3] + bv.y;
    }
    __syncthreads();

#pragma unroll 1
    for (int rit = 0; rit < 16; ++rit) {
        int row = rit * 8 + wid;
        float v = sOut[row * 33 + lane];
        float m = v;
#pragma unroll
        for (int o = 16; o > 0; o >>= 1)
            m = fmaxf(m, __shfl_xor_sync(0xffffffffu, m, o));
        float s = expf(v - m);
#pragma unroll
        for (int o = 16; o > 0; o >>= 1)
            s += __shfl_xor_sync(0xffffffffu, s, o);
        float lsm = v - m - logf(s);
        size_t gi = (size_t)(r0 + row) * OUTC + lane;
        out[gi] = lsm;
        if (write_raw) out[(size_t)BN * OUTC + gi] = v;
    }
}

// ---------------------------------------------------------------------------
extern "C" void kernel_launch(void* const* d_in, const int* in_sizes, int n_in,
                              void* d_out, int out_size) {
    const float* x   = (const float*)d_in[0];
    const int*   A   = (const int*)d_in[1];
    const float* W1l = (const float*)d_in[2];
    const float* W1r = (const float*)d_in[3];
    const float* b1  = (const float*)d_in[4];
    const float* W2l = (const float*)d_in[5];
    const float* W2r = (const float*)d_in[6];
    const float* b2  = (const float*)d_in[7];
    float* out = (float*)d_out;
    (void)in_sizes; (void)n_in;

    const int write_raw = (out_size >= 2 * BN * OUTC) ? 1 : 0;

    constexpr int AGG1_SMEM = 2 * 40960 + 256;  // 82176
    constexpr int AGG2_SMEM = 2 * 32768;        // 65536
    constexpr int D1_SMEM = 2 * 49152;          // 98304
    constexpr int D2_SMEM = 2 * 40960;          // 81920
    cudaFuncSetAttribute(agg1_kernel,
                         cudaFuncAttributeMaxDynamicSharedMemorySize, AGG1_SMEM);
    cudaFuncSetAttribute(agg2_kernel,
                         cudaFuncAttributeMaxDynamicSharedMemorySize, AGG2_SMEM);
    cudaFuncSetAttribute(dense1_mma_kernel,
                         cudaFuncAttributeMaxDynamicSharedMemorySize, D1_SMEM);
    cudaFuncSetAttribute(dense2_mma_kernel,
                         cudaFuncAttributeMaxDynamicSharedMemorySize, D2_SMEM);

    prep_kernel<<<dim3(N_ / 64, INC / 64, B_ + 1), 256>>>(x, W1l, W1r, W2l, W2r);
    agg1_kernel<<<dim3(N_ / 64, 1, B_), 256, AGG1_SMEM>>>(A);
    dense1_mma_kernel<<<dim3(BN / 64, HIDC / 128), 256, D1_SMEM>>>(b1);
    agg2_kernel<<<dim3(N_ / 128, HIDC / 128, B_), 256, AGG2_SMEM>>>();
    dense2_mma_kernel<<<BN / 128, 256, D2_SMEM>>>(b2, out, write_raw);
}

// round 10
// speedup vs baseline: 1.9206x; 1.0653x over previous
#include <cuda_runtime.h>
#include <cuda_bf16.h>
#include <cuda_fp16.h>
#include <cstdint>
#include <cstddef>

// Problem constants
constexpr int B_ = 8;
constexpr int N_ = 2048;
constexpr int INC = 128;
constexpr int HIDC = 256;
constexpr int OUTC = 32;
constexpr int BN = B_ * N_;

// Scratch (device globals: no allocation allowed)
__device__ __align__(16) float g_deg_inv[BN];
__device__ __align__(16) __nv_bfloat16 g_agg_hi[(size_t)BN * HIDC];  // row-major
__device__ __align__(16) __nv_bfloat16 g_agg_lo[(size_t)BN * HIDC];
__device__ __align__(16) __nv_bfloat16 g_h_hi[(size_t)BN * HIDC];    // row-major
__device__ __align__(16) __nv_bfloat16 g_h_lo[(size_t)BN * HIDC];
__device__ __align__(16) __nv_bfloat16 g_x_hi[(size_t)BN * INC];     // row-major
__device__ __align__(16) __nv_bfloat16 g_x_lo[(size_t)BN * INC];
// layer1: x^T fp16 single; layer2: reused as h^T fp16 single  [b][d][i]
__device__ __align__(16) __half g_T16[(size_t)B_ * HIDC * N_];
// Bit-packed mask: [b][jt64(32)][it64(32)] tiles of 64j x 64i bits
// tile = 256 uint16; entry [iq(4)*64 + jj(64)] covers i = iq*16..+15 of row jj
__device__ __align__(16) uint16_t g_Mbits[(size_t)B_ * 32 * 32 * 256];
__device__ __align__(16) __nv_bfloat16 g_W1t_hi[2 * HIDC * INC];   // [mtx][n][k]
__device__ __align__(16) __nv_bfloat16 g_W1t_lo[2 * HIDC * INC];
__device__ __align__(16) __nv_bfloat16 g_W2t_hi[2 * OUTC * HIDC];
__device__ __align__(16) __nv_bfloat16 g_W2t_lo[2 * OUTC * HIDC];

#define SWZ(off) ((off) ^ (((off) >> 3) & 0x70))

__device__ __forceinline__ uint32_t smem_u32(const void* p) {
    uint32_t a;
    asm("{ .reg .u64 t; cvta.to.shared.u64 t, %1; cvt.u32.u64 %0, t; }"
        : "=r"(a) : "l"(p));
    return a;
}
__device__ __forceinline__ void cpa16(uint32_t dst, const void* src) {
    asm volatile("cp.async.cg.shared.global [%0], [%1], 16;" :: "r"(dst), "l"(src));
}
__device__ __forceinline__ void ldsm4(uint32_t* r, uint32_t addr) {
    asm volatile("ldmatrix.sync.aligned.m8n8.x4.shared.b16 {%0,%1,%2,%3}, [%4];"
                 : "=r"(r[0]), "=r"(r[1]), "=r"(r[2]), "=r"(r[3]) : "r"(addr));
}
__device__ __forceinline__ void mma_bf16(float* c, const uint32_t* a,
                                         uint32_t b0, uint32_t b1) {
    asm volatile(
        "mma.sync.aligned.m16n8k16.row.col.f32.bf16.bf16.f32 "
        "{%0,%1,%2,%3}, {%4,%5,%6,%7}, {%8,%9}, {%0,%1,%2,%3};"
        : "+f"(c[0]), "+f"(c[1]), "+f"(c[2]), "+f"(c[3])
        : "r"(a[0]), "r"(a[1]), "r"(a[2]), "r"(a[3]), "r"(b0), "r"(b1));
}
__device__ __forceinline__ void mma_f16(float* c, const uint32_t* a,
                                        uint32_t b0, uint32_t b1) {
    asm volatile(
        "mma.sync.aligned.m16n8k16.row.col.f32.f16.f16.f32 "
        "{%0,%1,%2,%3}, {%4,%5,%6,%7}, {%8,%9}, {%0,%1,%2,%3};"
        : "+f"(c[0]), "+f"(c[1]), "+f"(c[2]), "+f"(c[3])
        : "r"(a[0]), "r"(a[1]), "r"(a[2]), "r"(a[3]), "r"(b0), "r"(b1));
}
__device__ __forceinline__ void split2(float v0, float v1, uint32_t& hw, uint32_t& lw) {
    __nv_bfloat16 h0 = __float2bfloat16(v0);
    __nv_bfloat16 h1 = __float2bfloat16(v1);
    __nv_bfloat16 l0 = __float2bfloat16(v0 - __bfloat162float(h0));
    __nv_bfloat16 l1 = __float2bfloat16(v1 - __bfloat162float(h1));
    __nv_bfloat162 hp; hp.x = h0; hp.y = h1;
    __nv_bfloat162 lp; lp.x = l0; lp.y = l1;
    hw = *reinterpret_cast<uint32_t*>(&hp);
    lw = *reinterpret_cast<uint32_t*>(&lp);
}
// Expand low 8 bits of w into 4 fp16x2 words ({0,1} values)
__device__ __forceinline__ uint4 expand8(uint32_t w) {
    uint4 r;
    r.x = ((w >> 0) & 1u) * 0x3C00u | ((w >> 1) & 1u) * 0x3C000000u;
    r.y = ((w >> 2) & 1u) * 0x3C00u | ((w >> 3) & 1u) * 0x3C000000u;
    r.z = ((w >> 4) & 1u) * 0x3C00u | ((w >> 5) & 1u) * 0x3C000000u;
    r.w = ((w >> 6) & 1u) * 0x3C00u | ((w >> 7) & 1u) * 0x3C000000u;
    return r;
}

// ---------------------------------------------------------------------------
// Merged prep: z < 8: x transpose->fp16 + row-major bf16 hi/lo; z == 8: weights.
// ---------------------------------------------------------------------------
__global__ __launch_bounds__(256)
void prep_kernel(const float* __restrict__ src,
                 const float* __restrict__ W1l, const float* __restrict__ W1r,
                 const float* __restrict__ W2l, const float* __restrict__ W2r) {
    constexpr int C = INC;
    if (blockIdx.z == 8) {
        int base = (blockIdx.x * 2 + blockIdx.y) * 256 + threadIdx.x;
#pragma unroll 1
        for (int idx = base; idx < 2 * HIDC * INC + 2 * OUTC * HIDC; idx += 16384) {
            float v;
            __nv_bfloat16 *hi, *lo;
            int off;
            if (idx < 2 * HIDC * INC) {
                int mtx = idx >> 15, rem = idx & 32767;
                int n = rem >> 7, k = rem & 127;
                v = (mtx ? W1r : W1l)[k * HIDC + n];
                hi = g_W1t_hi; lo = g_W1t_lo; off = idx;
            } else {
                int j = idx - 2 * HIDC * INC;
                int mtx = j >> 13, rem = j & 8191;
                int n = rem >> 8, k = rem & 255;
                v = (mtx ? W2r : W2l)[k * OUTC + n];
                hi = g_W2t_hi; lo = g_W2t_lo; off = j;
            }
            __nv_bfloat16 h = __float2bfloat16(v);
            hi[off] = h;
            lo[off] = __float2bfloat16(v - __bfloat162float(h));
        }
        return;
    }

    __shared__ float sT[64][65];
    const int t = threadIdx.x;
    const int b = blockIdx.z, i0 = blockIdx.x * 64, d0 = blockIdx.y * 64;

#pragma unroll
    for (int p = 0; p < 4; ++p) {
        int e = t + p * 256;
        int row = e >> 4, c4 = e & 15;
        size_t goff = ((size_t)(b * N_ + i0 + row)) * C + d0 + c4 * 4;
        float4 v = *reinterpret_cast<const float4*>(src + goff);
        sT[row][c4 * 4 + 0] = v.x; sT[row][c4 * 4 + 1] = v.y;
        sT[row][c4 * 4 + 2] = v.z; sT[row][c4 * 4 + 3] = v.w;
        uint32_t h0, l0, h1, l1;
        split2(v.x, v.y, h0, l0);
        split2(v.z, v.w, h1, l1);
        *reinterpret_cast<uint2*>(g_x_hi + goff) = make_uint2(h0, h1);
        *reinterpret_cast<uint2*>(g_x_lo + goff) = make_uint2(l0, l1);
    }
    __syncthreads();

    const int d = t >> 2, ic = (t & 3) * 16;
    uint32_t hb[8];
#pragma unroll
    for (int q = 0; q < 8; ++q) {
        __half2 hp = __floats2half2_rn(sT[ic + q * 2][d], sT[ic + q * 2 + 1][d]);
        hb[q] = *reinterpret_cast<uint32_t*>(&hp);
    }
    size_t obase = ((size_t)(b * C + d0 + d)) * N_ + i0 + ic;
    reinterpret_cast<uint4*>(g_T16 + obase)[0] = make_uint4(hb[0], hb[1], hb[2], hb[3]);
    reinterpret_cast<uint4*>(g_T16 + obase)[1] = make_uint4(hb[4], hb[5], hb[6], hb[7]);
}

// ---------------------------------------------------------------------------
// agg1: reads A, converts mask in-pipeline (fp16 + packed bits + degree),
// fp16 single-term MMA with x^T. CTA 64j x 128d; 3-stage pipeline.
// ---------------------------------------------------------------------------
__global__ __launch_bounds__(256, 2)
void agg1_kernel(const int* __restrict__ A) {
    extern __shared__ __align__(1024) char smem[];
    constexpr int C = INC;
    constexpr int NIT = N_ / 64;
    constexpr int STG = 24576;  // mask 8 KB | X 16 KB
    const int tid = threadIdx.x, lane = tid & 31, wid = tid >> 5;
    const int b = blockIdx.z, jt = blockIdx.x, j0 = jt * 64;
    const int jw = wid & 1, dw = wid >> 1;
    const uint32_t sb = smem_u32(smem);
    float* sdeg = reinterpret_cast<float*>(smem + 3 * STG);

    if (tid < 64) sdeg[tid] = 0.0f;

    float acc[2][4][4];
#pragma unroll
    for (int mg = 0; mg < 2; ++mg)
#pragma unroll
        for (int ng = 0; ng < 4; ++ng)
#pragma unroll
            for (int q = 0; q < 4; ++q) acc[mg][ng][q] = 0.0f;

    const int jj = tid & 63, iq = tid >> 6;  // iq: 16 i's each
    const int* Ap = A + (size_t)b * N_ * N_ + j0 + jj;
    float degloc = 0.0f;

    auto fill = [&](int stage, int it) {
        const int i0 = it * 64;
        // mask: LDG A (coalesced over j), fp16 to smem + packed bits to gmem
        {
            char* mb = smem + stage * STG;
            uint32_t bits = 0;
#pragma unroll
            for (int r = 0; r < 8; ++r) {
                int il = iq * 16 + r * 2;
                uint32_t b0 = Ap[(size_t)(i0 + il) * N_] ? 1u : 0u;
                uint32_t b1 = Ap[(size_t)(i0 + il + 1) * N_] ? 1u : 0u;
                bits |= (b0 << (r * 2)) | (b1 << (r * 2 + 1));
                degloc += (float)(b0 + b1);
                uint32_t mv = b0 * 0x3C00u | b1 * 0x3C000000u;
                *reinterpret_cast<uint32_t*>(
                    mb + SWZ((uint32_t)(jj * 128 + il * 2))) = mv;
            }
            g_Mbits[(((size_t)(b * 32 + jt)) * 32 + it) * 256 + iq * 64 + jj] =
                (uint16_t)bits;
        }
        // X fp16: 128d x 64i
#pragma unroll
        for (int p = 0; p < 4; ++p) {
            int idx = tid + p * 256;
            int row = idx >> 3, c = idx & 7;
            cpa16(sb + stage * STG + 8192 + SWZ((uint32_t)(row * 128 + c * 16)),
                  g_T16 + ((size_t)(b * C + row)) * N_ + i0 + c * 8);
        }
        asm volatile("cp.async.commit_group;");
    };

    fill(0, 0);
    fill(1, 1);

#pragma unroll 1
    for (int it = 0; it < NIT; ++it) {
        const int cur = it % 3;
        if (it + 2 < NIT) {
            fill((it + 2) % 3, it + 2);
            asm volatile("cp.async.wait_group 2;");
        } else if (it + 1 < NIT) {
            asm volatile("cp.async.wait_group 1;");
        } else {
            asm volatile("cp.async.wait_group 0;");
        }
        __syncthreads();

        const uint32_t mbase = sb + cur * STG;
        const uint32_t xbase = mbase + 8192;
#pragma unroll
        for (int kk = 0; kk < 4; ++kk) {
            uint32_t a[2][4];
#pragma unroll
            for (int mg = 0; mg < 2; ++mg) {
                uint32_t addr = mbase + SWZ((uint32_t)(
                    (jw * 32 + mg * 16 + (lane & 15)) * 128 +
                    kk * 32 + (lane >> 4) * 16));
                ldsm4(a[mg], addr);
            }
            uint32_t bf[2][4];
#pragma unroll
            for (int ng = 0; ng < 2; ++ng) {
                int rowB = dw * 32 + ng * 16 + (lane & 7) + ((lane >> 4) << 3);
                uint32_t addr = xbase + SWZ((uint32_t)(
                    rowB * 128 + kk * 32 + ((lane >> 3) & 1) * 16));
                ldsm4(bf[ng], addr);
            }
#pragma unroll
            for (int mg = 0; mg < 2; ++mg)
#pragma unroll
                for (int ng = 0; ng < 2; ++ng)
#pragma unroll
                    for (int sub = 0; sub < 2; ++sub)
                        mma_f16(acc[mg][ng * 2 + sub], a[mg],
                                bf[ng][sub * 2], bf[ng][sub * 2 + 1]);
        }
        __syncthreads();
    }

    atomicAdd(&sdeg[jj], degloc);
    __syncthreads();
    if (tid < 64) {
        float dinv = 1.0f / fmaxf(sdeg[tid], 1.0f);
        g_deg_inv[b * N_ + j0 + tid] = dinv;
        sdeg[tid] = dinv;
    }
    __syncthreads();

#pragma unroll
    for (int mg = 0; mg < 2; ++mg) {
        int jl0 = jw * 32 + mg * 16 + (lane >> 2);
        float dv0 = sdeg[jl0], dv1 = sdeg[jl0 + 8];
#pragma unroll
        for (int ng = 0; ng < 4; ++ng) {
            int d = dw * 32 + ng * 8 + (lane & 3) * 2;
            size_t ro = ((size_t)(b * N_ + j0 + jl0)) * C + d;
            uint32_t hw, lw;
            split2(acc[mg][ng][0] * dv0, acc[mg][ng][1] * dv0, hw, lw);
            *reinterpret_cast<uint32_t*>(g_agg_hi + ro) = hw;
            *reinterpret_cast<uint32_t*>(g_agg_lo + ro) = lw;
            split2(acc[mg][ng][2] * dv1, acc[mg][ng][3] * dv1, hw, lw);
            *reinterpret_cast<uint32_t*>(g_agg_hi + ro + (size_t)8 * C) = hw;
            *reinterpret_cast<uint32_t*>(g_agg_lo + ro + (size_t)8 * C) = lw;
        }
    }
}

// ---------------------------------------------------------------------------
// agg2: mask from packed bits (expand in-register), fp16 single-term with
// h^T fp16. CTA 128j x 128d; 3-stage pipeline.
// ---------------------------------------------------------------------------
__global__ __launch_bounds__(256, 2)
void agg2_kernel() {
    extern __shared__ __align__(1024) char smem[];
    constexpr int C = HIDC;
    constexpr int NIT = N_ / 64;
    constexpr int STG = 32768;  // mask 16 KB | X 16 KB
    const int tid = threadIdx.x, lane = tid & 31, wid = tid >> 5;
    const int b = blockIdx.z, jt0 = blockIdx.x * 2, j0 = blockIdx.x * 128;
    const int d0 = blockIdx.y * 128;
    const int jw = wid & 3, dw = wid >> 2;
    const uint32_t sb = smem_u32(smem);

    float acc[2][8][4];
#pragma unroll
    for (int mg = 0; mg < 2; ++mg)
#pragma unroll
        for (int ng = 0; ng < 8; ++ng)
#pragma unroll
            for (int q = 0; q < 4; ++q) acc[mg][ng][q] = 0.0f;

    const int jj = tid & 127, iq2 = tid >> 7;  // iq2: 32 i's each
    const int jt64 = jt0 + (jj >> 6), jjl = jj & 63;

    auto fill = [&](int stage, int it) {
        const int i0 = it * 64;
        // load packed bits (32 i per thread)
        const size_t bbase = (((size_t)(b * 32 + jt64)) * 32 + it) * 256;
        uint32_t w = (uint32_t)g_Mbits[bbase + (iq2 * 2) * 64 + jjl] |
                     ((uint32_t)g_Mbits[bbase + (iq2 * 2 + 1) * 64 + jjl] << 16);
        // X fp16 via cp.async: 128d x 64i
#pragma unroll
        for (int p = 0; p < 4; ++p) {
            int idx = tid + p * 256;
            int row = idx >> 3, c = idx & 7;
            cpa16(sb + stage * STG + 16384 + SWZ((uint32_t)(row * 128 + c * 16)),
                  g_T16 + ((size_t)(b * C + d0 + row)) * N_ + i0 + c * 8);
        }
        asm volatile("cp.async.commit_group;");
        // expand bits -> fp16 mask tile (4x 16B stores)
        char* mb = smem + stage * STG;
#pragma unroll
        for (int p = 0; p < 4; ++p) {
            uint4 v = expand8(w >> (p * 8));
            *reinterpret_cast<uint4*>(
                mb + SWZ((uint32_t)(jj * 128 + iq2 * 64 + p * 16))) = v;
        }
    };

    fill(0, 0);
    fill(1, 1);

#pragma unroll 1
    for (int it = 0; it < NIT; ++it) {
        const int cur = it % 3;
        if (it + 2 < NIT) {
            fill((it + 2) % 3, it + 2);
            asm volatile("cp.async.wait_group 2;");
        } else if (it + 1 < NIT) {
            asm volatile("cp.async.wait_group 1;");
        } else {
            asm volatile("cp.async.wait_group 0;");
        }
        __syncthreads();

        const uint32_t mbase = sb + cur * STG;
        const uint32_t xbase = mbase + 16384;
#pragma unroll
        for (int kk = 0; kk < 4; ++kk) {
            uint32_t a[2][4];
#pragma unroll
            for (int mg = 0; mg < 2; ++mg) {
                int row = jw * 32 + mg * 16 + (lane & 15);
                uint32_t addr = mbase + SWZ((uint32_t)(
                    row * 128 + kk * 32 + (lane >> 4) * 16));
                ldsm4(a[mg], addr);
            }
            uint32_t bf[4][4];
#pragma unroll
            for (int ng = 0; ng < 4; ++ng) {
                int rowB = dw * 64 + ng * 16 + (lane & 7) + ((lane >> 4) << 3);
                uint32_t addr = xbase + SWZ((uint32_t)(
                    rowB * 128 + kk * 32 + ((lane >> 3) & 1) * 16));
                ldsm4(bf[ng], addr);
            }
#pragma unroll
            for (int mg = 0; mg < 2; ++mg)
#pragma unroll
                for (int ng = 0; ng < 4; ++ng)
#pragma unroll
                    for (int sub = 0; sub < 2; ++sub)
                        mma_f16(acc[mg][ng * 2 + sub], a[mg],
                                bf[ng][sub * 2], bf[ng][sub * 2 + 1]);
        }
        __syncthreads();
    }

#pragma unroll
    for (int mg = 0; mg < 2; ++mg) {
        int jl0 = jw * 32 + mg * 16 + (lane >> 2);
        float dv0 = g_deg_inv[b * N_ + j0 + jl0];
        float dv1 = g_deg_inv[b * N_ + j0 + jl0 + 8];
#pragma unroll
        for (int ng = 0; ng < 8; ++ng) {
            int d = d0 + dw * 64 + ng * 8 + (lane & 3) * 2;
            size_t ro = ((size_t)(b * N_ + j0 + jl0)) * C + d;
            uint32_t hw, lw;
            split2(acc[mg][ng][0] * dv0, acc[mg][ng][1] * dv0, hw, lw);
            *reinterpret_cast<uint32_t*>(g_agg_hi + ro) = hw;
            *reinterpret_cast<uint32_t*>(g_agg_lo + ro) = lw;
            split2(acc[mg][ng][2] * dv1, acc[mg][ng][3] * dv1, hw, lw);
            *reinterpret_cast<uint32_t*>(g_agg_hi + ro + (size_t)8 * C) = hw;
            *reinterpret_cast<uint32_t*>(g_agg_lo + ro + (size_t)8 * C) = lw;
        }
    }
}

// ---------------------------------------------------------------------------
// Dense1: per-64K-chunk {A_hi, A_lo, W_hi, W_lo}; 3 MMA combos; 4 stages.
// Epilogue: h row-major bf16 hi/lo + h^T fp16 single.
// ---------------------------------------------------------------------------
__global__ __launch_bounds__(256, 2)
void dense1_mma_kernel(const float* __restrict__ b1) {
    extern __shared__ __align__(1024) char smem[];
    constexpr int STG = 49152;  // Ah 8K | Al 8K | Bh 16K | Bl 16K
    const int tid = threadIdx.x, lane = tid & 31, wid = tid >> 5;
    const int mw = wid & 1, nw = wid >> 1;
    const int r0 = blockIdx.x * 64, c0 = blockIdx.y * 128;
    const int b = r0 >> 11, i0 = r0 & (N_ - 1);
    const uint32_t sb = smem_u32(smem);

    float acc[2][4][4];
#pragma unroll
    for (int mg = 0; mg < 2; ++mg)
#pragma unroll
        for (int nq = 0; nq < 4; ++nq)
#pragma unroll
            for (int q = 0; q < 4; ++q) acc[mg][nq][q] = 0.0f;

    auto load_stage = [&](int st, int sidx) {
        const int part = sidx >> 1, kb = (sidx & 1) * 64;
        const __nv_bfloat16* Ah = part ? g_x_hi : g_agg_hi;
        const __nv_bfloat16* Al = part ? g_x_lo : g_agg_lo;
        const __nv_bfloat16* Bh = g_W1t_hi + part * HIDC * INC;
        const __nv_bfloat16* Bl = g_W1t_lo + part * HIDC * INC;
#pragma unroll
        for (int p = 0; p < 4; ++p) {
            int idx = tid + p * 256;
            int r = idx >> 3, c = idx & 7;
            int hl = r >> 6, row = r & 63;
            cpa16(sb + st * STG + hl * 8192 + SWZ((uint32_t)(row * 128 + c * 16)),
                  (hl ? Al : Ah) + (size_t)(r0 + row) * INC + kb + c * 8);
        }
#pragma unroll
        for (int p = 0; p < 8; ++p) {
            int idx = tid + p * 256;
            int r = idx >> 3, c = idx & 7;
            int hl = r >> 7, row = r & 127;
            cpa16(sb + st * STG + 16384 + hl * 16384 +
                      SWZ((uint32_t)(row * 128 + c * 16)),
                  (hl ? Bl : Bh) + (size_t)(c0 + row) * INC + kb + c * 8);
        }
        asm volatile("cp.async.commit_group;");
    };

    load_stage(0, 0);

#pragma unroll 1
    for (int s = 0; s < 4; ++s) {
        const int cur = s & 1;
        if (s + 1 < 4) {
            load_stage(cur ^ 1, s + 1);
            asm volatile("cp.async.wait_group 1;");
        } else {
            asm volatile("cp.async.wait_group 0;");
        }
        __syncthreads();

        const uint32_t ahb = sb + cur * STG;
        const uint32_t alb = ahb + 8192;
        const uint32_t bhb = ahb + 16384;
        const uint32_t blb = ahb + 32768;
#pragma unroll
        for (int kk = 0; kk < 4; ++kk) {
            uint32_t ah[2][4], al[2][4];
#pragma unroll
            for (int mg = 0; mg < 2; ++mg) {
                uint32_t off = SWZ((uint32_t)(
                    (mw * 32 + mg * 16 + (lane & 15)) * 128 +
                    kk * 32 + (lane >> 4) * 16));
                ldsm4(ah[mg], ahb + off);
                ldsm4(al[mg], alb + off);
            }
            uint32_t bh[2][4], bl[2][4];
#pragma unroll
            for (int ng = 0; ng < 2; ++ng) {
                int rowB = nw * 32 + ng * 16 + (lane & 7) + ((lane >> 4) << 3);
                uint32_t off = SWZ((uint32_t)(
                    rowB * 128 + kk * 32 + ((lane >> 3) & 1) * 16));
                ldsm4(bh[ng], bhb + off);
                ldsm4(bl[ng], blb + off);
            }
#pragma unroll
            for (int mg = 0; mg < 2; ++mg)
#pragma unroll
                for (int ng = 0; ng < 2; ++ng)
#pragma unroll
                    for (int sub = 0; sub < 2; ++sub) {
                        float* c = acc[mg][ng * 2 + sub];
                        mma_bf16(c, ah[mg], bh[ng][sub * 2], bh[ng][sub * 2 + 1]);
                        mma_bf16(c, al[mg], bh[ng][sub * 2], bh[ng][sub * 2 + 1]);
                        mma_bf16(c, ah[mg], bl[ng][sub * 2], bl[ng][sub * 2 + 1]);
                    }
        }
        __syncthreads();
    }

#pragma unroll
    for (int mg = 0; mg < 2; ++mg) {
#pragma unroll
        for (int nq = 0; nq < 4; ++nq) {
            int dloc = nw * 32 + nq * 8 + (lane & 3) * 2;
            float2 bv = *reinterpret_cast<const float2*>(b1 + c0 + dloc);
            acc[mg][nq][0] = fmaxf(acc[mg][nq][0] + bv.x, 0.0f);
            acc[mg][nq][1] = fmaxf(acc[mg][nq][1] + bv.y, 0.0f);
            acc[mg][nq][2] = fmaxf(acc[mg][nq][2] + bv.x, 0.0f);
            acc[mg][nq][3] = fmaxf(acc[mg][nq][3] + bv.y, 0.0f);
            size_t ro = ((size_t)(r0 + mw * 32 + mg * 16 + (lane >> 2))) * HIDC +
                        c0 + dloc;
            uint32_t hw, lw;
            split2(acc[mg][nq][0], acc[mg][nq][1], hw, lw);
            *reinterpret_cast<uint32_t*>(g_h_hi + ro) = hw;
            *reinterpret_cast<uint32_t*>(g_h_lo + ro) = lw;
            split2(acc[mg][nq][2], acc[mg][nq][3], hw, lw);
            *reinterpret_cast<uint32_t*>(g_h_hi + ro + (size_t)8 * HIDC) = hw;
            *reinterpret_cast<uint32_t*>(g_h_lo + ro + (size_t)8 * HIDC) = lw;
        }
    }

    // single-pass transpose, fp16 single h^T
    float* sT = reinterpret_cast<float*>(smem);  // [64][129]
#pragma unroll
    for (int mg = 0; mg < 2; ++mg)
#pragma unroll
        for (int nq = 0; nq < 4; ++nq)
#pragma unroll
            for (int q = 0; q < 4; ++q) {
                int irow = mw * 32 + mg * 16 + (lane >> 2) + (q >> 1) * 8;
                int dl = nw * 32 + nq * 8 + (lane & 3) * 2 + (q & 1);
                sT[irow * 129 + dl] = acc[mg][nq][q];
            }
    __syncthreads();

    const int dl = tid & 127, iq = (tid >> 7) * 32;
    uint32_t hb[16];
#pragma unroll
    for (int q = 0; q < 16; ++q) {
        __half2 hp = __floats2half2_rn(sT[(iq + q * 2) * 129 + dl],
                                       sT[(iq + q * 2 + 1) * 129 + dl]);
        hb[q] = *reinterpret_cast<uint32_t*>(&hp);
    }
    size_t ob = ((size_t)(b * HIDC + c0 + dl)) * N_ + i0 + iq;
#pragma unroll
    for (int q = 0; q < 4; ++q)
        reinterpret_cast<uint4*>(g_T16 + ob)[q] =
            make_uint4(hb[q * 4], hb[q * 4 + 1], hb[q * 4 + 2], hb[q * 4 + 3]);
}

// ---------------------------------------------------------------------------
// Dense2: per-chunk {A_hi, A_lo, W_hi, W_lo} with 3 combos; 8 stages.
// ---------------------------------------------------------------------------
__global__ __launch_bounds__(256, 2)
void dense2_mma_kernel(const float* __restrict__ b2, float* __restrict__ out,
                       int write_raw) {
    extern __shared__ __align__(1024) char smem[];
    constexpr int STG = 40960;  // Ah 16K | Al 16K | Bh 4K | Bl 4K
    const int tid = threadIdx.x, lane = tid & 31, wid = tid >> 5;
    const int r0 = blockIdx.x * 128;
    const uint32_t sb = smem_u32(smem);

    float acc[4][4];
#pragma unroll
    for (int t = 0; t < 4; ++t)
#pragma unroll
        for (int q = 0; q < 4; ++q) acc[t][q] = 0.0f;

    auto load_stage = [&](int st, int sidx) {
        const int part = sidx >> 2, kb = (sidx & 3) * 64;
        const __nv_bfloat16* Ah = part ? g_h_hi : g_agg_hi;
        const __nv_bfloat16* Al = part ? g_h_lo : g_agg_lo;
        const __nv_bfloat16* Bh = g_W2t_hi + part * OUTC * HIDC;
        const __nv_bfloat16* Bl = g_W2t_lo + part * OUTC * HIDC;
#pragma unroll
        for (int p = 0; p < 8; ++p) {
            int idx = tid + p * 256;
            int r = idx >> 3, c = idx & 7;
            int hl = r >> 7, row = r & 127;
            cpa16(sb + st * STG + hl * 16384 + SWZ((uint32_t)(row * 128 + c * 16)),
                  (hl ? Al : Ah) + (size_t)(r0 + row) * HIDC + kb + c * 8);
        }
#pragma unroll
        for (int p = 0; p < 2; ++p) {
            int idx = tid + p * 256;
            int r = idx >> 3, c = idx & 7;
            int hl = r >> 5, row = r & 31;
            cpa16(sb + st * STG + 32768 + hl * 4096 +
                      SWZ((uint32_t)(row * 128 + c * 16)),
                  (hl ? Bl : Bh) + (size_t)row * HIDC + kb + c * 8);
        }
        asm volatile("cp.async.commit_group;");
    };

    load_stage(0, 0);

#pragma unroll 1
    for (int s = 0; s < 8; ++s) {
        const int cur = s & 1;
        if (s + 1 < 8) {
            load_stage(cur ^ 1, s + 1);
            asm volatile("cp.async.wait_group 1;");
        } else {
            asm volatile("cp.async.wait_group 0;");
        }
        __syncthreads();

        const uint32_t ahb = sb + cur * STG;
        const uint32_t alb = ahb + 16384;
        const uint32_t bhb = ahb + 32768;
        const uint32_t blb = ahb + 36864;
#pragma unroll
        for (int kk = 0; kk < 4; ++kk) {
            uint32_t ah[4], al[4];
            {
                uint32_t off = SWZ((uint32_t)(
                    (wid * 16 + (lane & 15)) * 128 + kk * 32 + (lane >> 4) * 16));
                ldsm4(ah, ahb + off);
                ldsm4(al, alb + off);
            }
            uint32_t bh[2][4], bl[2][4];
#pragma unroll
            for (int ng = 0; ng < 2; ++ng) {
                int rowB = ng * 16 + (lane & 7) + ((lane >> 4) << 3);
                uint32_t off = SWZ((uint32_t)(
                    rowB * 128 + kk * 32 + ((lane >> 3) & 1) * 16));
                ldsm4(bh[ng], bhb + off);
                ldsm4(bl[ng], blb + off);
            }
#pragma unroll
            for (int ng = 0; ng < 2; ++ng)
#pragma unroll
                for (int sub = 0; sub < 2; ++sub) {
                    float* c = acc[ng * 2 + sub];
                    mma_bf16(c, ah, bh[ng][sub * 2], bh[ng][sub * 2 + 1]);
                    mma_bf16(c, al, bh[ng][sub * 2], bh[ng][sub * 2 + 1]);
                    mma_bf16(c, ah, bl[ng][sub * 2], bl[ng][sub * 2 + 1]);
                }
        }
        __syncthreads();
    }

    float* sOut = reinterpret_cast<float*>(smem);
    __syncthreads();
#pragma unroll
    for (int t = 0; t < 4; ++t) {
        int d = t * 8 + (lane & 3) * 2;
        float2 bv = *reinterpret_cast<const float2*>(b2 + d);
        int row = wid * 16 + (lane >> 2);
        sOut[row * 33 + d] = acc[t][0] + bv.x;
        sOut[row * 33 + d + 1] = acc[t][1] + bv.y;
        sOut[(row + 8) * 33 + d] = acc[t][2] + bv.x;
        sOut[(row + 8) * 33 + d + 1] = acc[t][3] + bv.y;
    }
    __syncthreads();

#pragma unroll 1
    for (int rit = 0; rit < 16; ++rit) {
        int row = rit * 8 + wid;
        float v = sOut[row * 33 + lane];
        float m = v;
#pragma unroll
        for (int o = 16; o > 0; o >>= 1)
            m = fmaxf(m, __shfl_xor_sync(0xffffffffu, m, o));
        float s = expf(v - m);
#pragma unroll
        for (int o = 16; o > 0; o >>= 1)
            s += __shfl_xor_sync(0xffffffffu, s, o);
        float lsm = v - m - logf(s);
        size_t gi = (size_t)(r0 + row) * OUTC + lane;
        out[gi] = lsm;
        if (write_raw) out[(size_t)BN * OUTC + gi] = v;
    }
}

// ---------------------------------------------------------------------------
extern "C" void kernel_launch(void* const* d_in, const int* in_sizes, int n_in,
                              void* d_out, int out_size) {
    const float* x   = (const float*)d_in[0];
    const int*   A   = (const int*)d_in[1];
    const float* W1l = (const float*)d_in[2];
    const float* W1r = (const float*)d_in[3];
    const float* b1  = (const float*)d_in[4];
    const float* W2l = (const float*)d_in[5];
    const float* W2r = (const float*)d_in[6];
    const float* b2  = (const float*)d_in[7];
    float* out = (float*)d_out;
    (void)in_sizes; (void)n_in;

    const int write_raw = (out_size >= 2 * BN * OUTC) ? 1 : 0;

    constexpr int AGG1_SMEM = 3 * 24576 + 256;  // 73984
    constexpr int AGG2_SMEM = 3 * 32768;        // 98304
    constexpr int D1_SMEM = 2 * 49152;          // 98304
    constexpr int D2_SMEM = 2 * 40960;          // 81920
    cudaFuncSetAttribute(agg1_kernel,
                         cudaFuncAttributeMaxDynamicSharedMemorySize, AGG1_SMEM);
    cudaFuncSetAttribute(agg2_kernel,
                         cudaFuncAttributeMaxDynamicSharedMemorySize, AGG2_SMEM);
    cudaFuncSetAttribute(dense1_mma_kernel,
                         cudaFuncAttributeMaxDynamicSharedMemorySize, D1_SMEM);
    cudaFuncSetAttribute(dense2_mma_kernel,
                         cudaFuncAttributeMaxDynamicSharedMemorySize, D2_SMEM);

    prep_kernel<<<dim3(N_ / 64, INC / 64, B_ + 1), 256>>>(x, W1l, W1r, W2l, W2r);
    agg1_kernel<<<dim3(N_ / 64, 1, B_), 256, AGG1_SMEM>>>(A);
    dense1_mma_kernel<<<dim3(BN / 64, HIDC / 128), 256, D1_SMEM>>>(b1);
    agg2_kernel<<<dim3(N_ / 128, HIDC / 128, B_), 256, AGG2_SMEM>>>();
    dense2_mma_kernel<<<BN / 128, 256, D2_SMEM>>>(b2, out, write_raw);
}

// round 12
// speedup vs baseline: 1.9257x; 1.0027x over previous
#include <cuda_runtime.h>
#include <cuda_bf16.h>
#include <cuda_fp16.h>
#include <cstdint>
#include <cstddef>

// Problem constants
constexpr int B_ = 8;
constexpr int N_ = 2048;
constexpr int INC = 128;
constexpr int HIDC = 256;
constexpr int OUTC = 32;
constexpr int BN = B_ * N_;

// Scratch (device globals: no allocation allowed)
__device__ __align__(16) float g_deg_inv[BN];
__device__ __align__(16) __nv_bfloat16 g_agg_hi[(size_t)BN * HIDC];  // row-major
__device__ __align__(16) __nv_bfloat16 g_agg_lo[(size_t)BN * HIDC];
__device__ __align__(16) __nv_bfloat16 g_h_hi[(size_t)BN * HIDC];    // row-major
__device__ __align__(16) __nv_bfloat16 g_h_lo[(size_t)BN * HIDC];
__device__ __align__(16) __nv_bfloat16 g_x_hi[(size_t)BN * INC];     // row-major
__device__ __align__(16) __nv_bfloat16 g_x_lo[(size_t)BN * INC];
// layer1: x^T fp16 single; layer2: reused as h^T fp16 single  [b][d][i]
__device__ __align__(16) __half g_T16[(size_t)B_ * HIDC * N_];
// Bit-packed mask: [b][it(32)][j(2048)][iq(4)] uint16 (i = it*64 + iq*16 .. +15)
__device__ __align__(16) uint16_t g_Mbits[(size_t)B_ * 32 * N_ * 4];
__device__ __align__(16) __nv_bfloat16 g_W1t_hi[2 * HIDC * INC];   // [mtx][n][k]
__device__ __align__(16) __nv_bfloat16 g_W1t_lo[2 * HIDC * INC];
__device__ __align__(16) __nv_bfloat16 g_W2t_hi[2 * OUTC * HIDC];
__device__ __align__(16) __nv_bfloat16 g_W2t_lo[2 * OUTC * HIDC];

#define SWZ(off) ((off) ^ (((off) >> 3) & 0x70))

__device__ __forceinline__ uint32_t smem_u32(const void* p) {
    uint32_t a;
    asm("{ .reg .u64 t; cvta.to.shared.u64 t, %1; cvt.u32.u64 %0, t; }"
        : "=r"(a) : "l"(p));
    return a;
}
__device__ __forceinline__ void cpa16(uint32_t dst, const void* src) {
    asm volatile("cp.async.cg.shared.global [%0], [%1], 16;" :: "r"(dst), "l"(src));
}
__device__ __forceinline__ void ldsm4(uint32_t* r, uint32_t addr) {
    asm volatile("ldmatrix.sync.aligned.m8n8.x4.shared.b16 {%0,%1,%2,%3}, [%4];"
                 : "=r"(r[0]), "=r"(r[1]), "=r"(r[2]), "=r"(r[3]) : "r"(addr));
}
__device__ __forceinline__ void mma_bf16(float* c, const uint32_t* a,
                                         uint32_t b0, uint32_t b1) {
    asm volatile(
        "mma.sync.aligned.m16n8k16.row.col.f32.bf16.bf16.f32 "
        "{%0,%1,%2,%3}, {%4,%5,%6,%7}, {%8,%9}, {%0,%1,%2,%3};"
        : "+f"(c[0]), "+f"(c[1]), "+f"(c[2]), "+f"(c[3])
        : "r"(a[0]), "r"(a[1]), "r"(a[2]), "r"(a[3]), "r"(b0), "r"(b1));
}
__device__ __forceinline__ void mma_f16(float* c, const uint32_t* a,
                                        uint32_t b0, uint32_t b1) {
    asm volatile(
        "mma.sync.aligned.m16n8k16.row.col.f32.f16.f16.f32 "
        "{%0,%1,%2,%3}, {%4,%5,%6,%7}, {%8,%9}, {%0,%1,%2,%3};"
        : "+f"(c[0]), "+f"(c[1]), "+f"(c[2]), "+f"(c[3])
        : "r"(a[0]), "r"(a[1]), "r"(a[2]), "r"(a[3]), "r"(b0), "r"(b1));
}
__device__ __forceinline__ void split2(float v0, float v1, uint32_t& hw, uint32_t& lw) {
    __nv_bfloat16 h0 = __float2bfloat16(v0);
    __nv_bfloat16 h1 = __float2bfloat16(v1);
    __nv_bfloat16 l0 = __float2bfloat16(v0 - __bfloat162float(h0));
    __nv_bfloat16 l1 = __float2bfloat16(v1 - __bfloat162float(h1));
    __nv_bfloat162 hp; hp.x = h0; hp.y = h1;
    __nv_bfloat162 lp; lp.x = l0; lp.y = l1;
    hw = *reinterpret_cast<uint32_t*>(&hp);
    lw = *reinterpret_cast<uint32_t*>(&lp);
}
// Expand low 8 bits of w into 4 fp16x2 words ({0,1} values)
__device__ __forceinline__ uint4 expand8(uint32_t w) {
    uint4 r;
    r.x = ((w >> 0) & 1u) * 0x3C00u | ((w >> 1) & 1u) * 0x3C000000u;
    r.y = ((w >> 2) & 1u) * 0x3C00u | ((w >> 3) & 1u) * 0x3C000000u;
    r.z = ((w >> 4) & 1u) * 0x3C00u | ((w >> 5) & 1u) * 0x3C000000u;
    r.w = ((w >> 6) & 1u) * 0x3C00u | ((w >> 7) & 1u) * 0x3C000000u;
    return r;
}

// ---------------------------------------------------------------------------
// Merged prep: z < 8: x transpose->fp16 + row-major bf16 hi/lo; z == 8: weights.
// ---------------------------------------------------------------------------
__global__ __launch_bounds__(256)
void prep_kernel(const float* __restrict__ src,
                 const float* __restrict__ W1l, const float* __restrict__ W1r,
                 const float* __restrict__ W2l, const float* __restrict__ W2r) {
    constexpr int C = INC;
    if (blockIdx.z == 8) {
        int base = (blockIdx.x * 2 + blockIdx.y) * 256 + threadIdx.x;
#pragma unroll 1
        for (int idx = base; idx < 2 * HIDC * INC + 2 * OUTC * HIDC; idx += 16384) {
            float v;
            __nv_bfloat16 *hi, *lo;
            int off;
            if (idx < 2 * HIDC * INC) {
                int mtx = idx >> 15, rem = idx & 32767;
                int n = rem >> 7, k = rem & 127;
                v = (mtx ? W1r : W1l)[k * HIDC + n];
                hi = g_W1t_hi; lo = g_W1t_lo; off = idx;
            } else {
                int j = idx - 2 * HIDC * INC;
                int mtx = j >> 13, rem = j & 8191;
                int n = rem >> 8, k = rem & 255;
                v = (mtx ? W2r : W2l)[k * OUTC + n];
                hi = g_W2t_hi; lo = g_W2t_lo; off = j;
            }
            __nv_bfloat16 h = __float2bfloat16(v);
            hi[off] = h;
            lo[off] = __float2bfloat16(v - __bfloat162float(h));
        }
        return;
    }

    __shared__ float sT[64][65];
    const int t = threadIdx.x;
    const int b = blockIdx.z, i0 = blockIdx.x * 64, d0 = blockIdx.y * 64;

#pragma unroll
    for (int p = 0; p < 4; ++p) {
        int e = t + p * 256;
        int row = e >> 4, c4 = e & 15;
        size_t goff = ((size_t)(b * N_ + i0 + row)) * C + d0 + c4 * 4;
        float4 v = *reinterpret_cast<const float4*>(src + goff);
        sT[row][c4 * 4 + 0] = v.x; sT[row][c4 * 4 + 1] = v.y;
        sT[row][c4 * 4 + 2] = v.z; sT[row][c4 * 4 + 3] = v.w;
        uint32_t h0, l0, h1, l1;
        split2(v.x, v.y, h0, l0);
        split2(v.z, v.w, h1, l1);
        *reinterpret_cast<uint2*>(g_x_hi + goff) = make_uint2(h0, h1);
        *reinterpret_cast<uint2*>(g_x_lo + goff) = make_uint2(l0, l1);
    }
    __syncthreads();

    const int d = t >> 2, ic = (t & 3) * 16;
    uint32_t hb[8];
#pragma unroll
    for (int q = 0; q < 8; ++q) {
        __half2 hp = __floats2half2_rn(sT[ic + q * 2][d], sT[ic + q * 2 + 1][d]);
        hb[q] = *reinterpret_cast<uint32_t*>(&hp);
    }
    size_t obase = ((size_t)(b * C + d0 + d)) * N_ + i0 + ic;
    reinterpret_cast<uint4*>(g_T16 + obase)[0] = make_uint4(hb[0], hb[1], hb[2], hb[3]);
    reinterpret_cast<uint4*>(g_T16 + obase)[1] = make_uint4(hb[4], hb[5], hb[6], hb[7]);
}

// ---------------------------------------------------------------------------
// agg1: reads A, converts mask in-pipeline (fp16 + packed bits + degree),
// fp16 single-term MMA with x^T. CTA 64j x 128d; 3-stage pipeline.
// ---------------------------------------------------------------------------
__global__ __launch_bounds__(256, 2)
void agg1_kernel(const int* __restrict__ A) {
    extern __shared__ __align__(1024) char smem[];
    constexpr int C = INC;
    constexpr int NIT = N_ / 64;
    constexpr int STG = 24576;  // mask 8 KB | X 16 KB
    const int tid = threadIdx.x, lane = tid & 31, wid = tid >> 5;
    const int b = blockIdx.z, jt = blockIdx.x, j0 = jt * 64;
    const int jw = wid & 1, dw = wid >> 1;
    const uint32_t sb = smem_u32(smem);
    float* sdeg = reinterpret_cast<float*>(smem + 3 * STG);

    if (tid < 64) sdeg[tid] = 0.0f;

    float acc[2][4][4];
#pragma unroll
    for (int mg = 0; mg < 2; ++mg)
#pragma unroll
        for (int ng = 0; ng < 4; ++ng)
#pragma unroll
            for (int q = 0; q < 4; ++q) acc[mg][ng][q] = 0.0f;

    const int jj = tid & 63, iq = tid >> 6;  // iq: 16 i's each
    const int* Ap = A + (size_t)b * N_ * N_ + j0 + jj;
    float degloc = 0.0f;

    auto fill = [&](int stage, int it) {
        const int i0 = it * 64;
        // mask: LDG A (coalesced over j), fp16 to smem + packed bits to gmem
        {
            char* mb = smem + stage * STG;
            uint32_t bits = 0;
#pragma unroll
            for (int r = 0; r < 8; ++r) {
                int il = iq * 16 + r * 2;
                uint32_t b0 = Ap[(size_t)(i0 + il) * N_] ? 1u : 0u;
                uint32_t b1 = Ap[(size_t)(i0 + il + 1) * N_] ? 1u : 0u;
                bits |= (b0 << (r * 2)) | (b1 << (r * 2 + 1));
                degloc += (float)(b0 + b1);
                uint32_t mv = b0 * 0x3C00u | b1 * 0x3C000000u;
                *reinterpret_cast<uint32_t*>(
                    mb + SWZ((uint32_t)(jj * 128 + il * 2))) = mv;
            }
            // layout: [b][it][j][iq]
            g_Mbits[(((size_t)(b * 32 + it)) * N_ + j0 + jj) * 4 + iq] =
                (uint16_t)bits;
        }
        // X fp16: 128d x 64i
#pragma unroll
        for (int p = 0; p < 4; ++p) {
            int idx = tid + p * 256;
            int row = idx >> 3, c = idx & 7;
            cpa16(sb + stage * STG + 8192 + SWZ((uint32_t)(row * 128 + c * 16)),
                  g_T16 + ((size_t)(b * C + row)) * N_ + i0 + c * 8);
        }
        asm volatile("cp.async.commit_group;");
    };

    fill(0, 0);
    fill(1, 1);

#pragma unroll 1
    for (int it = 0; it < NIT; ++it) {
        const int cur = it % 3;
        if (it + 2 < NIT) {
            fill((it + 2) % 3, it + 2);
            asm volatile("cp.async.wait_group 2;");
        } else if (it + 1 < NIT) {
            asm volatile("cp.async.wait_group 1;");
        } else {
            asm volatile("cp.async.wait_group 0;");
        }
        __syncthreads();

        const uint32_t mbase = sb + cur * STG;
        const uint32_t xbase = mbase + 8192;
#pragma unroll
        for (int kk = 0; kk < 4; ++kk) {
            uint32_t a[2][4];
#pragma unroll
            for (int mg = 0; mg < 2; ++mg) {
                uint32_t addr = mbase + SWZ((uint32_t)(
                    (jw * 32 + mg * 16 + (lane & 15)) * 128 +
                    kk * 32 + (lane >> 4) * 16));
                ldsm4(a[mg], addr);
            }
            uint32_t bf[2][4];
#pragma unroll
            for (int ng = 0; ng < 2; ++ng) {
                int rowB = dw * 32 + ng * 16 + (lane & 7) + ((lane >> 4) << 3);
                uint32_t addr = xbase + SWZ((uint32_t)(
                    rowB * 128 + kk * 32 + ((lane >> 3) & 1) * 16));
                ldsm4(bf[ng], addr);
            }
#pragma unroll
            for (int mg = 0; mg < 2; ++mg)
#pragma unroll
                for (int ng = 0; ng < 2; ++ng)
#pragma unroll
                    for (int sub = 0; sub < 2; ++sub)
                        mma_f16(acc[mg][ng * 2 + sub], a[mg],
                                bf[ng][sub * 2], bf[ng][sub * 2 + 1]);
        }
        __syncthreads();
    }

    atomicAdd(&sdeg[jj], degloc);
    __syncthreads();
    if (tid < 64) {
        float dinv = 1.0f / fmaxf(sdeg[tid], 1.0f);
        g_deg_inv[b * N_ + j0 + tid] = dinv;
        sdeg[tid] = dinv;
    }
    __syncthreads();

#pragma unroll
    for (int mg = 0; mg < 2; ++mg) {
        int jl0 = jw * 32 + mg * 16 + (lane >> 2);
        float dv0 = sdeg[jl0], dv1 = sdeg[jl0 + 8];
#pragma unroll
        for (int ng = 0; ng < 4; ++ng) {
            int d = dw * 32 + ng * 8 + (lane & 3) * 2;
            size_t ro = ((size_t)(b * N_ + j0 + jl0)) * C + d;
            uint32_t hw, lw;
            split2(acc[mg][ng][0] * dv0, acc[mg][ng][1] * dv0, hw, lw);
            *reinterpret_cast<uint32_t*>(g_agg_hi + ro) = hw;
            *reinterpret_cast<uint32_t*>(g_agg_lo + ro) = lw;
            split2(acc[mg][ng][2] * dv1, acc[mg][ng][3] * dv1, hw, lw);
            *reinterpret_cast<uint32_t*>(g_agg_hi + ro + (size_t)8 * C) = hw;
            *reinterpret_cast<uint32_t*>(g_agg_lo + ro + (size_t)8 * C) = lw;
        }
    }
}

// ---------------------------------------------------------------------------
// agg2 v3 (race-fixed): CTA-resident bit mask (32 KB, preloaded once);
// expansion off critical path; X re-issue moved AFTER the trailing sync.
// CTA 128j x 128d; fp16 single-term with h^T fp16.
// smem: [0,32K) bits [it(32)][j(128)][8B]; [32K,+32K) X bufs; [64K,+32K) mask bufs
// ---------------------------------------------------------------------------
__global__ __launch_bounds__(256, 2)
void agg2_kernel() {
    extern __shared__ __align__(1024) char smem[];
    constexpr int C = HIDC;
    constexpr int NIT = N_ / 64;
    constexpr uint32_t XOFF = 32768, MOFF = 65536;
    const int tid = threadIdx.x, lane = tid & 31, wid = tid >> 5;
    const int b = blockIdx.z, j0 = blockIdx.x * 128;
    const int d0 = blockIdx.y * 128;
    const int jw = wid & 3, dw = wid >> 2;
    const uint32_t sb = smem_u32(smem);

    float acc[2][8][4];
#pragma unroll
    for (int mg = 0; mg < 2; ++mg)
#pragma unroll
        for (int ng = 0; ng < 8; ++ng)
#pragma unroll
            for (int q = 0; q < 4; ++q) acc[mg][ng][q] = 0.0f;

    const int jj = tid & 127, iq2 = tid >> 7;  // iq2: 32 i's per thread

    // ---- preload CTA's bit mask: 32 its x 128 j x 8 B = 32 KB ----
    {
        const char* Mb = reinterpret_cast<const char*>(g_Mbits) +
                         ((size_t)(b * 32) * N_ + j0) * 8;
#pragma unroll
        for (int p = 0; p < 8; ++p) {
            int idx = tid + p * 256;       // 2048 chunks of 16 B
            int it = idx >> 6, c = idx & 63;
            cpa16(sb + it * 1024 + c * 16, Mb + (size_t)it * (N_ * 8) + c * 16);
        }
        asm volatile("cp.async.commit_group;");
    }

    auto issueX = [&](int stage, int it) {
        const int i0 = it * 64;
#pragma unroll
        for (int p = 0; p < 4; ++p) {
            int idx = tid + p * 256;
            int row = idx >> 3, c = idx & 7;
            cpa16(sb + XOFF + stage * 16384 + SWZ((uint32_t)(row * 128 + c * 16)),
                  g_T16 + ((size_t)(b * C + d0 + row)) * N_ + i0 + c * 8);
        }
        asm volatile("cp.async.commit_group;");
    };
    auto expand = [&](int it) {
        uint32_t w = *reinterpret_cast<const uint32_t*>(
            smem + it * 1024 + jj * 8 + iq2 * 4);
        char* mb = smem + MOFF + (it & 1) * 16384;
#pragma unroll
        for (int p = 0; p < 4; ++p) {
            uint4 v = expand8(w >> (p * 8));
            *reinterpret_cast<uint4*>(
                mb + SWZ((uint32_t)(jj * 128 + iq2 * 64 + p * 16))) = v;
        }
    };

    issueX(0, 0);                               // groups: bits, X0
    asm volatile("cp.async.wait_group 1;");     // bits arrived
    __syncthreads();
    expand(0);
    issueX(1, 1);

#pragma unroll 1
    for (int it = 0; it < NIT; ++it) {
        if (it + 1 < NIT) {
            asm volatile("cp.async.wait_group 1;");
        } else {
            asm volatile("cp.async.wait_group 0;");
        }
        __syncthreads();   // X(it) + mask(it) ready; prev compute done

        if (it + 1 < NIT) expand(it + 1);  // overlaps with MMA below

        const uint32_t mbase = sb + MOFF + (it & 1) * 16384;
        const uint32_t xbase = sb + XOFF + (it & 1) * 16384;
#pragma unroll
        for (int kk = 0; kk < 4; ++kk) {
            uint32_t a[2][4];
#pragma unroll
            for (int mg = 0; mg < 2; ++mg) {
                int row = jw * 32 + mg * 16 + (lane & 15);
                uint32_t addr = mbase + SWZ((uint32_t)(
                    row * 128 + kk * 32 + (lane >> 4) * 16));
                ldsm4(a[mg], addr);
            }
            uint32_t bf[4][4];
#pragma unroll
            for (int ng = 0; ng < 4; ++ng) {
                int rowB = dw * 64 + ng * 16 + (lane & 7) + ((lane >> 4) << 3);
                uint32_t addr = xbase + SWZ((uint32_t)(
                    rowB * 128 + kk * 32 + ((lane >> 3) & 1) * 16));
                ldsm4(bf[ng], addr);
            }
#pragma unroll
            for (int mg = 0; mg < 2; ++mg)
#pragma unroll
                for (int ng = 0; ng < 4; ++ng)
#pragma unroll
                    for (int sub = 0; sub < 2; ++sub)
                        mma_f16(acc[mg][ng * 2 + sub], a[mg],
                                bf[ng][sub * 2], bf[ng][sub * 2 + 1]);
        }
        __syncthreads();   // all reads of X buf (it&1) complete
        if (it + 2 < NIT) issueX((it + 2) & 1, it + 2);  // safe: after sync
    }

#pragma unroll
    for (int mg = 0; mg < 2; ++mg) {
        int jl0 = jw * 32 + mg * 16 + (lane >> 2);
        float dv0 = g_deg_inv[b * N_ + j0 + jl0];
        float dv1 = g_deg_inv[b * N_ + j0 + jl0 + 8];
#pragma unroll
        for (int ng = 0; ng < 8; ++ng) {
            int d = d0 + dw * 64 + ng * 8 + (lane & 3) * 2;
            size_t ro = ((size_t)(b * N_ + j0 + jl0)) * C + d;
            uint32_t hw, lw;
            split2(acc[mg][ng][0] * dv0, acc[mg][ng][1] * dv0, hw, lw);
            *reinterpret_cast<uint32_t*>(g_agg_hi + ro) = hw;
            *reinterpret_cast<uint32_t*>(g_agg_lo + ro) = lw;
            split2(acc[mg][ng][2] * dv1, acc[mg][ng][3] * dv1, hw, lw);
            *reinterpret_cast<uint32_t*>(g_agg_hi + ro + (size_t)8 * C) = hw;
            *reinterpret_cast<uint32_t*>(g_agg_lo + ro + (size_t)8 * C) = lw;
        }
    }
}

// ---------------------------------------------------------------------------
// Dense1: per-64K-chunk {A_hi, A_lo, W_hi, W_lo}; 3 MMA combos; 4 stages.
// Epilogue: h row-major bf16 hi/lo + h^T fp16 single.
// ---------------------------------------------------------------------------
__global__ __launch_bounds__(256, 2)
void dense1_mma_kernel(const float* __restrict__ b1) {
    extern __shared__ __align__(1024) char smem[];
    constexpr int STG = 49152;  // Ah 8K | Al 8K | Bh 16K | Bl 16K
    const int tid = threadIdx.x, lane = tid & 31, wid = tid >> 5;
    const int mw = wid & 1, nw = wid >> 1;
    const int r0 = blockIdx.x * 64, c0 = blockIdx.y * 128;
    const int b = r0 >> 11, i0 = r0 & (N_ - 1);
    const uint32_t sb = smem_u32(smem);

    float acc[2][4][4];
#pragma unroll
    for (int mg = 0; mg < 2; ++mg)
#pragma unroll
        for (int nq = 0; nq < 4; ++nq)
#pragma unroll
            for (int q = 0; q < 4; ++q) acc[mg][nq][q] = 0.0f;

    auto load_stage = [&](int st, int sidx) {
        const int part = sidx >> 1, kb = (sidx & 1) * 64;
        const __nv_bfloat16* Ah = part ? g_x_hi : g_agg_hi;
        const __nv_bfloat16* Al = part ? g_x_lo : g_agg_lo;
        const __nv_bfloat16* Bh = g_W1t_hi + part * HIDC * INC;
        const __nv_bfloat16* Bl = g_W1t_lo + part * HIDC * INC;
#pragma unroll
        for (int p = 0; p < 4; ++p) {
            int idx = tid + p * 256;
            int r = idx >> 3, c = idx & 7;
            int hl = r >> 6, row = r & 63;
            cpa16(sb + st * STG + hl * 8192 + SWZ((uint32_t)(row * 128 + c * 16)),
                  (hl ? Al : Ah) + (size_t)(r0 + row) * INC + kb + c * 8);
        }
#pragma unroll
        for (int p = 0; p < 8; ++p) {
            int idx = tid + p * 256;
            int r = idx >> 3, c = idx & 7;
            int hl = r >> 7, row = r & 127;
            cpa16(sb + st * STG + 16384 + hl * 16384 +
                      SWZ((uint32_t)(row * 128 + c * 16)),
                  (hl ? Bl : Bh) + (size_t)(c0 + row) * INC + kb + c * 8);
        }
        asm volatile("cp.async.commit_group;");
    };

    load_stage(0, 0);

#pragma unroll 1
    for (int s = 0; s < 4; ++s) {
        const int cur = s & 1;
        if (s + 1 < 4) {
            load_stage(cur ^ 1, s + 1);
            asm volatile("cp.async.wait_group 1;");
        } else {
            asm volatile("cp.async.wait_group 0;");
        }
        __syncthreads();

        const uint32_t ahb = sb + cur * STG;
        const uint32_t alb = ahb + 8192;
        const uint32_t bhb = ahb + 16384;
        const uint32_t blb = ahb + 32768;
#pragma unroll
        for (int kk = 0; kk < 4; ++kk) {
            uint32_t ah[2][4], al[2][4];
#pragma unroll
            for (int mg = 0; mg < 2; ++mg) {
                uint32_t off = SWZ((uint32_t)(
                    (mw * 32 + mg * 16 + (lane & 15)) * 128 +
                    kk * 32 + (lane >> 4) * 16));
                ldsm4(ah[mg], ahb + off);
                ldsm4(al[mg], alb + off);
            }
            uint32_t bh[2][4], bl[2][4];
#pragma unroll
            for (int ng = 0; ng < 2; ++ng) {
                int rowB = nw * 32 + ng * 16 + (lane & 7) + ((lane >> 4) << 3);
                uint32_t off = SWZ((uint32_t)(
                    rowB * 128 + kk * 32 + ((lane >> 3) & 1) * 16));
                ldsm4(bh[ng], bhb + off);
                ldsm4(bl[ng], blb + off);
            }
#pragma unroll
            for (int mg = 0; mg < 2; ++mg)
#pragma unroll
                for (int ng = 0; ng < 2; ++ng)
#pragma unroll
                    for (int sub = 0; sub < 2; ++sub) {
                        float* c = acc[mg][ng * 2 + sub];
                        mma_bf16(c, ah[mg], bh[ng][sub * 2], bh[ng][sub * 2 + 1]);
                        mma_bf16(c, al[mg], bh[ng][sub * 2], bh[ng][sub * 2 + 1]);
                        mma_bf16(c, ah[mg], bl[ng][sub * 2], bl[ng][sub * 2 + 1]);
                    }
        }
        __syncthreads();
    }

#pragma unroll
    for (int mg = 0; mg < 2; ++mg) {
#pragma unroll
        for (int nq = 0; nq < 4; ++nq) {
            int dloc = nw * 32 + nq * 8 + (lane & 3) * 2;
            float2 bv = *reinterpret_cast<const float2*>(b1 + c0 + dloc);
            acc[mg][nq][0] = fmaxf(acc[mg][nq][0] + bv.x, 0.0f);
            acc[mg][nq][1] = fmaxf(acc[mg][nq][1] + bv.y, 0.0f);
            acc[mg][nq][2] = fmaxf(acc[mg][nq][2] + bv.x, 0.0f);
            acc[mg][nq][3] = fmaxf(acc[mg][nq][3] + bv.y, 0.0f);
            size_t ro = ((size_t)(r0 + mw * 32 + mg * 16 + (lane >> 2))) * HIDC +
                        c0 + dloc;
            uint32_t hw, lw;
            split2(acc[mg][nq][0], acc[mg][nq][1], hw, lw);
            *reinterpret_cast<uint32_t*>(g_h_hi + ro) = hw;
            *reinterpret_cast<uint32_t*>(g_h_lo + ro) = lw;
            split2(acc[mg][nq][2], acc[mg][nq][3], hw, lw);
            *reinterpret_cast<uint32_t*>(g_h_hi + ro + (size_t)8 * HIDC) = hw;
            *reinterpret_cast<uint32_t*>(g_h_lo + ro + (size_t)8 * HIDC) = lw;
        }
    }

    // single-pass transpose, fp16 single h^T
    float* sT = reinterpret_cast<float*>(smem);  // [64][129]
#pragma unroll
    for (int mg = 0; mg < 2; ++mg)
#pragma unroll
        for (int nq = 0; nq < 4; ++nq)
#pragma unroll
            for (int q = 0; q < 4; ++q) {
                int irow = mw * 32 + mg * 16 + (lane >> 2) + (q >> 1) * 8;
                int dl = nw * 32 + nq * 8 + (lane & 3) * 2 + (q & 1);
                sT[irow * 129 + dl] = acc[mg][nq][q];
            }
    __syncthreads();

    const int dl = tid & 127, iq = (tid >> 7) * 32;
    uint32_t hb[16];
#pragma unroll
    for (int q = 0; q < 16; ++q) {
        __half2 hp = __floats2half2_rn(sT[(iq + q * 2) * 129 + dl],
                                       sT[(iq + q * 2 + 1) * 129 + dl]);
        hb[q] = *reinterpret_cast<uint32_t*>(&hp);
    }
    size_t ob = ((size_t)(b * HIDC + c0 + dl)) * N_ + i0 + iq;
#pragma unroll
    for (int q = 0; q < 4; ++q)
        reinterpret_cast<uint4*>(g_T16 + ob)[q] =
            make_uint4(hb[q * 4], hb[q * 4 + 1], hb[q * 4 + 2], hb[q * 4 + 3]);
}

// ---------------------------------------------------------------------------
// Dense2: per-chunk {A_hi, A_lo, W_hi, W_lo} with 3 combos; 8 stages.
// ---------------------------------------------------------------------------
__global__ __launch_bounds__(256, 2)
void dense2_mma_kernel(const float* __restrict__ b2, float* __restrict__ out,
                       int write_raw) {
    extern __shared__ __align__(1024) char smem[];
    constexpr int STG = 40960;  // Ah 16K | Al 16K | Bh 4K | Bl 4K
    const int tid = threadIdx.x, lane = tid & 31, wid = tid >> 5;
    const int r0 = blockIdx.x * 128;
    const uint32_t sb = smem_u32(smem);

    float acc[4][4];
#pragma unroll
    for (int t = 0; t < 4; ++t)
#pragma unroll
        for (int q = 0; q < 4; ++q) acc[t][q] = 0.0f;

    auto load_stage = [&](int st, int sidx) {
        const int part = sidx >> 2, kb = (sidx & 3) * 64;
        const __nv_bfloat16* Ah = part ? g_h_hi : g_agg_hi;
        const __nv_bfloat16* Al = part ? g_h_lo : g_agg_lo;
        const __nv_bfloat16* Bh = g_W2t_hi + part * OUTC * HIDC;
        const __nv_bfloat16* Bl = g_W2t_lo + part * OUTC * HIDC;
#pragma unroll
        for (int p = 0; p < 8; ++p) {
            int idx = tid + p * 256;
            int r = idx >> 3, c = idx & 7;
            int hl = r >> 7, row = r & 127;
            cpa16(sb + st * STG + hl * 16384 + SWZ((uint32_t)(row * 128 + c * 16)),
                  (hl ? Al : Ah) + (size_t)(r0 + row) * HIDC + kb + c * 8);
        }
#pragma unroll
        for (int p = 0; p < 2; ++p) {
            int idx = tid + p * 256;
            int r = idx >> 3, c = idx & 7;
            int hl = r >> 5, row = r & 31;
            cpa16(sb + st * STG + 32768 + hl * 4096 +
                      SWZ((uint32_t)(row * 128 + c * 16)),
                  (hl ? Bl : Bh) + (size_t)row * HIDC + kb + c * 8);
        }
        asm volatile("cp.async.commit_group;");
    };

    load_stage(0, 0);

#pragma unroll 1
    for (int s = 0; s < 8; ++s) {
        const int cur = s & 1;
        if (s + 1 < 8) {
            load_stage(cur ^ 1, s + 1);
            asm volatile("cp.async.wait_group 1;");
        } else {
            asm volatile("cp.async.wait_group 0;");
        }
        __syncthreads();

        const uint32_t ahb = sb + cur * STG;
        const uint32_t alb = ahb + 16384;
        const uint32_t bhb = ahb + 32768;
        const uint32_t blb = ahb + 36864;
#pragma unroll
        for (int kk = 0; kk < 4; ++kk) {
            uint32_t ah[4], al[4];
            {
                uint32_t off = SWZ((uint32_t)(
                    (wid * 16 + (lane & 15)) * 128 + kk * 32 + (lane >> 4) * 16));
                ldsm4(ah, ahb + off);
                ldsm4(al, alb + off);
            }
            uint32_t bh[2][4], bl[2][4];
#pragma unroll
            for (int ng = 0; ng < 2; ++ng) {
                int rowB = ng * 16 + (lane & 7) + ((lane >> 4) << 3);
                uint32_t off = SWZ((uint32_t)(
                    rowB * 128 + kk * 32 + ((lane >> 3) & 1) * 16));
                ldsm4(bh[ng], bhb + off);
                ldsm4(bl[ng], blb + off);
            }
#pragma unroll
            for (int ng = 0; ng < 2; ++ng)
#pragma unroll
                for (int sub = 0; sub < 2; ++sub) {
                    float* c = acc[ng * 2 + sub];
                    mma_bf16(c, ah, bh[ng][sub * 2], bh[ng][sub * 2 + 1]);
                    mma_bf16(c, al, bh[ng][sub * 2], bh[ng][sub * 2 + 1]);
                    mma_bf16(c, ah, bl[ng][sub * 2], bl[ng][sub * 2 + 1]);
                }
        }
        __syncthreads();
    }

    float* sOut = reinterpret_cast<float*>(smem);
    __syncthreads();
#pragma unroll
    for (int t = 0; t < 4; ++t) {
        int d = t * 8 + (lane & 3) * 2;
        float2 bv = *reinterpret_cast<const float2*>(b2 + d);
        int row = wid * 16 + (lane >> 2);
        sOut[row * 33 + d] = acc[t][0] + bv.x;
        sOut[row * 33 + d + 1] = acc[t][1] + bv.y;
        sOut[(row + 8) * 33 + d] = acc[t][2] + bv.x;
        sOut[(row + 8) * 33 + d + 1] = acc[t][3] + bv.y;
    }
    __syncthreads();

#pragma unroll 1
    for (int rit = 0; rit < 16; ++rit) {
        int row = rit * 8 + wid;
        float v = sOut[row * 33 + lane];
        float m = v;
#pragma unroll
        for (int o = 16; o > 0; o >>= 1)
            m = fmaxf(m, __shfl_xor_sync(0xffffffffu, m, o));
        float s = expf(v - m);
#pragma unroll
        for (int o = 16; o > 0; o >>= 1)
            s += __shfl_xor_sync(0xffffffffu, s, o);
        float lsm = v - m - logf(s);
        size_t gi = (size_t)(r0 + row) * OUTC + lane;
        out[gi] = lsm;
        if (write_raw) out[(size_t)BN * OUTC + gi] = v;
    }
}

// ---------------------------------------------------------------------------
extern "C" void kernel_launch(void* const* d_in, const int* in_sizes, int n_in,
                              void* d_out, int out_size) {
    const float* x   = (const float*)d_in[0];
    const int*   A   = (const int*)d_in[1];
    const float* W1l = (const float*)d_in[2];
    const float* W1r = (const float*)d_in[3];
    const float* b1  = (const float*)d_in[4];
    const float* W2l = (const float*)d_in[5];
    const float* W2r = (const float*)d_in[6];
    const float* b2  = (const float*)d_in[7];
    float* out = (float*)d_out;
    (void)in_sizes; (void)n_in;

    const int write_raw = (out_size >= 2 * BN * OUTC) ? 1 : 0;

    constexpr int AGG1_SMEM = 3 * 24576 + 256;  // 73984
    constexpr int AGG2_SMEM = 98304;            // bits 32K + X 32K + mask 32K
    constexpr int D1_SMEM = 2 * 49152;          // 98304
    constexpr int D2_SMEM = 2 * 40960;          // 81920
    cudaFuncSetAttribute(agg1_kernel,
                         cudaFuncAttributeMaxDynamicSharedMemorySize, AGG1_SMEM);
    cudaFuncSetAttribute(agg2_kernel,
                         cudaFuncAttributeMaxDynamicSharedMemorySize, AGG2_SMEM);
    cudaFuncSetAttribute(dense1_mma_kernel,
                         cudaFuncAttributeMaxDynamicSharedMemorySize, D1_SMEM);
    cudaFuncSetAttribute(dense2_mma_kernel,
                         cudaFuncAttributeMaxDynamicSharedMemorySize, D2_SMEM);

    prep_kernel<<<dim3(N_ / 64, INC / 64, B_ + 1), 256>>>(x, W1l, W1r, W2l, W2r);
    agg1_kernel<<<dim3(N_ / 64, 1, B_), 256, AGG1_SMEM>>>(A);
    dense1_mma_kernel<<<dim3(BN / 64, HIDC / 128), 256, D1_SMEM>>>(b1);
    agg2_kernel<<<dim3(N_ / 128, HIDC / 128, B_), 256, AGG2_SMEM>>>();
    dense2_mma_kernel<<<BN / 128, 256, D2_SMEM>>>(b2, out, write_raw);
}